// round 8
// baseline (speedup 1.0000x reference)
#include <cuda_runtime.h>
#include <cuda_bf16.h>
#include <cstdint>
#include <math.h>

#define Nn 50000
#define Ee 800000
#define Gg 64
#define Ff 6
#define Hh 256
#define Oo 2
#define NEx 8
#define NH (Nn*Hh)
#define NMATS 49   // 1 router + 3 layers * 8 experts * 2

// ---------------- scratch (static __device__ arrays; no allocation) ----------------
__device__ __align__(128) float g_h[NH];                  // encoder output (fp32)
__device__ __align__(128) __nv_bfloat16 g_A0h[NH];        // encoder bf16 hi
__device__ __align__(128) __nv_bfloat16 g_A0l[NH];        // encoder bf16 lo
__device__ __align__(128) __nv_bfloat16 g_G0h[NH];        // agg(h) bf16 hi (layer-0, shared)
__device__ __align__(128) __nv_bfloat16 g_G0l[NH];        // agg(h) bf16 lo
__device__ __align__(128) float g_r[NH];                  // router hidden
__device__ __align__(128) float g_rt[NH];                 // router GEMM scratch
__device__ __align__(128) float g_t[NEx*NH];              // he @ Wr
__device__ __align__(128) float g_v[NEx*NH];              // he @ Wn (or agg@Wn for L0)
__device__ __align__(128) __nv_bfloat16 g_Ah[NEx*NH];     // per-expert activation bf16 hi
__device__ __align__(128) __nv_bfloat16 g_Al[NEx*NH];     // per-expert activation bf16 lo
__device__ __align__(128) __nv_bfloat16 g_Wth[NMATS*65536]; // weights bf16 hi [mat][n][k]
__device__ __align__(128) __nv_bfloat16 g_Wtl[NMATS*65536]; // weights bf16 lo
__device__ __align__(128) float g_sf[Nn*2];
__device__ __align__(128) float g_logits[Nn*NEx];
__device__ __align__(128) float g_sparse[Nn*NEx];
__device__ __align__(128) float g_mz[NEx*Nn*4];           // [m0,m1,z0,z1] per (e,node)
__device__ __align__(128) float g_aggz[NEx*Nn*2];
__device__ int g_nodecnt[Gg];
__device__ int g_edgecnt[Gg];
__device__ int g_indeg[Nn];
__device__ int g_scantmp[Nn];
__device__ int g_bsum[64];
__device__ int g_bsumscan[64];
__device__ int g_rowstart[Nn+1];
__device__ int g_cursor[Nn];
__device__ int g_csr_src[Ee];

// ======================= warp MMA helpers (plain-target: sm_80+) =======================
__device__ __forceinline__ uint32_t smem_to_u32(const void* smem_ptr) {
    uint32_t addr;
    asm("{ .reg .u64 tmp; cvta.to.shared.u64 tmp, %1; cvt.u32.u64 %0, tmp; }"
        : "=r"(addr) : "l"(smem_ptr));
    return addr;
}
#define LDSM4(r0,r1,r2,r3,addr) \
    asm volatile("ldmatrix.sync.aligned.m8n8.x4.shared.b16 {%0,%1,%2,%3}, [%4];" \
        : "=r"(r0), "=r"(r1), "=r"(r2), "=r"(r3) : "r"(addr))
#define MMA16816(c, a, b) \
    asm volatile("mma.sync.aligned.m16n8k16.row.col.f32.bf16.bf16.f32 " \
        "{%0,%1,%2,%3}, {%4,%5,%6,%7}, {%8,%9}, {%0,%1,%2,%3};" \
        : "+f"((c)[0]), "+f"((c)[1]), "+f"((c)[2]), "+f"((c)[3]) \
        : "r"((a)[0]), "r"((a)[1]), "r"((a)[2]), "r"((a)[3]), \
          "r"((b)[0]), "r"((b)[1]))
#define CPA16(dst, src) \
    asm volatile("cp.async.cg.shared.global [%0], [%1], 16;" :: "r"(dst), "l"(src))
#define CP_COMMIT() asm volatile("cp.async.commit_group;")
#define CP_WAIT1()  asm volatile("cp.async.wait_group 1;")
#define CP_WAIT0()  asm volatile("cp.async.wait_group 0;")

// ---------------- small kernels ----------------
__global__ void k_zero() {
    int i = blockIdx.x*blockDim.x + threadIdx.x;
    if (i < Gg) { g_nodecnt[i]=0; g_edgecnt[i]=0; }
    if (i < Nn) g_indeg[i]=0;
}

__global__ void k_encoder(const float* __restrict__ x, const float* __restrict__ W,
                          const float* __restrict__ b) {
    int idx = blockIdx.x*blockDim.x + threadIdx.x;
    if (idx >= NH) return;
    int i = idx >> 8, c = idx & 255;
    float acc = b[c];
#pragma unroll
    for (int k=0;k<Ff;k++) acc += x[i*Ff+k]*W[k*Hh+c];
    float v = fmaxf(acc, 0.f);
    g_h[idx] = v;
    __nv_bfloat16 hi = __float2bfloat16(v);
    g_A0h[idx] = hi;
    g_A0l[idx] = __float2bfloat16(v - __bfloat162float(hi));
}

// convert + transpose all weights to bf16 hi/lo, layout [mat][n][k]
__global__ void k_convW(const float* __restrict__ rW1, const float* __restrict__ hWr,
                        const float* __restrict__ hWn) {
    size_t idx = (size_t)blockIdx.x*blockDim.x + threadIdx.x;
    if (idx >= (size_t)NMATS*65536) return;
    int mat = (int)(idx >> 16);
    int r = (int)(idx & 65535);
    int n = r >> 8, k = r & 255;
    float w;
    if (mat == 0) {
        w = rW1[k*256 + n];
    } else {
        int hm = mat - 1;
        int l = hm >> 4, rr = hm & 15;
        int e = rr >> 1, m = rr & 1;
        const float* W = m ? hWn : hWr;
        w = W[((size_t)(l*NEx + e))*65536 + k*256 + n];
    }
    __nv_bfloat16 hi = __float2bfloat16(w);
    g_Wth[idx] = hi;
    g_Wtl[idx] = __float2bfloat16(w - __bfloat162float(hi));
}

__global__ void k_count_nodes(const int* __restrict__ batch) {
    __shared__ int hist[Gg];
    int t = threadIdx.x;
    if (t < Gg) hist[t]=0;
    __syncthreads();
    for (int i = blockIdx.x*blockDim.x + t; i < Nn; i += gridDim.x*blockDim.x)
        atomicAdd(&hist[batch[i]], 1);
    __syncthreads();
    if (t < Gg) atomicAdd(&g_nodecnt[t], hist[t]);
}

__global__ void k_count_edges(const int* __restrict__ ei, const int* __restrict__ batch) {
    __shared__ int hist[Gg];
    int t = threadIdx.x;
    if (t < Gg) hist[t]=0;
    __syncthreads();
    for (int e = blockIdx.x*blockDim.x + t; e < Ee; e += gridDim.x*blockDim.x)
        atomicAdd(&hist[batch[ei[e]]], 1);
    __syncthreads();
    if (t < Gg) atomicAdd(&g_edgecnt[t], hist[t]);
}

__global__ void k_indeg(const int* __restrict__ ei) {
    int e = blockIdx.x*blockDim.x + threadIdx.x;
    if (e < Ee) atomicAdd(&g_indeg[ei[Ee+e]], 1);
}

__global__ void k_sizefeat(const int* __restrict__ batch) {
    int i = blockIdx.x*blockDim.x + threadIdx.x;
    if (i >= Nn) return;
    int g = batch[i];
    g_sf[i*2+0] = logf((float)g_nodecnt[g] + 1.f);
    g_sf[i*2+1] = logf((float)g_edgecnt[g] + 1.f);
}

__global__ void k_scan1() {
    __shared__ int sh[1024];
    int t = threadIdx.x, gid = blockIdx.x*1024 + t;
    sh[t] = (gid < Nn) ? g_indeg[gid] : 0;
    __syncthreads();
    for (int off=1; off<1024; off<<=1) {
        int a = (t>=off) ? sh[t-off] : 0;
        __syncthreads();
        sh[t] += a;
        __syncthreads();
    }
    if (gid < Nn) g_scantmp[gid] = sh[t];
    if (t == 1023) g_bsum[blockIdx.x] = sh[1023];
}

__global__ void k_scan2() {
    __shared__ int sh[64];
    int t = threadIdx.x;
    const int NB1 = (Nn + 1023)/1024;
    sh[t] = (t < NB1) ? g_bsum[t] : 0;
    __syncthreads();
    for (int off=1; off<64; off<<=1) {
        int a = (t>=off) ? sh[t-off] : 0;
        __syncthreads();
        sh[t] += a;
        __syncthreads();
    }
    g_bsumscan[t] = sh[t];
}

__global__ void k_scan3() {
    int i = blockIdx.x*blockDim.x + threadIdx.x;
    if (i >= Nn) return;
    int blk = i >> 10;
    int incl = g_scantmp[i] + (blk ? g_bsumscan[blk-1] : 0);
    g_rowstart[i+1] = incl;
    if (i == 0) g_rowstart[0] = 0;
}

__global__ void k_cursor() {
    int i = blockIdx.x*blockDim.x + threadIdx.x;
    if (i < Nn) g_cursor[i] = g_rowstart[i];
}

__global__ void k_scatter(const int* __restrict__ ei) {
    int e = blockIdx.x*blockDim.x + threadIdx.x;
    if (e >= Ee) return;
    int d = ei[Ee+e];
    int p = atomicAdd(&g_cursor[d], 1);
    g_csr_src[p] = ei[e];
}

// ---------------- router SGEMM (exact fp32, tile 128x128) -> g_rt ----------------
__global__ void __launch_bounds__(256) k_sgemm_router(const float* __restrict__ B) {
    const float* A = g_h;
    float* Cb = g_rt;

    __shared__ float As[16][128];
    __shared__ float Bs[16][128];

    int tid = threadIdx.x;
    int bm = blockIdx.x*128, bn = blockIdx.y*128;
    int tx = tid & 15, ty = tid >> 4;
    int a_row = tid >> 2;
    int a_col = (tid & 3) * 4;
    int b_row = tid >> 5;
    int b_col = (tid & 31) * 4;

    float acc[8][8];
#pragma unroll
    for (int i=0;i<8;i++)
#pragma unroll
        for (int j=0;j<8;j++) acc[i][j]=0.f;

    for (int kt=0; kt<256; kt+=16) {
        __syncthreads();
#pragma unroll
        for (int i=0;i<2;i++) {
            int r = a_row + i*64;
            int gm = bm + r;
            float4 av = make_float4(0.f,0.f,0.f,0.f);
            if (gm < Nn) av = *(const float4*)(A + (size_t)gm*256 + kt + a_col);
            As[a_col+0][r]=av.x; As[a_col+1][r]=av.y;
            As[a_col+2][r]=av.z; As[a_col+3][r]=av.w;
        }
#pragma unroll
        for (int i=0;i<2;i++) {
            int r = b_row + i*8;
            *(float4*)&Bs[r][b_col] = *(const float4*)(B + (size_t)(kt+r)*256 + bn + b_col);
        }
        __syncthreads();
#pragma unroll
        for (int kk=0;kk<16;kk++) {
            float4 a0 = *(const float4*)&As[kk][ty*4];
            float4 a1 = *(const float4*)&As[kk][64+ty*4];
            float4 b0 = *(const float4*)&Bs[kk][tx*4];
            float4 b1 = *(const float4*)&Bs[kk][64+tx*4];
            float a[8] = {a0.x,a0.y,a0.z,a0.w,a1.x,a1.y,a1.z,a1.w};
            float b[8] = {b0.x,b0.y,b0.z,b0.w,b1.x,b1.y,b1.z,b1.w};
#pragma unroll
            for (int i=0;i<8;i++)
#pragma unroll
                for (int j=0;j<8;j++) acc[i][j] += a[i]*b[j];
        }
    }
#pragma unroll
    for (int ih=0; ih<2; ih++) {
#pragma unroll
        for (int i=0;i<4;i++) {
            int gm = bm + ih*64 + ty*4 + i;
            if (gm >= Nn) continue;
            float* crow = Cb + (size_t)gm*256 + bn;
            int r = ih*4 + i;
            *(float4*)(crow + tx*4)      = make_float4(acc[r][0],acc[r][1],acc[r][2],acc[r][3]);
            *(float4*)(crow + 64 + tx*4) = make_float4(acc[r][4],acc[r][5],acc[r][6],acc[r][7]);
        }
    }
}

// ============== HMMA bf16x3 GEMM, 3-stage cp.async, 1 sync/iter =====================
// asel: 0 -> A = g_A0 (shared h), 1 -> A = g_A(e), 2 -> A = g_G0 (shared agg(h))
// mSel: -1 -> z covers e*2+m ; 0/1 -> z covers e, m fixed
// mat = matBase + e*2 + m ; C = (m? g_v : g_t)[e]
// Stage (24576B): Ah@0, Al@6144, Bh@12288, Bl@18432 — rows pitch 48B. 3 stages = 73728B dyn.
#define HG_STAGE 24576

__global__ void __launch_bounds__(256) k_hgemm(int asel, int mSel, int matBase)
{
    extern __shared__ __align__(16) char hg_smem[];
    uint32_t sbase = smem_to_u32(hg_smem);
    int tid = threadIdx.x, lane = tid & 31, wid = tid >> 5;
    int bm = blockIdx.x * 128, bn = blockIdx.y * 128;
    int z = blockIdx.z;
    int e, m;
    if (mSel < 0) { e = z >> 1; m = z & 1; } else { e = z; m = mSel; }
    int mat = matBase + e*2 + m;

    const __nv_bfloat16 *Abh, *Abl;
    if (asel == 0)      { Abh = g_A0h; Abl = g_A0l; }
    else if (asel == 1) { Abh = g_Ah + (size_t)e*NH; Abl = g_Al + (size_t)e*NH; }
    else                { Abh = g_G0h; Abl = g_G0l; }
    const __nv_bfloat16* Bh = g_Wth + (size_t)mat * 65536;
    const __nv_bfloat16* Bl = g_Wtl + (size_t)mat * 65536;

    int wm = (wid & 3) * 32;
    int wn = (wid >> 2) * 64;

    float c[2][8][4];
#pragma unroll
    for (int mi=0;mi<2;mi++)
#pragma unroll
        for (int nf=0;nf<8;nf++)
#pragma unroll
            for (int r=0;r<4;r++) c[mi][nf][r] = 0.f;

    // cp.async slots: each thread one 16B chunk into each of the 4 arrays.
    int lrow = tid >> 1, lch = tid & 1;
    int agr = bm + lrow; if (agr >= Nn) agr = Nn - 1;   // clamp: junk rows masked on store
    const __nv_bfloat16* srcAh = Abh + (size_t)agr*256 + lch*8;
    const __nv_bfloat16* srcAl = Abl + (size_t)agr*256 + lch*8;
    const __nv_bfloat16* srcBh = Bh + (size_t)(bn + lrow)*256 + lch*8;
    const __nv_bfloat16* srcBl = Bl + (size_t)(bn + lrow)*256 + lch*8;
    uint32_t dstOff = (uint32_t)lrow*48 + (uint32_t)lch*16;

    // prologue: stages 0,1
#pragma unroll
    for (int s = 0; s < 2; s++) {
        uint32_t d = sbase + s*HG_STAGE + dstOff;
        int k0 = s*16;
        CPA16(d,         srcAh + k0);
        CPA16(d + 6144,  srcAl + k0);
        CPA16(d + 12288, srcBh + k0);
        CPA16(d + 18432, srcBl + k0);
        CP_COMMIT();
    }

    int rsel = lane & 15;
    int cofs = (lane & 16) ? 16 : 0;

    int buf = 0;
    for (int kt = 0; kt < 16; kt++) {
        if (kt < 15) CP_WAIT1(); else CP_WAIT0();
        __syncthreads();
        if (kt + 2 < 16) {
            int nb = buf + 2; if (nb >= 3) nb -= 3;
            uint32_t d = sbase + nb*HG_STAGE + dstOff;
            int k0 = (kt + 2) * 16;
            CPA16(d,         srcAh + k0);
            CPA16(d + 6144,  srcAl + k0);
            CPA16(d + 12288, srcBh + k0);
            CPA16(d + 18432, srcBl + k0);
            CP_COMMIT();
        }
        uint32_t b0 = sbase + buf*HG_STAGE;

        uint32_t a_h[2][4], a_l[2][4];
#pragma unroll
        for (int mi = 0; mi < 2; mi++) {
            uint32_t ro = b0 + (uint32_t)(wm + mi*16 + rsel) * 48 + cofs;
            LDSM4(a_h[mi][0], a_h[mi][1], a_h[mi][2], a_h[mi][3], ro);
            LDSM4(a_l[mi][0], a_l[mi][1], a_l[mi][2], a_l[mi][3], ro + 6144);
        }
#pragma unroll
        for (int np = 0; np < 4; np++) {
            uint32_t ro = b0 + 12288 + (uint32_t)(wn + np*16 + rsel) * 48 + cofs;
            uint32_t h0, h1, h2, h3, l0, l1, l2, l3;
            LDSM4(h0, h1, h2, h3, ro);
            LDSM4(l0, l1, l2, l3, ro + 6144);
            uint32_t bf0[2] = {h0, h2}, bf1[2] = {h1, h3};
            uint32_t bg0[2] = {l0, l2}, bg1[2] = {l1, l3};
#pragma unroll
            for (int mi = 0; mi < 2; mi++) {
                MMA16816(c[mi][np*2],   a_h[mi], bf0);
                MMA16816(c[mi][np*2],   a_h[mi], bg0);
                MMA16816(c[mi][np*2],   a_l[mi], bf0);
                MMA16816(c[mi][np*2+1], a_h[mi], bf1);
                MMA16816(c[mi][np*2+1], a_h[mi], bg1);
                MMA16816(c[mi][np*2+1], a_l[mi], bf1);
            }
        }
        buf++; if (buf >= 3) buf = 0;
    }

    float* C = (m ? g_v : g_t) + (size_t)e * NH;
#pragma unroll
    for (int mi = 0; mi < 2; mi++) {
        int row0 = bm + wm + mi*16 + (lane >> 2);
#pragma unroll
        for (int nf = 0; nf < 8; nf++) {
            int col = bn + wn + nf*8 + (lane & 3)*2;
            if (row0 < Nn)
                *(float2*)(C + (size_t)row0*256 + col) = make_float2(c[mi][nf][0], c[mi][nf][1]);
            if (row0 + 8 < Nn)
                *(float2*)(C + (size_t)(row0+8)*256 + col) = make_float2(c[mi][nf][2], c[mi][nf][3]);
        }
    }
}

// ---------------- router epilogue ----------------
__global__ void k_router_epi(const float* __restrict__ W1, const float* __restrict__ b1) {
    int idx = blockIdx.x*blockDim.x + threadIdx.x;
    if (idx >= NH) return;
    int i = idx >> 8, c = idx & 255;
    float v = g_rt[idx] + g_sf[i*2]*W1[256*256+c] + g_sf[i*2+1]*W1[257*256+c] + b1[c];
    g_r[idx] = fmaxf(v, 0.f);
}

__global__ void k_logits(const float* __restrict__ W2, const float* __restrict__ b2) {
    int idx = blockIdx.x*blockDim.x + threadIdx.x;
    if (idx >= Nn*NEx) return;
    int i = idx >> 3, e2 = idx & 7;
    const float* r = g_r + (size_t)i*256;
    float acc = b2[e2];
#pragma unroll 8
    for (int k=0;k<256;k++) acc += r[k]*W2[k*8+e2];
    g_logits[idx] = acc;
}

__global__ void k_topk() {
    int i = blockIdx.x*blockDim.x + threadIdx.x;
    if (i >= Nn) return;
    float l[8];
#pragma unroll
    for (int e=0;e<8;e++) l[e] = g_logits[i*8+e];
    int i1 = 0; float m1 = l[0];
#pragma unroll
    for (int e=1;e<8;e++) if (l[e] > m1) { m1 = l[e]; i1 = e; }
    int i2 = -1; float m2 = -1e30f;
#pragma unroll
    for (int e=0;e<8;e++) if (e != i1 && l[e] > m2) { m2 = l[e]; i2 = e; }
    float e2v = expf(m2 - m1);
    float inv = 1.f/(1.f + e2v);
    float s[8];
#pragma unroll
    for (int e=0;e<8;e++) s[e]=0.f;
    s[i1] = inv; s[i2] = e2v*inv;
#pragma unroll
    for (int e=0;e<8;e++) g_sparse[i*8+e] = s[e];
}

// ---------------- layer-0 SpMM: agg(h) once, shared across experts ----------------
__global__ void k_spmm0() {
    int dst = blockIdx.x*8 + (threadIdx.x >> 5);
    int lane = threadIdx.x & 31;
    if (dst >= Nn) return;
    const float* vb = g_h + lane*8;
    int s0 = g_rowstart[dst], s1 = g_rowstart[dst+1];
    float a0=0.f,a1=0.f,a2=0.f,a3=0.f,a4=0.f,a5=0.f,a6=0.f,a7=0.f;
    for (int p = s0; p < s1; p++) {
        int src = g_csr_src[p];
        const float4* row = (const float4*)(vb + (size_t)src*256);
        float4 x0 = row[0], x1 = row[1];
        a0 += x0.x; a1 += x0.y; a2 += x0.z; a3 += x0.w;
        a4 += x1.x; a5 += x1.y; a6 += x1.z; a7 += x1.w;
    }
    float vals[8] = {a0,a1,a2,a3,a4,a5,a6,a7};
    union { __nv_bfloat16 h[8]; uint4 u; } H, L;
#pragma unroll
    for (int j = 0; j < 8; j++) {
        __nv_bfloat16 hi = __float2bfloat16(vals[j]);
        H.h[j] = hi;
        L.h[j] = __float2bfloat16(vals[j] - __bfloat162float(hi));
    }
    size_t base = (size_t)dst*256 + lane*8;
    *(uint4*)(g_G0h + base) = H.u;
    *(uint4*)(g_G0l + base) = L.u;
}

// ---------------- layer-0 combine: he = relu(t + v + b), split hi/lo ----------------
__global__ void k_combine0(const float* __restrict__ bias) {
    size_t idx8 = (size_t)blockIdx.x*blockDim.x + threadIdx.x;
    if (idx8 >= (size_t)NEx*NH/8) return;
    size_t idx = idx8*8;
    int e = (int)(idx / NH);
    int c = (int)(idx & 255);
    const float4* tb = (const float4*)(g_t + idx);
    const float4* vb = (const float4*)(g_v + idx);
    const float4* bb = (const float4*)(bias + e*256 + c);
    float4 t0 = tb[0], t1 = tb[1], v0 = vb[0], v1 = vb[1], b0 = bb[0], b1 = bb[1];
    float vals[8];
    vals[0]=t0.x+v0.x+b0.x; vals[1]=t0.y+v0.y+b0.y; vals[2]=t0.z+v0.z+b0.z; vals[3]=t0.w+v0.w+b0.w;
    vals[4]=t1.x+v1.x+b1.x; vals[5]=t1.y+v1.y+b1.y; vals[6]=t1.z+v1.z+b1.z; vals[7]=t1.w+v1.w+b1.w;
    union { __nv_bfloat16 h[8]; uint4 u; } H, L;
#pragma unroll
    for (int j = 0; j < 8; j++) {
        float v = fmaxf(vals[j], 0.f);
        __nv_bfloat16 hi = __float2bfloat16(v);
        H.h[j] = hi;
        L.h[j] = __float2bfloat16(v - __bfloat162float(hi));
    }
    *(uint4*)(g_Ah + idx) = H.u;
    *(uint4*)(g_Al + idx) = L.u;
}

// ---------------- SpMM + combine + bf16 split (layers 1-2): warp per (dst, expert) ----------------
__global__ void k_spmm_combine(const float* __restrict__ bias) {
    int dst = blockIdx.x;
    int e = threadIdx.x >> 5;
    int lane = threadIdx.x & 31;
    const float* vb = g_v + (size_t)e*NH + lane*8;
    int s0 = g_rowstart[dst], s1 = g_rowstart[dst+1];
    float a0=0.f,a1=0.f,a2=0.f,a3=0.f,a4=0.f,a5=0.f,a6=0.f,a7=0.f;
    for (int p = s0; p < s1; p++) {
        int src = g_csr_src[p];
        const float4* row = (const float4*)(vb + (size_t)src*256);
        float4 x0 = row[0], x1 = row[1];
        a0 += x0.x; a1 += x0.y; a2 += x0.z; a3 += x0.w;
        a4 += x1.x; a5 += x1.y; a6 += x1.z; a7 += x1.w;
    }
    size_t base = (size_t)e*NH + (size_t)dst*256 + lane*8;
    const float4* tb = (const float4*)(g_t + base);
    float4 t0 = tb[0], t1 = tb[1];
    const float4* bb = (const float4*)(bias + e*256 + lane*8);
    float4 b0 = bb[0], b1 = bb[1];
    float vals[8];
    vals[0]=t0.x+a0+b0.x; vals[1]=t0.y+a1+b0.y; vals[2]=t0.z+a2+b0.z; vals[3]=t0.w+a3+b0.w;
    vals[4]=t1.x+a4+b1.x; vals[5]=t1.y+a5+b1.y; vals[6]=t1.z+a6+b1.z; vals[7]=t1.w+a7+b1.w;
    union { __nv_bfloat16 h[8]; uint4 u; } H, L;
#pragma unroll
    for (int j = 0; j < 8; j++) {
        float v = fmaxf(vals[j], 0.f);
        __nv_bfloat16 hi = __float2bfloat16(v);
        H.h[j] = hi;
        L.h[j] = __float2bfloat16(v - __bfloat162float(hi));
    }
    *(uint4*)(g_Ah + base) = H.u;
    *(uint4*)(g_Al + base) = L.u;
}

// ---------------- output layer ----------------
__global__ void k_mz(const float* __restrict__ Wr, const float* __restrict__ Wn) {
    int idx = blockIdx.x*blockDim.x + threadIdx.x;
    if (idx >= NEx*Nn) return;
    int i = idx % Nn, e = idx / Nn;
    const uint4* ah = (const uint4*)(g_Ah + (size_t)e*NH + (size_t)i*256);
    const uint4* al = (const uint4*)(g_Al + (size_t)e*NH + (size_t)i*256);
    const float* WRe = Wr + e*512;
    const float* WNe = Wn + e*512;
    float m0=0.f, m1=0.f, z0=0.f, z1=0.f;
#pragma unroll 4
    for (int k8 = 0; k8 < 32; k8++) {
        uint4 vh = ah[k8], vl = al[k8];
        const __nv_bfloat16* ph = (const __nv_bfloat16*)&vh;
        const __nv_bfloat16* pl = (const __nv_bfloat16*)&vl;
#pragma unroll
        for (int j = 0; j < 8; j++) {
            float a = __bfloat162float(ph[j]) + __bfloat162float(pl[j]);
            int k = k8*8 + j;
            m0 += a*WRe[k*2];   m1 += a*WRe[k*2+1];
            z0 += a*WNe[k*2];   z1 += a*WNe[k*2+1];
        }
    }
    float* o = g_mz + (size_t)idx*4;
    o[0]=m0; o[1]=m1; o[2]=z0; o[3]=z1;
}

__global__ void k_aggz() {
    int idx = blockIdx.x*blockDim.x + threadIdx.x;
    if (idx >= NEx*Nn) return;
    int dst = idx % Nn;
    int e = idx / Nn;
    int s0 = g_rowstart[dst], s1 = g_rowstart[dst+1];
    float a0=0.f, a1=0.f;
    for (int p=s0; p<s1; p++) {
        int src = g_csr_src[p];
        const float* z = g_mz + ((size_t)e*Nn + src)*4 + 2;
        a0 += z[0]; a1 += z[1];
    }
    g_aggz[((size_t)e*Nn+dst)*2+0] = a0;
    g_aggz[((size_t)e*Nn+dst)*2+1] = a1;
}

__global__ void k_final(const float* __restrict__ outb, float* __restrict__ out) {
    int i = blockIdx.x*blockDim.x + threadIdx.x;
    if (i >= Nn) return;
    float o0=0.f, o1=0.f;
#pragma unroll
    for (int e=0;e<8;e++) {
        float s = g_sparse[i*8+e];
        const float* mz = g_mz + ((size_t)e*Nn+i)*4;
        const float* az = g_aggz + ((size_t)e*Nn+i)*2;
        o0 += s*(mz[0] + az[0] + outb[e*2+0]);
        o1 += s*(mz[1] + az[1] + outb[e*2+1]);
    }
    out[i*2+0] = o0;
    out[i*2+1] = o1;
}

// ---------------- launch ----------------
extern "C" void kernel_launch(void* const* d_in, const int* in_sizes, int n_in,
                              void* d_out, int out_size) {
    const float* x    = (const float*)d_in[0];
    const int*   ei   = (const int*)  d_in[1];
    const int*   batch= (const int*)  d_in[2];
    const float* encW = (const float*)d_in[3];
    const float* encb = (const float*)d_in[4];
    const float* rW1  = (const float*)d_in[5];
    const float* rb1  = (const float*)d_in[6];
    const float* rW2  = (const float*)d_in[7];
    const float* rb2  = (const float*)d_in[8];
    const float* hWr  = (const float*)d_in[9];
    const float* hWn  = (const float*)d_in[10];
    const float* hb   = (const float*)d_in[11];
    const float* oWr  = (const float*)d_in[12];
    const float* oWn  = (const float*)d_in[13];
    const float* ob   = (const float*)d_in[14];
    float* out = (float*)d_out;

    cudaFuncSetAttribute(k_hgemm, cudaFuncAttributeMaxDynamicSharedMemorySize, 3*HG_STAGE);

    const int NTILES = (Nn + 127) / 128;   // 391
    dim3 gHalf(NTILES, 2, NEx);            // one m per launch
    dim3 gFull(NTILES, 2, NEx*2);          // both m
    dim3 gS(Nn, 1, 1);

    k_zero<<<(Nn+255)/256,256>>>();
    k_encoder<<<(NH+255)/256,256>>>(x, encW, encb);
    k_convW<<<(NMATS*65536+255)/256,256>>>(rW1, hWr, hWn);
    k_hgemm<<<gHalf,256,3*HG_STAGE>>>(0, 0, 1);   // L0 t = h @ Wr_e  (profiled slot)
    k_count_nodes<<<256,256>>>(batch);
    k_count_edges<<<512,256>>>(ei, batch);
    k_indeg<<<(Ee+255)/256,256>>>(ei);
    k_sizefeat<<<(Nn+255)/256,256>>>(batch);
    k_scan1<<<(Nn+1023)/1024,1024>>>();
    k_scan2<<<1,64>>>();
    k_scan3<<<(Nn+255)/256,256>>>();
    k_cursor<<<(Nn+255)/256,256>>>();
    k_scatter<<<(Ee+255)/256,256>>>(ei);

    // router (exact fp32 in its own buffer g_rt)
    {
        dim3 gR((Nn+127)/128, 2, 1);
        k_sgemm_router<<<gR,256>>>(rW1);
        k_router_epi<<<(NH+255)/256,256>>>(rW1, rb1);
        k_logits<<<(Nn*NEx+255)/256,256>>>(rW2, rb2);
        k_topk<<<(Nn+255)/256,256>>>();
    }

    // layer 0: shared aggregate of h, then v = agg(h) @ Wn_e
    k_spmm0<<<(Nn+7)/8,256>>>();
    k_hgemm<<<gHalf,256,3*HG_STAGE>>>(2, 1, 1);   // L0 v
    k_combine0<<<(NEx*NH/8+255)/256,256>>>(hb);

    // layers 1-2
    for (int l = 1; l < 3; l++) {
        k_hgemm<<<gFull,256,3*HG_STAGE>>>(1, -1, 1 + l*(NEx*2));
        k_spmm_combine<<<gS,256>>>(hb + (size_t)l*NEx*Hh);
    }

    // output layer
    k_mz<<<(NEx*Nn+255)/256,256>>>(oWr, oWn);
    k_aggz<<<(NEx*Nn+255)/256,256>>>();
    k_final<<<(Nn+255)/256,256>>>(ob, out);
}

// round 9
// speedup vs baseline: 1.1250x; 1.1250x over previous
#include <cuda_runtime.h>
#include <cuda_bf16.h>
#include <cstdint>
#include <math.h>

#define Nn 50000
#define Ee 800000
#define Gg 64
#define Ff 6
#define Hh 256
#define Oo 2
#define NEx 8
#define NH (Nn*Hh)
#define NMATS 49   // 1 router + 3 layers * 8 experts * 2

// ---------------- scratch (static __device__ arrays; no allocation) ----------------
__device__ __align__(128) float g_h[NH];                  // encoder output (fp32)
__device__ __align__(128) __nv_bfloat16 g_A0h[NH];        // encoder bf16 hi
__device__ __align__(128) __nv_bfloat16 g_A0l[NH];        // encoder bf16 lo
__device__ __align__(128) __nv_bfloat16 g_G0h[NH];        // agg(h) bf16 hi (layer-0, shared)
__device__ __align__(128) __nv_bfloat16 g_G0l[NH];        // agg(h) bf16 lo
__device__ __align__(128) float g_r[NH];                  // router hidden
__device__ __align__(128) float g_rt[NH];                 // router GEMM scratch
__device__ __align__(128) float g_t[NEx*NH];              // he @ Wr
__device__ __align__(128) float g_v[NEx*NH];              // he @ Wn (or agg@Wn for L0)
__device__ __align__(128) __nv_bfloat16 g_Ah[NEx*NH];     // per-expert activation bf16 hi
__device__ __align__(128) __nv_bfloat16 g_Al[NEx*NH];     // per-expert activation bf16 lo
__device__ __align__(128) __nv_bfloat16 g_Wth[NMATS*65536]; // weights bf16 hi [mat][n][k]
__device__ __align__(128) __nv_bfloat16 g_Wtl[NMATS*65536]; // weights bf16 lo
__device__ __align__(128) float g_sf[Nn*2];
__device__ __align__(128) float g_logits[Nn*NEx];
__device__ __align__(128) float g_sparse[Nn*NEx];
__device__ __align__(128) float g_mz[NEx*Nn*4];           // [m0,m1,z0,z1] per (e,node)
__device__ __align__(128) float g_aggz[NEx*Nn*2];
__device__ int g_nodecnt[Gg];
__device__ int g_edgecnt[Gg];
__device__ int g_indeg[Nn];
__device__ int g_scantmp[Nn];
__device__ int g_bsum[64];
__device__ int g_bsumscan[64];
__device__ int g_rowstart[Nn+1];
__device__ int g_cursor[Nn];
__device__ int g_csr_src[Ee];

// ======================= warp MMA helpers (plain-target: sm_80+) =======================
__device__ __forceinline__ uint32_t smem_to_u32(const void* smem_ptr) {
    uint32_t addr;
    asm("{ .reg .u64 tmp; cvta.to.shared.u64 tmp, %1; cvt.u32.u64 %0, tmp; }"
        : "=r"(addr) : "l"(smem_ptr));
    return addr;
}
#define LDSM4(r0,r1,r2,r3,addr) \
    asm volatile("ldmatrix.sync.aligned.m8n8.x4.shared.b16 {%0,%1,%2,%3}, [%4];" \
        : "=r"(r0), "=r"(r1), "=r"(r2), "=r"(r3) : "r"(addr))
#define MMA16816(c, a, b) \
    asm volatile("mma.sync.aligned.m16n8k16.row.col.f32.bf16.bf16.f32 " \
        "{%0,%1,%2,%3}, {%4,%5,%6,%7}, {%8,%9}, {%0,%1,%2,%3};" \
        : "+f"((c)[0]), "+f"((c)[1]), "+f"((c)[2]), "+f"((c)[3]) \
        : "r"((a)[0]), "r"((a)[1]), "r"((a)[2]), "r"((a)[3]), \
          "r"((b)[0]), "r"((b)[1]))
#define CPA16(dst, src) \
    asm volatile("cp.async.cg.shared.global [%0], [%1], 16;" :: "r"(dst), "l"(src))
#define CP_COMMIT() asm volatile("cp.async.commit_group;")
#define CP_WAIT1()  asm volatile("cp.async.wait_group 1;")
#define CP_WAIT0()  asm volatile("cp.async.wait_group 0;")

// ---------------- small kernels ----------------
__global__ void k_zero() {
    int i = blockIdx.x*blockDim.x + threadIdx.x;
    if (i < Gg) { g_nodecnt[i]=0; g_edgecnt[i]=0; }
    if (i < Nn) g_indeg[i]=0;
}

__global__ void k_encoder(const float* __restrict__ x, const float* __restrict__ W,
                          const float* __restrict__ b) {
    int idx = blockIdx.x*blockDim.x + threadIdx.x;
    if (idx >= NH) return;
    int i = idx >> 8, c = idx & 255;
    float acc = b[c];
#pragma unroll
    for (int k=0;k<Ff;k++) acc += x[i*Ff+k]*W[k*Hh+c];
    float v = fmaxf(acc, 0.f);
    g_h[idx] = v;
    __nv_bfloat16 hi = __float2bfloat16(v);
    g_A0h[idx] = hi;
    g_A0l[idx] = __float2bfloat16(v - __bfloat162float(hi));
}

// convert + transpose all weights to bf16 hi/lo, layout [mat][n][k]
__global__ void k_convW(const float* __restrict__ rW1, const float* __restrict__ hWr,
                        const float* __restrict__ hWn) {
    size_t idx = (size_t)blockIdx.x*blockDim.x + threadIdx.x;
    if (idx >= (size_t)NMATS*65536) return;
    int mat = (int)(idx >> 16);
    int r = (int)(idx & 65535);
    int n = r >> 8, k = r & 255;
    float w;
    if (mat == 0) {
        w = rW1[k*256 + n];
    } else {
        int hm = mat - 1;
        int l = hm >> 4, rr = hm & 15;
        int e = rr >> 1, m = rr & 1;
        const float* W = m ? hWn : hWr;
        w = W[((size_t)(l*NEx + e))*65536 + k*256 + n];
    }
    __nv_bfloat16 hi = __float2bfloat16(w);
    g_Wth[idx] = hi;
    g_Wtl[idx] = __float2bfloat16(w - __bfloat162float(hi));
}

__global__ void k_count_nodes(const int* __restrict__ batch) {
    __shared__ int hist[Gg];
    int t = threadIdx.x;
    if (t < Gg) hist[t]=0;
    __syncthreads();
    for (int i = blockIdx.x*blockDim.x + t; i < Nn; i += gridDim.x*blockDim.x)
        atomicAdd(&hist[batch[i]], 1);
    __syncthreads();
    if (t < Gg) atomicAdd(&g_nodecnt[t], hist[t]);
}

__global__ void k_count_edges(const int* __restrict__ ei, const int* __restrict__ batch) {
    __shared__ int hist[Gg];
    int t = threadIdx.x;
    if (t < Gg) hist[t]=0;
    __syncthreads();
    for (int e = blockIdx.x*blockDim.x + t; e < Ee; e += gridDim.x*blockDim.x)
        atomicAdd(&hist[batch[ei[e]]], 1);
    __syncthreads();
    if (t < Gg) atomicAdd(&g_edgecnt[t], hist[t]);
}

__global__ void k_indeg(const int* __restrict__ ei) {
    int e = blockIdx.x*blockDim.x + threadIdx.x;
    if (e < Ee) atomicAdd(&g_indeg[ei[Ee+e]], 1);
}

__global__ void k_sizefeat(const int* __restrict__ batch) {
    int i = blockIdx.x*blockDim.x + threadIdx.x;
    if (i >= Nn) return;
    int g = batch[i];
    g_sf[i*2+0] = logf((float)g_nodecnt[g] + 1.f);
    g_sf[i*2+1] = logf((float)g_edgecnt[g] + 1.f);
}

__global__ void k_scan1() {
    __shared__ int sh[1024];
    int t = threadIdx.x, gid = blockIdx.x*1024 + t;
    sh[t] = (gid < Nn) ? g_indeg[gid] : 0;
    __syncthreads();
    for (int off=1; off<1024; off<<=1) {
        int a = (t>=off) ? sh[t-off] : 0;
        __syncthreads();
        sh[t] += a;
        __syncthreads();
    }
    if (gid < Nn) g_scantmp[gid] = sh[t];
    if (t == 1023) g_bsum[blockIdx.x] = sh[1023];
}

__global__ void k_scan2() {
    __shared__ int sh[64];
    int t = threadIdx.x;
    const int NB1 = (Nn + 1023)/1024;
    sh[t] = (t < NB1) ? g_bsum[t] : 0;
    __syncthreads();
    for (int off=1; off<64; off<<=1) {
        int a = (t>=off) ? sh[t-off] : 0;
        __syncthreads();
        sh[t] += a;
        __syncthreads();
    }
    g_bsumscan[t] = sh[t];
}

__global__ void k_scan3() {
    int i = blockIdx.x*blockDim.x + threadIdx.x;
    if (i >= Nn) return;
    int blk = i >> 10;
    int incl = g_scantmp[i] + (blk ? g_bsumscan[blk-1] : 0);
    g_rowstart[i+1] = incl;
    if (i == 0) g_rowstart[0] = 0;
}

__global__ void k_cursor() {
    int i = blockIdx.x*blockDim.x + threadIdx.x;
    if (i < Nn) g_cursor[i] = g_rowstart[i];
}

__global__ void k_scatter(const int* __restrict__ ei) {
    int e = blockIdx.x*blockDim.x + threadIdx.x;
    if (e >= Ee) return;
    int d = ei[Ee+e];
    int p = atomicAdd(&g_cursor[d], 1);
    g_csr_src[p] = ei[e];
}

// ---------------- router SGEMM (exact fp32, tile 128x128) -> g_rt ----------------
__global__ void __launch_bounds__(256) k_sgemm_router(const float* __restrict__ B) {
    const float* A = g_h;
    float* Cb = g_rt;

    __shared__ float As[16][128];
    __shared__ float Bs[16][128];

    int tid = threadIdx.x;
    int bm = blockIdx.x*128, bn = blockIdx.y*128;
    int tx = tid & 15, ty = tid >> 4;
    int a_row = tid >> 2;
    int a_col = (tid & 3) * 4;
    int b_row = tid >> 5;
    int b_col = (tid & 31) * 4;

    float acc[8][8];
#pragma unroll
    for (int i=0;i<8;i++)
#pragma unroll
        for (int j=0;j<8;j++) acc[i][j]=0.f;

    for (int kt=0; kt<256; kt+=16) {
        __syncthreads();
#pragma unroll
        for (int i=0;i<2;i++) {
            int r = a_row + i*64;
            int gm = bm + r;
            float4 av = make_float4(0.f,0.f,0.f,0.f);
            if (gm < Nn) av = *(const float4*)(A + (size_t)gm*256 + kt + a_col);
            As[a_col+0][r]=av.x; As[a_col+1][r]=av.y;
            As[a_col+2][r]=av.z; As[a_col+3][r]=av.w;
        }
#pragma unroll
        for (int i=0;i<2;i++) {
            int r = b_row + i*8;
            *(float4*)&Bs[r][b_col] = *(const float4*)(B + (size_t)(kt+r)*256 + bn + b_col);
        }
        __syncthreads();
#pragma unroll
        for (int kk=0;kk<16;kk++) {
            float4 a0 = *(const float4*)&As[kk][ty*4];
            float4 a1 = *(const float4*)&As[kk][64+ty*4];
            float4 b0 = *(const float4*)&Bs[kk][tx*4];
            float4 b1 = *(const float4*)&Bs[kk][64+tx*4];
            float a[8] = {a0.x,a0.y,a0.z,a0.w,a1.x,a1.y,a1.z,a1.w};
            float b[8] = {b0.x,b0.y,b0.z,b0.w,b1.x,b1.y,b1.z,b1.w};
#pragma unroll
            for (int i=0;i<8;i++)
#pragma unroll
                for (int j=0;j<8;j++) acc[i][j] += a[i]*b[j];
        }
    }
#pragma unroll
    for (int ih=0; ih<2; ih++) {
#pragma unroll
        for (int i=0;i<4;i++) {
            int gm = bm + ih*64 + ty*4 + i;
            if (gm >= Nn) continue;
            float* crow = Cb + (size_t)gm*256 + bn;
            int r = ih*4 + i;
            *(float4*)(crow + tx*4)      = make_float4(acc[r][0],acc[r][1],acc[r][2],acc[r][3]);
            *(float4*)(crow + 64 + tx*4) = make_float4(acc[r][4],acc[r][5],acc[r][6],acc[r][7]);
        }
    }
}

// ============== HMMA bf16x3 GEMM, 2-stage cp.async, term-major MMA order ==========
// asel: 0 -> A = g_A0 (shared h), 1 -> A = g_A(e), 2 -> A = g_G0 (shared agg(h))
// mSel: -1 -> z covers e*2+m ; 0/1 -> z covers e, m fixed
// Stage (24576B): Ah@0, Al@6144, Bh@12288, Bl@18432 — rows pitch 48B. 2 stages static.
#define HG_STAGE 24576

__global__ void __launch_bounds__(256, 2) k_hgemm(int asel, int mSel, int matBase)
{
    __shared__ __align__(16) char smarr[2*HG_STAGE];   // 48 KB static
    uint32_t sbase = smem_to_u32(smarr);
    int tid = threadIdx.x, lane = tid & 31, wid = tid >> 5;
    int bm = blockIdx.x * 128, bn = blockIdx.y * 128;
    int z = blockIdx.z;
    int e, m;
    if (mSel < 0) { e = z >> 1; m = z & 1; } else { e = z; m = mSel; }
    int mat = matBase + e*2 + m;

    const __nv_bfloat16 *Abh, *Abl;
    if (asel == 0)      { Abh = g_A0h; Abl = g_A0l; }
    else if (asel == 1) { Abh = g_Ah + (size_t)e*NH; Abl = g_Al + (size_t)e*NH; }
    else                { Abh = g_G0h; Abl = g_G0l; }
    const __nv_bfloat16* Bh = g_Wth + (size_t)mat * 65536;
    const __nv_bfloat16* Bl = g_Wtl + (size_t)mat * 65536;

    int wm = (wid & 3) * 32;
    int wn = (wid >> 2) * 64;

    float c[2][8][4];
#pragma unroll
    for (int mi=0;mi<2;mi++)
#pragma unroll
        for (int nf=0;nf<8;nf++)
#pragma unroll
            for (int r=0;r<4;r++) c[mi][nf][r] = 0.f;

    // cp.async slots: each thread one 16B chunk into each of the 4 arrays.
    int lrow = tid >> 1, lch = tid & 1;
    int agr = bm + lrow; if (agr >= Nn) agr = Nn - 1;   // clamp: junk rows masked on store
    const __nv_bfloat16* srcAh = Abh + (size_t)agr*256 + lch*8;
    const __nv_bfloat16* srcAl = Abl + (size_t)agr*256 + lch*8;
    const __nv_bfloat16* srcBh = Bh + (size_t)(bn + lrow)*256 + lch*8;
    const __nv_bfloat16* srcBl = Bl + (size_t)(bn + lrow)*256 + lch*8;
    uint32_t dstOff = (uint32_t)lrow*48 + (uint32_t)lch*16;

    // prologue: stage 0
    {
        uint32_t d = sbase + dstOff;
        CPA16(d,         srcAh);
        CPA16(d + 6144,  srcAl);
        CPA16(d + 12288, srcBh);
        CPA16(d + 18432, srcBl);
        CP_COMMIT();
    }

    int rsel = lane & 15;
    int cofs = (lane & 16) ? 16 : 0;

    for (int kt = 0; kt < 16; kt++) {
        if (kt < 15) {
            int k0 = (kt + 1) * 16;
            uint32_t d = sbase + ((kt + 1) & 1) * HG_STAGE + dstOff;
            CPA16(d,         srcAh + k0);
            CPA16(d + 6144,  srcAl + k0);
            CPA16(d + 12288, srcBh + k0);
            CPA16(d + 18432, srcBl + k0);
            CP_COMMIT();
            CP_WAIT1();
        } else {
            CP_WAIT0();
        }
        __syncthreads();
        uint32_t buf = sbase + (kt & 1) * HG_STAGE;

        uint32_t a_h[2][4], a_l[2][4];
#pragma unroll
        for (int mi = 0; mi < 2; mi++) {
            uint32_t ro = buf + (uint32_t)(wm + mi*16 + rsel) * 48 + cofs;
            LDSM4(a_h[mi][0], a_h[mi][1], a_h[mi][2], a_h[mi][3], ro);
            LDSM4(a_l[mi][0], a_l[mi][1], a_l[mi][2], a_l[mi][3], ro + 6144);
        }
        uint32_t b_h[8][2], b_l[8][2];
#pragma unroll
        for (int np = 0; np < 4; np++) {
            uint32_t ro = buf + 12288 + (uint32_t)(wn + np*16 + rsel) * 48 + cofs;
            uint32_t r0, r1, r2, r3;
            LDSM4(r0, r1, r2, r3, ro);
            b_h[np*2][0]=r0; b_h[np*2+1][0]=r1; b_h[np*2][1]=r2; b_h[np*2+1][1]=r3;
            LDSM4(r0, r1, r2, r3, ro + 6144);
            b_l[np*2][0]=r0; b_l[np*2+1][0]=r1; b_l[np*2][1]=r2; b_l[np*2+1][1]=r3;
        }
        // term-major order: same-accumulator reuse distance = 16 MMAs (latency hidden)
#pragma unroll
        for (int mi = 0; mi < 2; mi++)
#pragma unroll
            for (int nf = 0; nf < 8; nf++)
                MMA16816(c[mi][nf], a_h[mi], b_h[nf]);
#pragma unroll
        for (int mi = 0; mi < 2; mi++)
#pragma unroll
            for (int nf = 0; nf < 8; nf++)
                MMA16816(c[mi][nf], a_h[mi], b_l[nf]);
#pragma unroll
        for (int mi = 0; mi < 2; mi++)
#pragma unroll
            for (int nf = 0; nf < 8; nf++)
                MMA16816(c[mi][nf], a_l[mi], b_h[nf]);
        __syncthreads();
    }

    float* C = (m ? g_v : g_t) + (size_t)e * NH;
#pragma unroll
    for (int mi = 0; mi < 2; mi++) {
        int row0 = bm + wm + mi*16 + (lane >> 2);
#pragma unroll
        for (int nf = 0; nf < 8; nf++) {
            int col = bn + wn + nf*8 + (lane & 3)*2;
            if (row0 < Nn)
                *(float2*)(C + (size_t)row0*256 + col) = make_float2(c[mi][nf][0], c[mi][nf][1]);
            if (row0 + 8 < Nn)
                *(float2*)(C + (size_t)(row0+8)*256 + col) = make_float2(c[mi][nf][2], c[mi][nf][3]);
        }
    }
}

// ---------------- router epilogue ----------------
__global__ void k_router_epi(const float* __restrict__ W1, const float* __restrict__ b1) {
    int idx = blockIdx.x*blockDim.x + threadIdx.x;
    if (idx >= NH) return;
    int i = idx >> 8, c = idx & 255;
    float v = g_rt[idx] + g_sf[i*2]*W1[256*256+c] + g_sf[i*2+1]*W1[257*256+c] + b1[c];
    g_r[idx] = fmaxf(v, 0.f);
}

__global__ void k_logits(const float* __restrict__ W2, const float* __restrict__ b2) {
    int idx = blockIdx.x*blockDim.x + threadIdx.x;
    if (idx >= Nn*NEx) return;
    int i = idx >> 3, e2 = idx & 7;
    const float* r = g_r + (size_t)i*256;
    float acc = b2[e2];
#pragma unroll 8
    for (int k=0;k<256;k++) acc += r[k]*W2[k*8+e2];
    g_logits[idx] = acc;
}

__global__ void k_topk() {
    int i = blockIdx.x*blockDim.x + threadIdx.x;
    if (i >= Nn) return;
    float l[8];
#pragma unroll
    for (int e=0;e<8;e++) l[e] = g_logits[i*8+e];
    int i1 = 0; float m1 = l[0];
#pragma unroll
    for (int e=1;e<8;e++) if (l[e] > m1) { m1 = l[e]; i1 = e; }
    int i2 = -1; float m2 = -1e30f;
#pragma unroll
    for (int e=0;e<8;e++) if (e != i1 && l[e] > m2) { m2 = l[e]; i2 = e; }
    float e2v = expf(m2 - m1);
    float inv = 1.f/(1.f + e2v);
    float s[8];
#pragma unroll
    for (int e=0;e<8;e++) s[e]=0.f;
    s[i1] = inv; s[i2] = e2v*inv;
#pragma unroll
    for (int e=0;e<8;e++) g_sparse[i*8+e] = s[e];
}

// ---------------- layer-0 SpMM: agg(h) once, shared across experts ----------------
__global__ void k_spmm0() {
    int dst = blockIdx.x*8 + (threadIdx.x >> 5);
    int lane = threadIdx.x & 31;
    if (dst >= Nn) return;
    const float* vb = g_h + lane*8;
    int s0 = g_rowstart[dst], s1 = g_rowstart[dst+1];
    float a0=0.f,a1=0.f,a2=0.f,a3=0.f,a4=0.f,a5=0.f,a6=0.f,a7=0.f;
    for (int p = s0; p < s1; p++) {
        int src = g_csr_src[p];
        const float4* row = (const float4*)(vb + (size_t)src*256);
        float4 x0 = row[0], x1 = row[1];
        a0 += x0.x; a1 += x0.y; a2 += x0.z; a3 += x0.w;
        a4 += x1.x; a5 += x1.y; a6 += x1.z; a7 += x1.w;
    }
    float vals[8] = {a0,a1,a2,a3,a4,a5,a6,a7};
    union { __nv_bfloat16 h[8]; uint4 u; } H, L;
#pragma unroll
    for (int j = 0; j < 8; j++) {
        __nv_bfloat16 hi = __float2bfloat16(vals[j]);
        H.h[j] = hi;
        L.h[j] = __float2bfloat16(vals[j] - __bfloat162float(hi));
    }
    size_t base = (size_t)dst*256 + lane*8;
    *(uint4*)(g_G0h + base) = H.u;
    *(uint4*)(g_G0l + base) = L.u;
}

// ---------------- layer-0 combine: he = relu(t + v + b), split hi/lo ----------------
__global__ void k_combine0(const float* __restrict__ bias) {
    size_t idx8 = (size_t)blockIdx.x*blockDim.x + threadIdx.x;
    if (idx8 >= (size_t)NEx*NH/8) return;
    size_t idx = idx8*8;
    int e = (int)(idx / NH);
    int c = (int)(idx & 255);
    const float4* tb = (const float4*)(g_t + idx);
    const float4* vb = (const float4*)(g_v + idx);
    const float4* bb = (const float4*)(bias + e*256 + c);
    float4 t0 = tb[0], t1 = tb[1], v0 = vb[0], v1 = vb[1], b0 = bb[0], b1 = bb[1];
    float vals[8];
    vals[0]=t0.x+v0.x+b0.x; vals[1]=t0.y+v0.y+b0.y; vals[2]=t0.z+v0.z+b0.z; vals[3]=t0.w+v0.w+b0.w;
    vals[4]=t1.x+v1.x+b1.x; vals[5]=t1.y+v1.y+b1.y; vals[6]=t1.z+v1.z+b1.z; vals[7]=t1.w+v1.w+b1.w;
    union { __nv_bfloat16 h[8]; uint4 u; } H, L;
#pragma unroll
    for (int j = 0; j < 8; j++) {
        float v = fmaxf(vals[j], 0.f);
        __nv_bfloat16 hi = __float2bfloat16(v);
        H.h[j] = hi;
        L.h[j] = __float2bfloat16(v - __bfloat162float(hi));
    }
    *(uint4*)(g_Ah + idx) = H.u;
    *(uint4*)(g_Al + idx) = L.u;
}

// ---------------- SpMM + combine + bf16 split (layers 1-2): warp per (dst, expert) ----------------
__global__ void k_spmm_combine(const float* __restrict__ bias) {
    int dst = blockIdx.x;
    int e = threadIdx.x >> 5;
    int lane = threadIdx.x & 31;
    const float* vb = g_v + (size_t)e*NH + lane*8;
    int s0 = g_rowstart[dst], s1 = g_rowstart[dst+1];
    float a0=0.f,a1=0.f,a2=0.f,a3=0.f,a4=0.f,a5=0.f,a6=0.f,a7=0.f;
    for (int p = s0; p < s1; p++) {
        int src = g_csr_src[p];
        const float4* row = (const float4*)(vb + (size_t)src*256);
        float4 x0 = row[0], x1 = row[1];
        a0 += x0.x; a1 += x0.y; a2 += x0.z; a3 += x0.w;
        a4 += x1.x; a5 += x1.y; a6 += x1.z; a7 += x1.w;
    }
    size_t base = (size_t)e*NH + (size_t)dst*256 + lane*8;
    const float4* tb = (const float4*)(g_t + base);
    float4 t0 = tb[0], t1 = tb[1];
    const float4* bb = (const float4*)(bias + e*256 + lane*8);
    float4 b0 = bb[0], b1 = bb[1];
    float vals[8];
    vals[0]=t0.x+a0+b0.x; vals[1]=t0.y+a1+b0.y; vals[2]=t0.z+a2+b0.z; vals[3]=t0.w+a3+b0.w;
    vals[4]=t1.x+a4+b1.x; vals[5]=t1.y+a5+b1.y; vals[6]=t1.z+a6+b1.z; vals[7]=t1.w+a7+b1.w;
    union { __nv_bfloat16 h[8]; uint4 u; } H, L;
#pragma unroll
    for (int j = 0; j < 8; j++) {
        float v = fmaxf(vals[j], 0.f);
        __nv_bfloat16 hi = __float2bfloat16(v);
        H.h[j] = hi;
        L.h[j] = __float2bfloat16(v - __bfloat162float(hi));
    }
    *(uint4*)(g_Ah + base) = H.u;
    *(uint4*)(g_Al + base) = L.u;
}

// ---------------- output layer ----------------
__global__ void k_mz(const float* __restrict__ Wr, const float* __restrict__ Wn) {
    int idx = blockIdx.x*blockDim.x + threadIdx.x;
    if (idx >= NEx*Nn) return;
    int i = idx % Nn, e = idx / Nn;
    const uint4* ah = (const uint4*)(g_Ah + (size_t)e*NH + (size_t)i*256);
    const uint4* al = (const uint4*)(g_Al + (size_t)e*NH + (size_t)i*256);
    const float* WRe = Wr + e*512;
    const float* WNe = Wn + e*512;
    float m0=0.f, m1=0.f, z0=0.f, z1=0.f;
#pragma unroll 4
    for (int k8 = 0; k8 < 32; k8++) {
        uint4 vh = ah[k8], vl = al[k8];
        const __nv_bfloat16* ph = (const __nv_bfloat16*)&vh;
        const __nv_bfloat16* pl = (const __nv_bfloat16*)&vl;
#pragma unroll
        for (int j = 0; j < 8; j++) {
            float a = __bfloat162float(ph[j]) + __bfloat162float(pl[j]);
            int k = k8*8 + j;
            m0 += a*WRe[k*2];   m1 += a*WRe[k*2+1];
            z0 += a*WNe[k*2];   z1 += a*WNe[k*2+1];
        }
    }
    float* o = g_mz + (size_t)idx*4;
    o[0]=m0; o[1]=m1; o[2]=z0; o[3]=z1;
}

__global__ void k_aggz() {
    int idx = blockIdx.x*blockDim.x + threadIdx.x;
    if (idx >= NEx*Nn) return;
    int dst = idx % Nn;
    int e = idx / Nn;
    int s0 = g_rowstart[dst], s1 = g_rowstart[dst+1];
    float a0=0.f, a1=0.f;
    for (int p=s0; p<s1; p++) {
        int src = g_csr_src[p];
        const float* z = g_mz + ((size_t)e*Nn + src)*4 + 2;
        a0 += z[0]; a1 += z[1];
    }
    g_aggz[((size_t)e*Nn+dst)*2+0] = a0;
    g_aggz[((size_t)e*Nn+dst)*2+1] = a1;
}

__global__ void k_final(const float* __restrict__ outb, float* __restrict__ out) {
    int i = blockIdx.x*blockDim.x + threadIdx.x;
    if (i >= Nn) return;
    float o0=0.f, o1=0.f;
#pragma unroll
    for (int e=0;e<8;e++) {
        float s = g_sparse[i*8+e];
        const float* mz = g_mz + ((size_t)e*Nn+i)*4;
        const float* az = g_aggz + ((size_t)e*Nn+i)*2;
        o0 += s*(mz[0] + az[0] + outb[e*2+0]);
        o1 += s*(mz[1] + az[1] + outb[e*2+1]);
    }
    out[i*2+0] = o0;
    out[i*2+1] = o1;
}

// ---------------- launch ----------------
extern "C" void kernel_launch(void* const* d_in, const int* in_sizes, int n_in,
                              void* d_out, int out_size) {
    const float* x    = (const float*)d_in[0];
    const int*   ei   = (const int*)  d_in[1];
    const int*   batch= (const int*)  d_in[2];
    const float* encW = (const float*)d_in[3];
    const float* encb = (const float*)d_in[4];
    const float* rW1  = (const float*)d_in[5];
    const float* rb1  = (const float*)d_in[6];
    const float* rW2  = (const float*)d_in[7];
    const float* rb2  = (const float*)d_in[8];
    const float* hWr  = (const float*)d_in[9];
    const float* hWn  = (const float*)d_in[10];
    const float* hb   = (const float*)d_in[11];
    const float* oWr  = (const float*)d_in[12];
    const float* oWn  = (const float*)d_in[13];
    const float* ob   = (const float*)d_in[14];
    float* out = (float*)d_out;

    const int NTILES = (Nn + 127) / 128;   // 391
    dim3 gHalf(NTILES, 2, NEx);            // one m per launch
    dim3 gFull(NTILES, 2, NEx*2);          // both m
    dim3 gS(Nn, 1, 1);

    k_zero<<<(Nn+255)/256,256>>>();
    k_encoder<<<(NH+255)/256,256>>>(x, encW, encb);
    k_convW<<<(NMATS*65536+255)/256,256>>>(rW1, hWr, hWn);
    k_hgemm<<<gHalf,256>>>(0, 0, 1);   // L0 t = h @ Wr_e  (profiled slot)
    k_count_nodes<<<256,256>>>(batch);
    k_count_edges<<<512,256>>>(ei, batch);
    k_indeg<<<(Ee+255)/256,256>>>(ei);
    k_sizefeat<<<(Nn+255)/256,256>>>(batch);
    k_scan1<<<(Nn+1023)/1024,1024>>>();
    k_scan2<<<1,64>>>();
    k_scan3<<<(Nn+255)/256,256>>>();
    k_cursor<<<(Nn+255)/256,256>>>();
    k_scatter<<<(Ee+255)/256,256>>>(ei);

    // router (exact fp32 in its own buffer g_rt)
    {
        dim3 gR((Nn+127)/128, 2, 1);
        k_sgemm_router<<<gR,256>>>(rW1);
        k_router_epi<<<(NH+255)/256,256>>>(rW1, rb1);
        k_logits<<<(Nn*NEx+255)/256,256>>>(rW2, rb2);
        k_topk<<<(Nn+255)/256,256>>>();
    }

    // layer 0: shared aggregate of h, then v = agg(h) @ Wn_e
    k_spmm0<<<(Nn+7)/8,256>>>();
    k_hgemm<<<gHalf,256>>>(2, 1, 1);   // L0 v
    k_combine0<<<(NEx*NH/8+255)/256,256>>>(hb);

    // layers 1-2
    for (int l = 1; l < 3; l++) {
        k_hgemm<<<gFull,256>>>(1, -1, 1 + l*(NEx*2));
        k_spmm_combine<<<gS,256>>>(hb + (size_t)l*NEx*Hh);
    }

    // output layer
    k_mz<<<(NEx*Nn+255)/256,256>>>(oWr, oWn);
    k_aggz<<<(NEx*Nn+255)/256,256>>>();
    k_final<<<(Nn+255)/256,256>>>(ob, out);
}

// round 10
// speedup vs baseline: 1.1451x; 1.0178x over previous
#include <cuda_runtime.h>
#include <cuda_bf16.h>
#include <cstdint>
#include <math.h>

#define Nn 50000
#define Ee 800000
#define Gg 64
#define Ff 6
#define Hh 256
#define Oo 2
#define NEx 8
#define NH (Nn*Hh)
#define NMATS 49   // 1 router + 3 layers * 8 experts * 2

// ---------------- scratch (static __device__ arrays; no allocation) ----------------
__device__ __align__(128) float g_h[NH];                  // encoder output (fp32)
__device__ __align__(128) __nv_bfloat16 g_A0h[NH];        // encoder bf16 hi
__device__ __align__(128) __nv_bfloat16 g_A0l[NH];        // encoder bf16 lo
__device__ __align__(128) __nv_bfloat16 g_G0h[NH];        // agg(h) bf16 hi (layer-0, shared)
__device__ __align__(128) __nv_bfloat16 g_G0l[NH];        // agg(h) bf16 lo
__device__ __align__(128) float g_r[NH];                  // router hidden
__device__ __align__(128) float g_rt[NH];                 // router GEMM scratch
__device__ __align__(128) float g_t[NEx*NH];              // he @ Wr
__device__ __align__(128) float g_v[NEx*NH];              // he @ Wn (or agg@Wn for L0)
__device__ __align__(128) __nv_bfloat16 g_Ah[NEx*NH];     // per-expert activation bf16 hi
__device__ __align__(128) __nv_bfloat16 g_Al[NEx*NH];     // per-expert activation bf16 lo
__device__ __align__(128) __nv_bfloat16 g_Wth[NMATS*65536]; // weights bf16 hi [mat][n][k]
__device__ __align__(128) __nv_bfloat16 g_Wtl[NMATS*65536]; // weights bf16 lo
__device__ __align__(128) float g_sf[Nn*2];
__device__ __align__(128) float g_logits[Nn*NEx];
__device__ __align__(128) float g_sparse[Nn*NEx];
__device__ __align__(128) float g_mz[NEx*Nn*4];           // [m0,m1,z0,z1] per (e,node)
__device__ __align__(128) float g_aggz[NEx*Nn*2];
__device__ int g_nodecnt[Gg];
__device__ int g_edgecnt[Gg];
__device__ int g_indeg[Nn];
__device__ int g_scantmp[Nn];
__device__ int g_bsum[64];
__device__ int g_bsumscan[64];
__device__ int g_rowstart[Nn+1];
__device__ int g_cursor[Nn];
__device__ int g_csr_src[Ee];

// ======================= warp MMA helpers (plain-target: sm_80+) =======================
__device__ __forceinline__ uint32_t smem_to_u32(const void* smem_ptr) {
    uint32_t addr;
    asm("{ .reg .u64 tmp; cvta.to.shared.u64 tmp, %1; cvt.u32.u64 %0, tmp; }"
        : "=r"(addr) : "l"(smem_ptr));
    return addr;
}
#define LDSM4(r0,r1,r2,r3,addr) \
    asm volatile("ldmatrix.sync.aligned.m8n8.x4.shared.b16 {%0,%1,%2,%3}, [%4];" \
        : "=r"(r0), "=r"(r1), "=r"(r2), "=r"(r3) : "r"(addr))
#define MMA16816(c, a, b) \
    asm volatile("mma.sync.aligned.m16n8k16.row.col.f32.bf16.bf16.f32 " \
        "{%0,%1,%2,%3}, {%4,%5,%6,%7}, {%8,%9}, {%0,%1,%2,%3};" \
        : "+f"((c)[0]), "+f"((c)[1]), "+f"((c)[2]), "+f"((c)[3]) \
        : "r"((a)[0]), "r"((a)[1]), "r"((a)[2]), "r"((a)[3]), \
          "r"((b)[0]), "r"((b)[1]))
#define CPA16(dst, src) \
    asm volatile("cp.async.cg.shared.global [%0], [%1], 16;" :: "r"(dst), "l"(src))
#define CP_COMMIT() asm volatile("cp.async.commit_group;")
#define CP_WAIT1()  asm volatile("cp.async.wait_group 1;")
#define CP_WAIT0()  asm volatile("cp.async.wait_group 0;")

// ---------------- small kernels ----------------
__global__ void k_zero() {
    int i = blockIdx.x*blockDim.x + threadIdx.x;
    if (i < Gg) { g_nodecnt[i]=0; g_edgecnt[i]=0; }
    if (i < Nn) g_indeg[i]=0;
}

__global__ void k_encoder(const float* __restrict__ x, const float* __restrict__ W,
                          const float* __restrict__ b) {
    int idx = blockIdx.x*blockDim.x + threadIdx.x;
    if (idx >= NH) return;
    int i = idx >> 8, c = idx & 255;
    float acc = b[c];
#pragma unroll
    for (int k=0;k<Ff;k++) acc += x[i*Ff+k]*W[k*Hh+c];
    float v = fmaxf(acc, 0.f);
    g_h[idx] = v;
    __nv_bfloat16 hi = __float2bfloat16(v);
    g_A0h[idx] = hi;
    g_A0l[idx] = __float2bfloat16(v - __bfloat162float(hi));
}

// convert + transpose all weights to bf16 hi/lo, layout [mat][n][k]
__global__ void k_convW(const float* __restrict__ rW1, const float* __restrict__ hWr,
                        const float* __restrict__ hWn) {
    size_t idx = (size_t)blockIdx.x*blockDim.x + threadIdx.x;
    if (idx >= (size_t)NMATS*65536) return;
    int mat = (int)(idx >> 16);
    int r = (int)(idx & 65535);
    int n = r >> 8, k = r & 255;
    float w;
    if (mat == 0) {
        w = rW1[k*256 + n];
    } else {
        int hm = mat - 1;
        int l = hm >> 4, rr = hm & 15;
        int e = rr >> 1, m = rr & 1;
        const float* W = m ? hWn : hWr;
        w = W[((size_t)(l*NEx + e))*65536 + k*256 + n];
    }
    __nv_bfloat16 hi = __float2bfloat16(w);
    g_Wth[idx] = hi;
    g_Wtl[idx] = __float2bfloat16(w - __bfloat162float(hi));
}

__global__ void k_count_nodes(const int* __restrict__ batch) {
    __shared__ int hist[Gg];
    int t = threadIdx.x;
    if (t < Gg) hist[t]=0;
    __syncthreads();
    for (int i = blockIdx.x*blockDim.x + t; i < Nn; i += gridDim.x*blockDim.x)
        atomicAdd(&hist[batch[i]], 1);
    __syncthreads();
    if (t < Gg) atomicAdd(&g_nodecnt[t], hist[t]);
}

__global__ void k_count_edges(const int* __restrict__ ei, const int* __restrict__ batch) {
    __shared__ int hist[Gg];
    int t = threadIdx.x;
    if (t < Gg) hist[t]=0;
    __syncthreads();
    for (int e = blockIdx.x*blockDim.x + t; e < Ee; e += gridDim.x*blockDim.x)
        atomicAdd(&hist[batch[ei[e]]], 1);
    __syncthreads();
    if (t < Gg) atomicAdd(&g_edgecnt[t], hist[t]);
}

__global__ void k_indeg(const int* __restrict__ ei) {
    int e = blockIdx.x*blockDim.x + threadIdx.x;
    if (e < Ee) atomicAdd(&g_indeg[ei[Ee+e]], 1);
}

__global__ void k_sizefeat(const int* __restrict__ batch) {
    int i = blockIdx.x*blockDim.x + threadIdx.x;
    if (i >= Nn) return;
    int g = batch[i];
    g_sf[i*2+0] = logf((float)g_nodecnt[g] + 1.f);
    g_sf[i*2+1] = logf((float)g_edgecnt[g] + 1.f);
}

__global__ void k_scan1() {
    __shared__ int sh[1024];
    int t = threadIdx.x, gid = blockIdx.x*1024 + t;
    sh[t] = (gid < Nn) ? g_indeg[gid] : 0;
    __syncthreads();
    for (int off=1; off<1024; off<<=1) {
        int a = (t>=off) ? sh[t-off] : 0;
        __syncthreads();
        sh[t] += a;
        __syncthreads();
    }
    if (gid < Nn) g_scantmp[gid] = sh[t];
    if (t == 1023) g_bsum[blockIdx.x] = sh[1023];
}

__global__ void k_scan2() {
    __shared__ int sh[64];
    int t = threadIdx.x;
    const int NB1 = (Nn + 1023)/1024;
    sh[t] = (t < NB1) ? g_bsum[t] : 0;
    __syncthreads();
    for (int off=1; off<64; off<<=1) {
        int a = (t>=off) ? sh[t-off] : 0;
        __syncthreads();
        sh[t] += a;
        __syncthreads();
    }
    g_bsumscan[t] = sh[t];
}

__global__ void k_scan3() {
    int i = blockIdx.x*blockDim.x + threadIdx.x;
    if (i >= Nn) return;
    int blk = i >> 10;
    int incl = g_scantmp[i] + (blk ? g_bsumscan[blk-1] : 0);
    g_rowstart[i+1] = incl;
    if (i == 0) g_rowstart[0] = 0;
}

__global__ void k_cursor() {
    int i = blockIdx.x*blockDim.x + threadIdx.x;
    if (i < Nn) g_cursor[i] = g_rowstart[i];
}

__global__ void k_scatter(const int* __restrict__ ei) {
    int e = blockIdx.x*blockDim.x + threadIdx.x;
    if (e >= Ee) return;
    int d = ei[Ee+e];
    int p = atomicAdd(&g_cursor[d], 1);
    g_csr_src[p] = ei[e];
}

// ---------------- router SGEMM (exact fp32, tile 128x128) -> g_rt ----------------
__global__ void __launch_bounds__(256) k_sgemm_router(const float* __restrict__ B) {
    const float* A = g_h;
    float* Cb = g_rt;

    __shared__ float As[16][128];
    __shared__ float Bs[16][128];

    int tid = threadIdx.x;
    int bm = blockIdx.x*128, bn = blockIdx.y*128;
    int tx = tid & 15, ty = tid >> 4;
    int a_row = tid >> 2;
    int a_col = (tid & 3) * 4;
    int b_row = tid >> 5;
    int b_col = (tid & 31) * 4;

    float acc[8][8];
#pragma unroll
    for (int i=0;i<8;i++)
#pragma unroll
        for (int j=0;j<8;j++) acc[i][j]=0.f;

    for (int kt=0; kt<256; kt+=16) {
        __syncthreads();
#pragma unroll
        for (int i=0;i<2;i++) {
            int r = a_row + i*64;
            int gm = bm + r;
            float4 av = make_float4(0.f,0.f,0.f,0.f);
            if (gm < Nn) av = *(const float4*)(A + (size_t)gm*256 + kt + a_col);
            As[a_col+0][r]=av.x; As[a_col+1][r]=av.y;
            As[a_col+2][r]=av.z; As[a_col+3][r]=av.w;
        }
#pragma unroll
        for (int i=0;i<2;i++) {
            int r = b_row + i*8;
            *(float4*)&Bs[r][b_col] = *(const float4*)(B + (size_t)(kt+r)*256 + bn + b_col);
        }
        __syncthreads();
#pragma unroll
        for (int kk=0;kk<16;kk++) {
            float4 a0 = *(const float4*)&As[kk][ty*4];
            float4 a1 = *(const float4*)&As[kk][64+ty*4];
            float4 b0 = *(const float4*)&Bs[kk][tx*4];
            float4 b1 = *(const float4*)&Bs[kk][64+tx*4];
            float a[8] = {a0.x,a0.y,a0.z,a0.w,a1.x,a1.y,a1.z,a1.w};
            float b[8] = {b0.x,b0.y,b0.z,b0.w,b1.x,b1.y,b1.z,b1.w};
#pragma unroll
            for (int i=0;i<8;i++)
#pragma unroll
                for (int j=0;j<8;j++) acc[i][j] += a[i]*b[j];
        }
    }
#pragma unroll
    for (int ih=0; ih<2; ih++) {
#pragma unroll
        for (int i=0;i<4;i++) {
            int gm = bm + ih*64 + ty*4 + i;
            if (gm >= Nn) continue;
            float* crow = Cb + (size_t)gm*256 + bn;
            int r = ih*4 + i;
            *(float4*)(crow + tx*4)      = make_float4(acc[r][0],acc[r][1],acc[r][2],acc[r][3]);
            *(float4*)(crow + 64 + tx*4) = make_float4(acc[r][4],acc[r][5],acc[r][6],acc[r][7]);
        }
    }
}

// ============== HMMA bf16x3 GEMM, BK=32, 2-stage cp.async (dynamic smem) ==========
// asel: 0 -> A = g_A0 (shared h), 1 -> A = g_A(e), 2 -> A = g_G0 (shared agg(h))
// mSel: -1 -> z covers e*2+m ; 0/1 -> z covers e, m fixed
// Stage (40960B): Ah@0, Al@10240, Bh@20480, Bl@30720 — rows pitch 80B (conflict-free
// ldmatrix: row step = 20 banks, 8 distinct banks per phase). 2 stages = 81920B dyn.
#define HG_STAGE 40960
#define HG_SMEM  (2*HG_STAGE)

__global__ void __launch_bounds__(256, 2) k_hgemm(int asel, int mSel, int matBase)
{
    extern __shared__ __align__(16) char hg_smem[];
    uint32_t sbase = smem_to_u32(hg_smem);
    int tid = threadIdx.x, lane = tid & 31, wid = tid >> 5;
    int bm = blockIdx.x * 128, bn = blockIdx.y * 128;
    int z = blockIdx.z;
    int e, m;
    if (mSel < 0) { e = z >> 1; m = z & 1; } else { e = z; m = mSel; }
    int mat = matBase + e*2 + m;

    const __nv_bfloat16 *Abh, *Abl;
    if (asel == 0)      { Abh = g_A0h; Abl = g_A0l; }
    else if (asel == 1) { Abh = g_Ah + (size_t)e*NH; Abl = g_Al + (size_t)e*NH; }
    else                { Abh = g_G0h; Abl = g_G0l; }
    const __nv_bfloat16* Bh = g_Wth + (size_t)mat * 65536;
    const __nv_bfloat16* Bl = g_Wtl + (size_t)mat * 65536;

    int wm = (wid & 3) * 32;
    int wn = (wid >> 2) * 64;

    float c[2][8][4];
#pragma unroll
    for (int mi=0;mi<2;mi++)
#pragma unroll
        for (int nf=0;nf<8;nf++)
#pragma unroll
            for (int r=0;r<4;r++) c[mi][nf][r] = 0.f;

    // cp.async slots: each thread loads 2 16B chunks per array (8 total per stage)
    int lrow = tid >> 1, lch = tid & 1;
    int agr = bm + lrow; if (agr >= Nn) agr = Nn - 1;   // clamp: junk rows masked on store
    const __nv_bfloat16* srcAh = Abh + (size_t)agr*256 + lch*8;
    const __nv_bfloat16* srcAl = Abl + (size_t)agr*256 + lch*8;
    const __nv_bfloat16* srcBh = Bh + (size_t)(bn + lrow)*256 + lch*8;
    const __nv_bfloat16* srcBl = Bl + (size_t)(bn + lrow)*256 + lch*8;
    uint32_t dstOff = (uint32_t)lrow*80 + (uint32_t)lch*16;

    // prologue: stage 0 (k [0,32))
    {
        uint32_t d = sbase + dstOff;
        CPA16(d,            srcAh);
        CPA16(d + 32,       srcAh + 16);
        CPA16(d + 10240,    srcAl);
        CPA16(d + 10272,    srcAl + 16);
        CPA16(d + 20480,    srcBh);
        CPA16(d + 20512,    srcBh + 16);
        CPA16(d + 30720,    srcBl);
        CPA16(d + 30752,    srcBl + 16);
        CP_COMMIT();
    }

    int rsel = lane & 15;
    int cofs = (lane & 16) ? 16 : 0;

    for (int kt = 0; kt < 8; kt++) {
        if (kt < 7) {
            int k0 = (kt + 1) * 32;
            uint32_t d = sbase + ((kt + 1) & 1) * HG_STAGE + dstOff;
            CPA16(d,            srcAh + k0);
            CPA16(d + 32,       srcAh + k0 + 16);
            CPA16(d + 10240,    srcAl + k0);
            CPA16(d + 10272,    srcAl + k0 + 16);
            CPA16(d + 20480,    srcBh + k0);
            CPA16(d + 20512,    srcBh + k0 + 16);
            CPA16(d + 30720,    srcBl + k0);
            CPA16(d + 30752,    srcBl + k0 + 16);
            CP_COMMIT();
            CP_WAIT1();
        } else {
            CP_WAIT0();
        }
        __syncthreads();
        uint32_t buf = sbase + (kt & 1) * HG_STAGE;

#pragma unroll
        for (int half = 0; half < 2; half++) {
            uint32_t hcol = (uint32_t)(half*32 + cofs);
            uint32_t a_h[2][4], a_l[2][4];
#pragma unroll
            for (int mi = 0; mi < 2; mi++) {
                uint32_t ro = buf + (uint32_t)(wm + mi*16 + rsel) * 80 + hcol;
                LDSM4(a_h[mi][0], a_h[mi][1], a_h[mi][2], a_h[mi][3], ro);
                LDSM4(a_l[mi][0], a_l[mi][1], a_l[mi][2], a_l[mi][3], ro + 10240);
            }
            uint32_t b_h[8][2], b_l[8][2];
#pragma unroll
            for (int np = 0; np < 4; np++) {
                uint32_t ro = buf + 20480 + (uint32_t)(wn + np*16 + rsel) * 80 + hcol;
                uint32_t r0, r1, r2, r3;
                LDSM4(r0, r1, r2, r3, ro);
                b_h[np*2][0]=r0; b_h[np*2+1][0]=r1; b_h[np*2][1]=r2; b_h[np*2+1][1]=r3;
                LDSM4(r0, r1, r2, r3, ro + 10240);
                b_l[np*2][0]=r0; b_l[np*2+1][0]=r1; b_l[np*2][1]=r2; b_l[np*2+1][1]=r3;
            }
#pragma unroll
            for (int mi = 0; mi < 2; mi++)
#pragma unroll
                for (int nf = 0; nf < 8; nf++)
                    MMA16816(c[mi][nf], a_h[mi], b_h[nf]);
#pragma unroll
            for (int mi = 0; mi < 2; mi++)
#pragma unroll
                for (int nf = 0; nf < 8; nf++)
                    MMA16816(c[mi][nf], a_h[mi], b_l[nf]);
#pragma unroll
            for (int mi = 0; mi < 2; mi++)
#pragma unroll
                for (int nf = 0; nf < 8; nf++)
                    MMA16816(c[mi][nf], a_l[mi], b_h[nf]);
        }
        __syncthreads();
    }

    float* C = (m ? g_v : g_t) + (size_t)e * NH;
#pragma unroll
    for (int mi = 0; mi < 2; mi++) {
        int row0 = bm + wm + mi*16 + (lane >> 2);
#pragma unroll
        for (int nf = 0; nf < 8; nf++) {
            int col = bn + wn + nf*8 + (lane & 3)*2;
            if (row0 < Nn)
                *(float2*)(C + (size_t)row0*256 + col) = make_float2(c[mi][nf][0], c[mi][nf][1]);
            if (row0 + 8 < Nn)
                *(float2*)(C + (size_t)(row0+8)*256 + col) = make_float2(c[mi][nf][2], c[mi][nf][3]);
        }
    }
}

// ---------------- router epilogue ----------------
__global__ void k_router_epi(const float* __restrict__ W1, const float* __restrict__ b1) {
    int idx = blockIdx.x*blockDim.x + threadIdx.x;
    if (idx >= NH) return;
    int i = idx >> 8, c = idx & 255;
    float v = g_rt[idx] + g_sf[i*2]*W1[256*256+c] + g_sf[i*2+1]*W1[257*256+c] + b1[c];
    g_r[idx] = fmaxf(v, 0.f);
}

__global__ void k_logits(const float* __restrict__ W2, const float* __restrict__ b2) {
    int idx = blockIdx.x*blockDim.x + threadIdx.x;
    if (idx >= Nn*NEx) return;
    int i = idx >> 3, e2 = idx & 7;
    const float* r = g_r + (size_t)i*256;
    float acc = b2[e2];
#pragma unroll 8
    for (int k=0;k<256;k++) acc += r[k]*W2[k*8+e2];
    g_logits[idx] = acc;
}

__global__ void k_topk() {
    int i = blockIdx.x*blockDim.x + threadIdx.x;
    if (i >= Nn) return;
    float l[8];
#pragma unroll
    for (int e=0;e<8;e++) l[e] = g_logits[i*8+e];
    int i1 = 0; float m1 = l[0];
#pragma unroll
    for (int e=1;e<8;e++) if (l[e] > m1) { m1 = l[e]; i1 = e; }
    int i2 = -1; float m2 = -1e30f;
#pragma unroll
    for (int e=0;e<8;e++) if (e != i1 && l[e] > m2) { m2 = l[e]; i2 = e; }
    float e2v = expf(m2 - m1);
    float inv = 1.f/(1.f + e2v);
    float s[8];
#pragma unroll
    for (int e=0;e<8;e++) s[e]=0.f;
    s[i1] = inv; s[i2] = e2v*inv;
#pragma unroll
    for (int e=0;e<8;e++) g_sparse[i*8+e] = s[e];
}

// ---------------- layer-0 SpMM: agg(h) once, shared across experts ----------------
__global__ void k_spmm0() {
    int dst = blockIdx.x*8 + (threadIdx.x >> 5);
    int lane = threadIdx.x & 31;
    if (dst >= Nn) return;
    const float* vb = g_h + lane*8;
    int s0 = g_rowstart[dst], s1 = g_rowstart[dst+1];
    float a0=0.f,a1=0.f,a2=0.f,a3=0.f,a4=0.f,a5=0.f,a6=0.f,a7=0.f;
    for (int p = s0; p < s1; p++) {
        int src = g_csr_src[p];
        const float4* row = (const float4*)(vb + (size_t)src*256);
        float4 x0 = row[0], x1 = row[1];
        a0 += x0.x; a1 += x0.y; a2 += x0.z; a3 += x0.w;
        a4 += x1.x; a5 += x1.y; a6 += x1.z; a7 += x1.w;
    }
    float vals[8] = {a0,a1,a2,a3,a4,a5,a6,a7};
    union { __nv_bfloat16 h[8]; uint4 u; } H, L;
#pragma unroll
    for (int j = 0; j < 8; j++) {
        __nv_bfloat16 hi = __float2bfloat16(vals[j]);
        H.h[j] = hi;
        L.h[j] = __float2bfloat16(vals[j] - __bfloat162float(hi));
    }
    size_t base = (size_t)dst*256 + lane*8;
    *(uint4*)(g_G0h + base) = H.u;
    *(uint4*)(g_G0l + base) = L.u;
}

// ---------------- layer-0 combine: he = relu(t + v + b), split hi/lo ----------------
__global__ void k_combine0(const float* __restrict__ bias) {
    size_t idx8 = (size_t)blockIdx.x*blockDim.x + threadIdx.x;
    if (idx8 >= (size_t)NEx*NH/8) return;
    size_t idx = idx8*8;
    int e = (int)(idx / NH);
    int c = (int)(idx & 255);
    const float4* tb = (const float4*)(g_t + idx);
    const float4* vb = (const float4*)(g_v + idx);
    const float4* bb = (const float4*)(bias + e*256 + c);
    float4 t0 = tb[0], t1 = tb[1], v0 = vb[0], v1 = vb[1], b0 = bb[0], b1 = bb[1];
    float vals[8];
    vals[0]=t0.x+v0.x+b0.x; vals[1]=t0.y+v0.y+b0.y; vals[2]=t0.z+v0.z+b0.z; vals[3]=t0.w+v0.w+b0.w;
    vals[4]=t1.x+v1.x+b1.x; vals[5]=t1.y+v1.y+b1.y; vals[6]=t1.z+v1.z+b1.z; vals[7]=t1.w+v1.w+b1.w;
    union { __nv_bfloat16 h[8]; uint4 u; } H, L;
#pragma unroll
    for (int j = 0; j < 8; j++) {
        float v = fmaxf(vals[j], 0.f);
        __nv_bfloat16 hi = __float2bfloat16(v);
        H.h[j] = hi;
        L.h[j] = __float2bfloat16(v - __bfloat162float(hi));
    }
    *(uint4*)(g_Ah + idx) = H.u;
    *(uint4*)(g_Al + idx) = L.u;
}

// ---------------- SpMM + combine + bf16 split (layers 1-2): warp per (dst, expert) ----------------
__global__ void k_spmm_combine(const float* __restrict__ bias) {
    int dst = blockIdx.x;
    int e = threadIdx.x >> 5;
    int lane = threadIdx.x & 31;
    const float* vb = g_v + (size_t)e*NH + lane*8;
    int s0 = g_rowstart[dst], s1 = g_rowstart[dst+1];
    float a0=0.f,a1=0.f,a2=0.f,a3=0.f,a4=0.f,a5=0.f,a6=0.f,a7=0.f;
    for (int p = s0; p < s1; p++) {
        int src = g_csr_src[p];
        const float4* row = (const float4*)(vb + (size_t)src*256);
        float4 x0 = row[0], x1 = row[1];
        a0 += x0.x; a1 += x0.y; a2 += x0.z; a3 += x0.w;
        a4 += x1.x; a5 += x1.y; a6 += x1.z; a7 += x1.w;
    }
    size_t base = (size_t)e*NH + (size_t)dst*256 + lane*8;
    const float4* tb = (const float4*)(g_t + base);
    float4 t0 = tb[0], t1 = tb[1];
    const float4* bb = (const float4*)(bias + e*256 + lane*8);
    float4 b0 = bb[0], b1 = bb[1];
    float vals[8];
    vals[0]=t0.x+a0+b0.x; vals[1]=t0.y+a1+b0.y; vals[2]=t0.z+a2+b0.z; vals[3]=t0.w+a3+b0.w;
    vals[4]=t1.x+a4+b1.x; vals[5]=t1.y+a5+b1.y; vals[6]=t1.z+a6+b1.z; vals[7]=t1.w+a7+b1.w;
    union { __nv_bfloat16 h[8]; uint4 u; } H, L;
#pragma unroll
    for (int j = 0; j < 8; j++) {
        float v = fmaxf(vals[j], 0.f);
        __nv_bfloat16 hi = __float2bfloat16(v);
        H.h[j] = hi;
        L.h[j] = __float2bfloat16(v - __bfloat162float(hi));
    }
    *(uint4*)(g_Ah + base) = H.u;
    *(uint4*)(g_Al + base) = L.u;
}

// ---------------- output layer ----------------
__global__ void k_mz(const float* __restrict__ Wr, const float* __restrict__ Wn) {
    int idx = blockIdx.x*blockDim.x + threadIdx.x;
    if (idx >= NEx*Nn) return;
    int i = idx % Nn, e = idx / Nn;
    const uint4* ah = (const uint4*)(g_Ah + (size_t)e*NH + (size_t)i*256);
    const uint4* al = (const uint4*)(g_Al + (size_t)e*NH + (size_t)i*256);
    const float* WRe = Wr + e*512;
    const float* WNe = Wn + e*512;
    float m0=0.f, m1=0.f, z0=0.f, z1=0.f;
#pragma unroll 4
    for (int k8 = 0; k8 < 32; k8++) {
        uint4 vh = ah[k8], vl = al[k8];
        const __nv_bfloat16* ph = (const __nv_bfloat16*)&vh;
        const __nv_bfloat16* pl = (const __nv_bfloat16*)&vl;
#pragma unroll
        for (int j = 0; j < 8; j++) {
            float a = __bfloat162float(ph[j]) + __bfloat162float(pl[j]);
            int k = k8*8 + j;
            m0 += a*WRe[k*2];   m1 += a*WRe[k*2+1];
            z0 += a*WNe[k*2];   z1 += a*WNe[k*2+1];
        }
    }
    float* o = g_mz + (size_t)idx*4;
    o[0]=m0; o[1]=m1; o[2]=z0; o[3]=z1;
}

__global__ void k_aggz() {
    int idx = blockIdx.x*blockDim.x + threadIdx.x;
    if (idx >= NEx*Nn) return;
    int dst = idx % Nn;
    int e = idx / Nn;
    int s0 = g_rowstart[dst], s1 = g_rowstart[dst+1];
    float a0=0.f, a1=0.f;
    for (int p=s0; p<s1; p++) {
        int src = g_csr_src[p];
        const float* z = g_mz + ((size_t)e*Nn + src)*4 + 2;
        a0 += z[0]; a1 += z[1];
    }
    g_aggz[((size_t)e*Nn+dst)*2+0] = a0;
    g_aggz[((size_t)e*Nn+dst)*2+1] = a1;
}

__global__ void k_final(const float* __restrict__ outb, float* __restrict__ out) {
    int i = blockIdx.x*blockDim.x + threadIdx.x;
    if (i >= Nn) return;
    float o0=0.f, o1=0.f;
#pragma unroll
    for (int e=0;e<8;e++) {
        float s = g_sparse[i*8+e];
        const float* mz = g_mz + ((size_t)e*Nn+i)*4;
        const float* az = g_aggz + ((size_t)e*Nn+i)*2;
        o0 += s*(mz[0] + az[0] + outb[e*2+0]);
        o1 += s*(mz[1] + az[1] + outb[e*2+1]);
    }
    out[i*2+0] = o0;
    out[i*2+1] = o1;
}

// ---------------- launch ----------------
extern "C" void kernel_launch(void* const* d_in, const int* in_sizes, int n_in,
                              void* d_out, int out_size) {
    const float* x    = (const float*)d_in[0];
    const int*   ei   = (const int*)  d_in[1];
    const int*   batch= (const int*)  d_in[2];
    const float* encW = (const float*)d_in[3];
    const float* encb = (const float*)d_in[4];
    const float* rW1  = (const float*)d_in[5];
    const float* rb1  = (const float*)d_in[6];
    const float* rW2  = (const float*)d_in[7];
    const float* rb2  = (const float*)d_in[8];
    const float* hWr  = (const float*)d_in[9];
    const float* hWn  = (const float*)d_in[10];
    const float* hb   = (const float*)d_in[11];
    const float* oWr  = (const float*)d_in[12];
    const float* oWn  = (const float*)d_in[13];
    const float* ob   = (const float*)d_in[14];
    float* out = (float*)d_out;

    cudaFuncSetAttribute(k_hgemm, cudaFuncAttributeMaxDynamicSharedMemorySize, HG_SMEM);

    const int NTILES = (Nn + 127) / 128;   // 391
    dim3 gHalf(NTILES, 2, NEx);            // one m per launch
    dim3 gFull(NTILES, 2, NEx*2);          // both m
    dim3 gS(Nn, 1, 1);

    k_zero<<<(Nn+255)/256,256>>>();
    k_encoder<<<(NH+255)/256,256>>>(x, encW, encb);
    k_convW<<<(NMATS*65536+255)/256,256>>>(rW1, hWr, hWn);
    k_hgemm<<<gHalf,256,HG_SMEM>>>(0, 0, 1);   // L0 t = h @ Wr_e  (profiled slot)
    k_count_nodes<<<256,256>>>(batch);
    k_count_edges<<<512,256>>>(ei, batch);
    k_indeg<<<(Ee+255)/256,256>>>(ei);
    k_sizefeat<<<(Nn+255)/256,256>>>(batch);
    k_scan1<<<(Nn+1023)/1024,1024>>>();
    k_scan2<<<1,64>>>();
    k_scan3<<<(Nn+255)/256,256>>>();
    k_cursor<<<(Nn+255)/256,256>>>();
    k_scatter<<<(Ee+255)/256,256>>>(ei);

    // router (exact fp32 in its own buffer g_rt)
    {
        dim3 gR((Nn+127)/128, 2, 1);
        k_sgemm_router<<<gR,256>>>(rW1);
        k_router_epi<<<(NH+255)/256,256>>>(rW1, rb1);
        k_logits<<<(Nn*NEx+255)/256,256>>>(rW2, rb2);
        k_topk<<<(Nn+255)/256,256>>>();
    }

    // layer 0: shared aggregate of h, then v = agg(h) @ Wn_e
    k_spmm0<<<(Nn+7)/8,256>>>();
    k_hgemm<<<gHalf,256,HG_SMEM>>>(2, 1, 1);   // L0 v
    k_combine0<<<(NEx*NH/8+255)/256,256>>>(hb);

    // layers 1-2
    for (int l = 1; l < 3; l++) {
        k_hgemm<<<gFull,256,HG_SMEM>>>(1, -1, 1 + l*(NEx*2));
        k_spmm_combine<<<gS,256>>>(hb + (size_t)l*NEx*Hh);
    }

    // output layer
    k_mz<<<(NEx*Nn+255)/256,256>>>(oWr, oWn);
    k_aggz<<<(NEx*Nn+255)/256,256>>>();
    k_final<<<(Nn+255)/256,256>>>(ob, out);
}

// round 11
// speedup vs baseline: 1.2748x; 1.1133x over previous
#include <cuda_runtime.h>
#include <cuda_bf16.h>
#include <cstdint>
#include <math.h>

#define Nn 50000
#define Ee 800000
#define Gg 64
#define Ff 6
#define Hh 256
#define Oo 2
#define NEx 8
#define NH (Nn*Hh)
#define NMATS 49   // 1 router + 3 layers * 8 experts * 2

// ---------------- scratch (static __device__ arrays; no allocation) ----------------
__device__ __align__(128) float g_h[NH];                  // encoder output (fp32)
__device__ __align__(128) __nv_bfloat16 g_A0h[NH];        // encoder bf16 hi
__device__ __align__(128) __nv_bfloat16 g_A0l[NH];        // encoder bf16 lo
__device__ __align__(128) __nv_bfloat16 g_G0h[NH];        // agg(h) bf16 hi (layer-0, shared)
__device__ __align__(128) __nv_bfloat16 g_G0l[NH];        // agg(h) bf16 lo
__device__ __align__(128) float g_r[NH];                  // router hidden
__device__ __align__(128) float g_rt[NH];                 // router GEMM scratch
__device__ __align__(128) float g_t[NEx*NH];              // he @ Wr
__device__ __align__(128) float g_v[NEx*NH];              // he @ Wn (or agg@Wn for L0)
__device__ __align__(128) __nv_bfloat16 g_Ah[NEx*NH];     // per-expert activation bf16 hi
__device__ __align__(128) __nv_bfloat16 g_Al[NEx*NH];     // per-expert activation bf16 lo
__device__ __align__(128) __nv_bfloat16 g_Wth[NMATS*65536]; // weights bf16 hi [mat][n][k]
__device__ __align__(128) __nv_bfloat16 g_Wtl[NMATS*65536]; // weights bf16 lo
__device__ __align__(128) float g_sf[Nn*2];
__device__ __align__(128) float g_logits[Nn*NEx];
__device__ __align__(128) float g_sparse[Nn*NEx];
__device__ __align__(128) float g_mz[NEx*Nn*4];           // [m0,m1,z0,z1] per (e,node)
__device__ __align__(128) float g_aggz[NEx*Nn*2];
__device__ int g_nodecnt[Gg];
__device__ int g_edgecnt[Gg];
__device__ int g_indeg[Nn];
__device__ int g_scantmp[Nn];
__device__ int g_bsum[64];
__device__ int g_bsumscan[64];
__device__ int g_rowstart[Nn+1];
__device__ int g_cursor[Nn];
__device__ int g_csr_src[Ee];

// ======================= warp MMA helpers (plain-target: sm_80+) =======================
__device__ __forceinline__ uint32_t smem_to_u32(const void* smem_ptr) {
    uint32_t addr;
    asm("{ .reg .u64 tmp; cvta.to.shared.u64 tmp, %1; cvt.u32.u64 %0, tmp; }"
        : "=r"(addr) : "l"(smem_ptr));
    return addr;
}
#define LDSM4(r0,r1,r2,r3,addr) \
    asm volatile("ldmatrix.sync.aligned.m8n8.x4.shared.b16 {%0,%1,%2,%3}, [%4];" \
        : "=r"(r0), "=r"(r1), "=r"(r2), "=r"(r3) : "r"(addr))
#define MMA16816(c, a, b) \
    asm volatile("mma.sync.aligned.m16n8k16.row.col.f32.bf16.bf16.f32 " \
        "{%0,%1,%2,%3}, {%4,%5,%6,%7}, {%8,%9}, {%0,%1,%2,%3};" \
        : "+f"((c)[0]), "+f"((c)[1]), "+f"((c)[2]), "+f"((c)[3]) \
        : "r"((a)[0]), "r"((a)[1]), "r"((a)[2]), "r"((a)[3]), \
          "r"((b)[0]), "r"((b)[1]))
#define CPA16(dst, src) \
    asm volatile("cp.async.cg.shared.global [%0], [%1], 16;" :: "r"(dst), "l"(src))
#define CP_COMMIT() asm volatile("cp.async.commit_group;")
#define CP_WAIT1()  asm volatile("cp.async.wait_group 1;")
#define CP_WAIT0()  asm volatile("cp.async.wait_group 0;")

// ---------------- small kernels ----------------
__global__ void k_zero() {
    int i = blockIdx.x*blockDim.x + threadIdx.x;
    if (i < Gg) { g_nodecnt[i]=0; g_edgecnt[i]=0; }
    if (i < Nn) g_indeg[i]=0;
}

__global__ void k_encoder(const float* __restrict__ x, const float* __restrict__ W,
                          const float* __restrict__ b) {
    int idx = blockIdx.x*blockDim.x + threadIdx.x;
    if (idx >= NH) return;
    int i = idx >> 8, c = idx & 255;
    float acc = b[c];
#pragma unroll
    for (int k=0;k<Ff;k++) acc += x[i*Ff+k]*W[k*Hh+c];
    float v = fmaxf(acc, 0.f);
    g_h[idx] = v;
    __nv_bfloat16 hi = __float2bfloat16(v);
    g_A0h[idx] = hi;
    g_A0l[idx] = __float2bfloat16(v - __bfloat162float(hi));
}

// convert + transpose all weights to bf16 hi/lo, layout [mat][n][k]
__global__ void k_convW(const float* __restrict__ rW1, const float* __restrict__ hWr,
                        const float* __restrict__ hWn) {
    size_t idx = (size_t)blockIdx.x*blockDim.x + threadIdx.x;
    if (idx >= (size_t)NMATS*65536) return;
    int mat = (int)(idx >> 16);
    int r = (int)(idx & 65535);
    int n = r >> 8, k = r & 255;
    float w;
    if (mat == 0) {
        w = rW1[k*256 + n];
    } else {
        int hm = mat - 1;
        int l = hm >> 4, rr = hm & 15;
        int e = rr >> 1, m = rr & 1;
        const float* W = m ? hWn : hWr;
        w = W[((size_t)(l*NEx + e))*65536 + k*256 + n];
    }
    __nv_bfloat16 hi = __float2bfloat16(w);
    g_Wth[idx] = hi;
    g_Wtl[idx] = __float2bfloat16(w - __bfloat162float(hi));
}

__global__ void k_count_nodes(const int* __restrict__ batch) {
    __shared__ int hist[Gg];
    int t = threadIdx.x;
    if (t < Gg) hist[t]=0;
    __syncthreads();
    for (int i = blockIdx.x*blockDim.x + t; i < Nn; i += gridDim.x*blockDim.x)
        atomicAdd(&hist[batch[i]], 1);
    __syncthreads();
    if (t < Gg) atomicAdd(&g_nodecnt[t], hist[t]);
}

__global__ void k_count_edges(const int* __restrict__ ei, const int* __restrict__ batch) {
    __shared__ int hist[Gg];
    int t = threadIdx.x;
    if (t < Gg) hist[t]=0;
    __syncthreads();
    for (int e = blockIdx.x*blockDim.x + t; e < Ee; e += gridDim.x*blockDim.x)
        atomicAdd(&hist[batch[ei[e]]], 1);
    __syncthreads();
    if (t < Gg) atomicAdd(&g_edgecnt[t], hist[t]);
}

__global__ void k_indeg(const int* __restrict__ ei) {
    int e = blockIdx.x*blockDim.x + threadIdx.x;
    if (e < Ee) atomicAdd(&g_indeg[ei[Ee+e]], 1);
}

__global__ void k_sizefeat(const int* __restrict__ batch) {
    int i = blockIdx.x*blockDim.x + threadIdx.x;
    if (i >= Nn) return;
    int g = batch[i];
    g_sf[i*2+0] = logf((float)g_nodecnt[g] + 1.f);
    g_sf[i*2+1] = logf((float)g_edgecnt[g] + 1.f);
}

__global__ void k_scan1() {
    __shared__ int sh[1024];
    int t = threadIdx.x, gid = blockIdx.x*1024 + t;
    sh[t] = (gid < Nn) ? g_indeg[gid] : 0;
    __syncthreads();
    for (int off=1; off<1024; off<<=1) {
        int a = (t>=off) ? sh[t-off] : 0;
        __syncthreads();
        sh[t] += a;
        __syncthreads();
    }
    if (gid < Nn) g_scantmp[gid] = sh[t];
    if (t == 1023) g_bsum[blockIdx.x] = sh[1023];
}

__global__ void k_scan2() {
    __shared__ int sh[64];
    int t = threadIdx.x;
    const int NB1 = (Nn + 1023)/1024;
    sh[t] = (t < NB1) ? g_bsum[t] : 0;
    __syncthreads();
    for (int off=1; off<64; off<<=1) {
        int a = (t>=off) ? sh[t-off] : 0;
        __syncthreads();
        sh[t] += a;
        __syncthreads();
    }
    g_bsumscan[t] = sh[t];
}

__global__ void k_scan3() {
    int i = blockIdx.x*blockDim.x + threadIdx.x;
    if (i >= Nn) return;
    int blk = i >> 10;
    int incl = g_scantmp[i] + (blk ? g_bsumscan[blk-1] : 0);
    g_rowstart[i+1] = incl;
    if (i == 0) g_rowstart[0] = 0;
}

__global__ void k_cursor() {
    int i = blockIdx.x*blockDim.x + threadIdx.x;
    if (i < Nn) g_cursor[i] = g_rowstart[i];
}

__global__ void k_scatter(const int* __restrict__ ei) {
    int e = blockIdx.x*blockDim.x + threadIdx.x;
    if (e >= Ee) return;
    int d = ei[Ee+e];
    int p = atomicAdd(&g_cursor[d], 1);
    g_csr_src[p] = ei[e];
}

// ---------------- router SGEMM (exact fp32, tile 128x128) -> g_rt ----------------
__global__ void __launch_bounds__(256) k_sgemm_router(const float* __restrict__ B) {
    const float* A = g_h;
    float* Cb = g_rt;

    __shared__ float As[16][128];
    __shared__ float Bs[16][128];

    int tid = threadIdx.x;
    int bm = blockIdx.x*128, bn = blockIdx.y*128;
    int tx = tid & 15, ty = tid >> 4;
    int a_row = tid >> 2;
    int a_col = (tid & 3) * 4;
    int b_row = tid >> 5;
    int b_col = (tid & 31) * 4;

    float acc[8][8];
#pragma unroll
    for (int i=0;i<8;i++)
#pragma unroll
        for (int j=0;j<8;j++) acc[i][j]=0.f;

    for (int kt=0; kt<256; kt+=16) {
        __syncthreads();
#pragma unroll
        for (int i=0;i<2;i++) {
            int r = a_row + i*64;
            int gm = bm + r;
            float4 av = make_float4(0.f,0.f,0.f,0.f);
            if (gm < Nn) av = *(const float4*)(A + (size_t)gm*256 + kt + a_col);
            As[a_col+0][r]=av.x; As[a_col+1][r]=av.y;
            As[a_col+2][r]=av.z; As[a_col+3][r]=av.w;
        }
#pragma unroll
        for (int i=0;i<2;i++) {
            int r = b_row + i*8;
            *(float4*)&Bs[r][b_col] = *(const float4*)(B + (size_t)(kt+r)*256 + bn + b_col);
        }
        __syncthreads();
#pragma unroll
        for (int kk=0;kk<16;kk++) {
            float4 a0 = *(const float4*)&As[kk][ty*4];
            float4 a1 = *(const float4*)&As[kk][64+ty*4];
            float4 b0 = *(const float4*)&Bs[kk][tx*4];
            float4 b1 = *(const float4*)&Bs[kk][64+tx*4];
            float a[8] = {a0.x,a0.y,a0.z,a0.w,a1.x,a1.y,a1.z,a1.w};
            float b[8] = {b0.x,b0.y,b0.z,b0.w,b1.x,b1.y,b1.z,b1.w};
#pragma unroll
            for (int i=0;i<8;i++)
#pragma unroll
                for (int j=0;j<8;j++) acc[i][j] += a[i]*b[j];
        }
    }
#pragma unroll
    for (int ih=0; ih<2; ih++) {
#pragma unroll
        for (int i=0;i<4;i++) {
            int gm = bm + ih*64 + ty*4 + i;
            if (gm >= Nn) continue;
            float* crow = Cb + (size_t)gm*256 + bn;
            int r = ih*4 + i;
            *(float4*)(crow + tx*4)      = make_float4(acc[r][0],acc[r][1],acc[r][2],acc[r][3]);
            *(float4*)(crow + 64 + tx*4) = make_float4(acc[r][4],acc[r][5],acc[r][6],acc[r][7]);
        }
    }
}

// ============== HMMA bf16x3 GEMM, BK=32, 2-stage cp.async (dynamic smem) ==========
// asel: 0 -> A = g_A0 (shared h), 1 -> A = g_A(e), 2 -> A = g_G0 (shared agg(h))
// mSel: -1 -> z covers e*2+m ; 0/1 -> z covers e, m fixed
// Stage (40960B): Ah@0, Al@10240, Bh@20480, Bl@30720 — rows pitch 80B. 2 stages dyn.
#define HG_STAGE 40960
#define HG_SMEM  (2*HG_STAGE)

__global__ void __launch_bounds__(256, 2) k_hgemm(int asel, int mSel, int matBase)
{
    extern __shared__ __align__(16) char hg_smem[];
    uint32_t sbase = smem_to_u32(hg_smem);
    int tid = threadIdx.x, lane = tid & 31, wid = tid >> 5;
    int bm = blockIdx.x * 128, bn = blockIdx.y * 128;
    int z = blockIdx.z;
    int e, m;
    if (mSel < 0) { e = z >> 1; m = z & 1; } else { e = z; m = mSel; }
    int mat = matBase + e*2 + m;

    const __nv_bfloat16 *Abh, *Abl;
    if (asel == 0)      { Abh = g_A0h; Abl = g_A0l; }
    else if (asel == 1) { Abh = g_Ah + (size_t)e*NH; Abl = g_Al + (size_t)e*NH; }
    else                { Abh = g_G0h; Abl = g_G0l; }
    const __nv_bfloat16* Bh = g_Wth + (size_t)mat * 65536;
    const __nv_bfloat16* Bl = g_Wtl + (size_t)mat * 65536;

    int wm = (wid & 3) * 32;
    int wn = (wid >> 2) * 64;

    float c[2][8][4];
#pragma unroll
    for (int mi=0;mi<2;mi++)
#pragma unroll
        for (int nf=0;nf<8;nf++)
#pragma unroll
            for (int r=0;r<4;r++) c[mi][nf][r] = 0.f;

    int lrow = tid >> 1, lch = tid & 1;
    int agr = bm + lrow; if (agr >= Nn) agr = Nn - 1;
    const __nv_bfloat16* srcAh = Abh + (size_t)agr*256 + lch*8;
    const __nv_bfloat16* srcAl = Abl + (size_t)agr*256 + lch*8;
    const __nv_bfloat16* srcBh = Bh + (size_t)(bn + lrow)*256 + lch*8;
    const __nv_bfloat16* srcBl = Bl + (size_t)(bn + lrow)*256 + lch*8;
    uint32_t dstOff = (uint32_t)lrow*80 + (uint32_t)lch*16;

    {
        uint32_t d = sbase + dstOff;
        CPA16(d,            srcAh);
        CPA16(d + 32,       srcAh + 16);
        CPA16(d + 10240,    srcAl);
        CPA16(d + 10272,    srcAl + 16);
        CPA16(d + 20480,    srcBh);
        CPA16(d + 20512,    srcBh + 16);
        CPA16(d + 30720,    srcBl);
        CPA16(d + 30752,    srcBl + 16);
        CP_COMMIT();
    }

    int rsel = lane & 15;
    int cofs = (lane & 16) ? 16 : 0;

    for (int kt = 0; kt < 8; kt++) {
        if (kt < 7) {
            int k0 = (kt + 1) * 32;
            uint32_t d = sbase + ((kt + 1) & 1) * HG_STAGE + dstOff;
            CPA16(d,            srcAh + k0);
            CPA16(d + 32,       srcAh + k0 + 16);
            CPA16(d + 10240,    srcAl + k0);
            CPA16(d + 10272,    srcAl + k0 + 16);
            CPA16(d + 20480,    srcBh + k0);
            CPA16(d + 20512,    srcBh + k0 + 16);
            CPA16(d + 30720,    srcBl + k0);
            CPA16(d + 30752,    srcBl + k0 + 16);
            CP_COMMIT();
            CP_WAIT1();
        } else {
            CP_WAIT0();
        }
        __syncthreads();
        uint32_t buf = sbase + (kt & 1) * HG_STAGE;

#pragma unroll
        for (int half = 0; half < 2; half++) {
            uint32_t hcol = (uint32_t)(half*32 + cofs);
            uint32_t a_h[2][4], a_l[2][4];
#pragma unroll
            for (int mi = 0; mi < 2; mi++) {
                uint32_t ro = buf + (uint32_t)(wm + mi*16 + rsel) * 80 + hcol;
                LDSM4(a_h[mi][0], a_h[mi][1], a_h[mi][2], a_h[mi][3], ro);
                LDSM4(a_l[mi][0], a_l[mi][1], a_l[mi][2], a_l[mi][3], ro + 10240);
            }
            uint32_t b_h[8][2], b_l[8][2];
#pragma unroll
            for (int np = 0; np < 4; np++) {
                uint32_t ro = buf + 20480 + (uint32_t)(wn + np*16 + rsel) * 80 + hcol;
                uint32_t r0, r1, r2, r3;
                LDSM4(r0, r1, r2, r3, ro);
                b_h[np*2][0]=r0; b_h[np*2+1][0]=r1; b_h[np*2][1]=r2; b_h[np*2+1][1]=r3;
                LDSM4(r0, r1, r2, r3, ro + 10240);
                b_l[np*2][0]=r0; b_l[np*2+1][0]=r1; b_l[np*2][1]=r2; b_l[np*2+1][1]=r3;
            }
#pragma unroll
            for (int mi = 0; mi < 2; mi++)
#pragma unroll
                for (int nf = 0; nf < 8; nf++)
                    MMA16816(c[mi][nf], a_h[mi], b_h[nf]);
#pragma unroll
            for (int mi = 0; mi < 2; mi++)
#pragma unroll
                for (int nf = 0; nf < 8; nf++)
                    MMA16816(c[mi][nf], a_h[mi], b_l[nf]);
#pragma unroll
            for (int mi = 0; mi < 2; mi++)
#pragma unroll
                for (int nf = 0; nf < 8; nf++)
                    MMA16816(c[mi][nf], a_l[mi], b_h[nf]);
        }
        __syncthreads();
    }

    float* C = (m ? g_v : g_t) + (size_t)e * NH;
#pragma unroll
    for (int mi = 0; mi < 2; mi++) {
        int row0 = bm + wm + mi*16 + (lane >> 2);
#pragma unroll
        for (int nf = 0; nf < 8; nf++) {
            int col = bn + wn + nf*8 + (lane & 3)*2;
            if (row0 < Nn)
                *(float2*)(C + (size_t)row0*256 + col) = make_float2(c[mi][nf][0], c[mi][nf][1]);
            if (row0 + 8 < Nn)
                *(float2*)(C + (size_t)(row0+8)*256 + col) = make_float2(c[mi][nf][2], c[mi][nf][3]);
        }
    }
}

// ---------------- router epilogue ----------------
__global__ void k_router_epi(const float* __restrict__ W1, const float* __restrict__ b1) {
    int idx = blockIdx.x*blockDim.x + threadIdx.x;
    if (idx >= NH) return;
    int i = idx >> 8, c = idx & 255;
    float v = g_rt[idx] + g_sf[i*2]*W1[256*256+c] + g_sf[i*2+1]*W1[257*256+c] + b1[c];
    g_r[idx] = fmaxf(v, 0.f);
}

// one thread per node; W2/b2 staged in smem (row read once)
__global__ void k_logits(const float* __restrict__ W2, const float* __restrict__ b2) {
    __shared__ float sW[2048];
    __shared__ float sb[8];
    int t = threadIdx.x;
    for (int j = t; j < 2048; j += 256) sW[j] = W2[j];
    if (t < 8) sb[t] = b2[t];
    __syncthreads();
    int i = blockIdx.x*256 + t;
    if (i >= Nn) return;
    const float4* r = (const float4*)(g_r + (size_t)i*256);
    float acc[8];
#pragma unroll
    for (int e=0;e<8;e++) acc[e] = sb[e];
    for (int k4 = 0; k4 < 64; k4++) {
        float4 v = r[k4];
        const float* w = &sW[k4*32];
#pragma unroll
        for (int e=0;e<8;e++)
            acc[e] += v.x*w[e] + v.y*w[8+e] + v.z*w[16+e] + v.w*w[24+e];
    }
#pragma unroll
    for (int e=0;e<8;e++) g_logits[i*8+e] = acc[e];
}

__global__ void k_topk() {
    int i = blockIdx.x*blockDim.x + threadIdx.x;
    if (i >= Nn) return;
    float l[8];
#pragma unroll
    for (int e=0;e<8;e++) l[e] = g_logits[i*8+e];
    int i1 = 0; float m1 = l[0];
#pragma unroll
    for (int e=1;e<8;e++) if (l[e] > m1) { m1 = l[e]; i1 = e; }
    int i2 = -1; float m2 = -1e30f;
#pragma unroll
    for (int e=0;e<8;e++) if (e != i1 && l[e] > m2) { m2 = l[e]; i2 = e; }
    float e2v = expf(m2 - m1);
    float inv = 1.f/(1.f + e2v);
    float s[8];
#pragma unroll
    for (int e=0;e<8;e++) s[e]=0.f;
    s[i1] = inv; s[i2] = e2v*inv;
#pragma unroll
    for (int e=0;e<8;e++) g_sparse[i*8+e] = s[e];
}

// ---------------- layer-0 SpMM: agg(h) once, shared across experts ----------------
__global__ void k_spmm0() {
    int dst = blockIdx.x*8 + (threadIdx.x >> 5);
    int lane = threadIdx.x & 31;
    if (dst >= Nn) return;
    const float* vb = g_h + lane*8;
    int s0 = g_rowstart[dst], s1 = g_rowstart[dst+1];
    float a0=0.f,a1=0.f,a2=0.f,a3=0.f,a4=0.f,a5=0.f,a6=0.f,a7=0.f;
    for (int p = s0; p < s1; p++) {
        int src = g_csr_src[p];
        const float4* row = (const float4*)(vb + (size_t)src*256);
        float4 x0 = row[0], x1 = row[1];
        a0 += x0.x; a1 += x0.y; a2 += x0.z; a3 += x0.w;
        a4 += x1.x; a5 += x1.y; a6 += x1.z; a7 += x1.w;
    }
    float vals[8] = {a0,a1,a2,a3,a4,a5,a6,a7};
    union { __nv_bfloat16 h[8]; uint4 u; } H, L;
#pragma unroll
    for (int j = 0; j < 8; j++) {
        __nv_bfloat16 hi = __float2bfloat16(vals[j]);
        H.h[j] = hi;
        L.h[j] = __float2bfloat16(vals[j] - __bfloat162float(hi));
    }
    size_t base = (size_t)dst*256 + lane*8;
    *(uint4*)(g_G0h + base) = H.u;
    *(uint4*)(g_G0l + base) = L.u;
}

// ---------------- layer-0 combine: he = relu(t + v + b), split hi/lo ----------------
__global__ void k_combine0(const float* __restrict__ bias) {
    size_t idx8 = (size_t)blockIdx.x*blockDim.x + threadIdx.x;
    if (idx8 >= (size_t)NEx*NH/8) return;
    size_t idx = idx8*8;
    int e = (int)(idx / NH);
    int c = (int)(idx & 255);
    const float4* tb = (const float4*)(g_t + idx);
    const float4* vb = (const float4*)(g_v + idx);
    const float4* bb = (const float4*)(bias + e*256 + c);
    float4 t0 = tb[0], t1 = tb[1], v0 = vb[0], v1 = vb[1], b0 = bb[0], b1 = bb[1];
    float vals[8];
    vals[0]=t0.x+v0.x+b0.x; vals[1]=t0.y+v0.y+b0.y; vals[2]=t0.z+v0.z+b0.z; vals[3]=t0.w+v0.w+b0.w;
    vals[4]=t1.x+v1.x+b1.x; vals[5]=t1.y+v1.y+b1.y; vals[6]=t1.z+v1.z+b1.z; vals[7]=t1.w+v1.w+b1.w;
    union { __nv_bfloat16 h[8]; uint4 u; } H, L;
#pragma unroll
    for (int j = 0; j < 8; j++) {
        float v = fmaxf(vals[j], 0.f);
        __nv_bfloat16 hi = __float2bfloat16(v);
        H.h[j] = hi;
        L.h[j] = __float2bfloat16(v - __bfloat162float(hi));
    }
    *(uint4*)(g_Ah + idx) = H.u;
    *(uint4*)(g_Al + idx) = L.u;
}

// ------- SpMM + combine, expert-major (grid: x = dst/8, y = expert) -------
// fuseOut=0: store bf16 hi/lo activations (layer 1).
// fuseOut=1: last hidden layer — fused output projection; writes g_mz only.
__global__ void k_spmm_combine(const float* __restrict__ bias,
                               const float* __restrict__ Wr,
                               const float* __restrict__ Wn,
                               int fuseOut) {
    int dst = blockIdx.x*8 + (threadIdx.x >> 5);
    int e = blockIdx.y;
    int lane = threadIdx.x & 31;
    if (dst >= Nn) return;
    const float* vb = g_v + (size_t)e*NH + lane*8;
    int s0 = g_rowstart[dst], s1 = g_rowstart[dst+1];
    float a0=0.f,a1=0.f,a2=0.f,a3=0.f,a4=0.f,a5=0.f,a6=0.f,a7=0.f;
    for (int p = s0; p < s1; p++) {
        int src = g_csr_src[p];
        const float4* row = (const float4*)(vb + (size_t)src*256);
        float4 x0 = row[0], x1 = row[1];
        a0 += x0.x; a1 += x0.y; a2 += x0.z; a3 += x0.w;
        a4 += x1.x; a5 += x1.y; a6 += x1.z; a7 += x1.w;
    }
    size_t base = (size_t)e*NH + (size_t)dst*256 + lane*8;
    const float4* tb = (const float4*)(g_t + base);
    float4 t0 = tb[0], t1 = tb[1];
    const float4* bb = (const float4*)(bias + e*256 + lane*8);
    float4 b0 = bb[0], b1 = bb[1];
    float vals[8];
    vals[0]=t0.x+a0+b0.x; vals[1]=t0.y+a1+b0.y; vals[2]=t0.z+a2+b0.z; vals[3]=t0.w+a3+b0.w;
    vals[4]=t1.x+a4+b1.x; vals[5]=t1.y+a5+b1.y; vals[6]=t1.z+a6+b1.z; vals[7]=t1.w+a7+b1.w;
    if (!fuseOut) {
        union { __nv_bfloat16 h[8]; uint4 u; } H, L;
#pragma unroll
        for (int j = 0; j < 8; j++) {
            float v = fmaxf(vals[j], 0.f);
            __nv_bfloat16 hi = __float2bfloat16(v);
            H.h[j] = hi;
            L.h[j] = __float2bfloat16(v - __bfloat162float(hi));
        }
        *(uint4*)(g_Ah + base) = H.u;
        *(uint4*)(g_Al + base) = L.u;
    } else {
        // fused output projection: warp holds full 256-ch row of expert e, node dst
        const float* WRe = Wr + e*512;
        const float* WNe = Wn + e*512;
        float m0=0.f, m1=0.f, z0=0.f, z1=0.f;
#pragma unroll
        for (int j = 0; j < 8; j++) {
            float v = fmaxf(vals[j], 0.f);
            int k = lane*8 + j;
            m0 += v*WRe[k*2];   m1 += v*WRe[k*2+1];
            z0 += v*WNe[k*2];   z1 += v*WNe[k*2+1];
        }
#pragma unroll
        for (int off = 16; off > 0; off >>= 1) {
            m0 += __shfl_xor_sync(0xFFFFFFFFu, m0, off);
            m1 += __shfl_xor_sync(0xFFFFFFFFu, m1, off);
            z0 += __shfl_xor_sync(0xFFFFFFFFu, z0, off);
            z1 += __shfl_xor_sync(0xFFFFFFFFu, z1, off);
        }
        if (lane == 0) {
            float* o = g_mz + ((size_t)e*Nn + dst)*4;
            o[0]=m0; o[1]=m1; o[2]=z0; o[3]=z1;
        }
    }
}

__global__ void k_aggz() {
    int idx = blockIdx.x*blockDim.x + threadIdx.x;
    if (idx >= NEx*Nn) return;
    int dst = idx % Nn;
    int e = idx / Nn;
    int s0 = g_rowstart[dst], s1 = g_rowstart[dst+1];
    float a0=0.f, a1=0.f;
    for (int p=s0; p<s1; p++) {
        int src = g_csr_src[p];
        const float* z = g_mz + ((size_t)e*Nn + src)*4 + 2;
        a0 += z[0]; a1 += z[1];
    }
    g_aggz[((size_t)e*Nn+dst)*2+0] = a0;
    g_aggz[((size_t)e*Nn+dst)*2+1] = a1;
}

__global__ void k_final(const float* __restrict__ outb, float* __restrict__ out) {
    int i = blockIdx.x*blockDim.x + threadIdx.x;
    if (i >= Nn) return;
    float o0=0.f, o1=0.f;
#pragma unroll
    for (int e=0;e<8;e++) {
        float s = g_sparse[i*8+e];
        const float* mz = g_mz + ((size_t)e*Nn+i)*4;
        const float* az = g_aggz + ((size_t)e*Nn+i)*2;
        o0 += s*(mz[0] + az[0] + outb[e*2+0]);
        o1 += s*(mz[1] + az[1] + outb[e*2+1]);
    }
    out[i*2+0] = o0;
    out[i*2+1] = o1;
}

// ---------------- launch ----------------
extern "C" void kernel_launch(void* const* d_in, const int* in_sizes, int n_in,
                              void* d_out, int out_size) {
    const float* x    = (const float*)d_in[0];
    const int*   ei   = (const int*)  d_in[1];
    const int*   batch= (const int*)  d_in[2];
    const float* encW = (const float*)d_in[3];
    const float* encb = (const float*)d_in[4];
    const float* rW1  = (const float*)d_in[5];
    const float* rb1  = (const float*)d_in[6];
    const float* rW2  = (const float*)d_in[7];
    const float* rb2  = (const float*)d_in[8];
    const float* hWr  = (const float*)d_in[9];
    const float* hWn  = (const float*)d_in[10];
    const float* hb   = (const float*)d_in[11];
    const float* oWr  = (const float*)d_in[12];
    const float* oWn  = (const float*)d_in[13];
    const float* ob   = (const float*)d_in[14];
    float* out = (float*)d_out;

    cudaFuncSetAttribute(k_hgemm, cudaFuncAttributeMaxDynamicSharedMemorySize, HG_SMEM);

    const int NTILES = (Nn + 127) / 128;   // 391
    dim3 gHalf(NTILES, 2, NEx);            // one m per launch
    dim3 gFull(NTILES, 2, NEx*2);          // both m
    dim3 gS2((Nn + 7)/8, NEx);             // expert-major SpMM

    k_zero<<<(Nn+255)/256,256>>>();
    k_encoder<<<(NH+255)/256,256>>>(x, encW, encb);
    k_convW<<<(NMATS*65536+255)/256,256>>>(rW1, hWr, hWn);
    k_hgemm<<<gHalf,256,HG_SMEM>>>(0, 0, 1);   // L0 t = h @ Wr_e  (profiled slot)
    k_count_nodes<<<256,256>>>(batch);
    k_count_edges<<<512,256>>>(ei, batch);
    k_indeg<<<(Ee+255)/256,256>>>(ei);
    k_sizefeat<<<(Nn+255)/256,256>>>(batch);
    k_scan1<<<(Nn+1023)/1024,1024>>>();
    k_scan2<<<1,64>>>();
    k_scan3<<<(Nn+255)/256,256>>>();
    k_cursor<<<(Nn+255)/256,256>>>();
    k_scatter<<<(Ee+255)/256,256>>>(ei);

    // router (exact fp32 in its own buffer g_rt)
    {
        dim3 gR((Nn+127)/128, 2, 1);
        k_sgemm_router<<<gR,256>>>(rW1);
        k_router_epi<<<(NH+255)/256,256>>>(rW1, rb1);
        k_logits<<<(Nn+255)/256,256>>>(rW2, rb2);
        k_topk<<<(Nn+255)/256,256>>>();
    }

    // layer 0: shared aggregate of h, then v = agg(h) @ Wn_e
    k_spmm0<<<(Nn+7)/8,256>>>();
    k_hgemm<<<gHalf,256,HG_SMEM>>>(2, 1, 1);   // L0 v
    k_combine0<<<(NEx*NH/8+255)/256,256>>>(hb);

    // layer 1: GEMMs + SpMM/combine (store activations)
    k_hgemm<<<gFull,256,HG_SMEM>>>(1, -1, 1 + 1*(NEx*2));
    k_spmm_combine<<<gS2,256>>>(hb + (size_t)1*NEx*Hh, oWr, oWn, 0);

    // layer 2: GEMMs + SpMM/combine with fused output projection
    k_hgemm<<<gFull,256,HG_SMEM>>>(1, -1, 1 + 2*(NEx*2));
    k_spmm_combine<<<gS2,256>>>(hb + (size_t)2*NEx*Hh, oWr, oWn, 1);

    // output layer
    k_aggz<<<(NEx*Nn+255)/256,256>>>();
    k_final<<<(Nn+255)/256,256>>>(ob, out);
}

// round 12
// speedup vs baseline: 1.2793x; 1.0035x over previous
#include <cuda_runtime.h>
#include <cuda_bf16.h>
#include <cstdint>
#include <math.h>

#define Nn 50000
#define Ee 800000
#define Gg 64
#define Ff 6
#define Hh 256
#define Oo 2
#define NEx 8
#define NH (Nn*Hh)
#define NMATS 49   // 1 router + 3 layers * 8 experts * 2

// ---------------- scratch (static __device__ arrays; no allocation) ----------------
__device__ __align__(128) float g_h[NH];                  // encoder output (fp32)
__device__ __align__(128) __nv_bfloat16 g_A0h[NH];        // encoder bf16 hi
__device__ __align__(128) __nv_bfloat16 g_A0l[NH];        // encoder bf16 lo
__device__ __align__(128) __nv_bfloat16 g_G0h[NH];        // agg(h) bf16 hi (layer-0, shared)
__device__ __align__(128) __nv_bfloat16 g_G0l[NH];        // agg(h) bf16 lo
__device__ __align__(128) float g_r[NH];                  // router hidden
__device__ __align__(128) float g_rt[NH];                 // router GEMM scratch
__device__ __align__(128) float g_t[NEx*NH];              // he @ Wr
__device__ __align__(128) float g_v[NEx*NH];              // he @ Wn
__device__ __align__(128) __nv_bfloat16 g_Ah[NEx*NH];     // per-expert activation bf16 hi
__device__ __align__(128) __nv_bfloat16 g_Al[NEx*NH];     // per-expert activation bf16 lo
__device__ __align__(128) __nv_bfloat16 g_Wth[NMATS*65536]; // weights bf16 hi [mat][n][k]
__device__ __align__(128) __nv_bfloat16 g_Wtl[NMATS*65536]; // weights bf16 lo
__device__ __align__(128) float g_sf[Nn*2];
__device__ __align__(128) float g_logits[Nn*NEx];
__device__ __align__(128) float g_sparse[Nn*NEx];
__device__ __align__(128) float g_mz[NEx*Nn*4];           // [m0,m1,z0,z1] per (e,node)
__device__ __align__(128) float g_aggz[NEx*Nn*2];
__device__ int g_nodecnt[Gg];
__device__ int g_edgecnt[Gg];
__device__ int g_indeg[Nn];
__device__ int g_scantmp[Nn];
__device__ int g_bsum[64];
__device__ int g_bsumscan[64];
__device__ int g_rowstart[Nn+1];
__device__ int g_cursor[Nn];
__device__ int g_csr_src[Ee];

// ======================= warp MMA helpers (plain-target: sm_80+) =======================
__device__ __forceinline__ uint32_t smem_to_u32(const void* smem_ptr) {
    uint32_t addr;
    asm("{ .reg .u64 tmp; cvta.to.shared.u64 tmp, %1; cvt.u32.u64 %0, tmp; }"
        : "=r"(addr) : "l"(smem_ptr));
    return addr;
}
#define LDSM4(r0,r1,r2,r3,addr) \
    asm volatile("ldmatrix.sync.aligned.m8n8.x4.shared.b16 {%0,%1,%2,%3}, [%4];" \
        : "=r"(r0), "=r"(r1), "=r"(r2), "=r"(r3) : "r"(addr))
#define MMA16816(c, a, b) \
    asm volatile("mma.sync.aligned.m16n8k16.row.col.f32.bf16.bf16.f32 " \
        "{%0,%1,%2,%3}, {%4,%5,%6,%7}, {%8,%9}, {%0,%1,%2,%3};" \
        : "+f"((c)[0]), "+f"((c)[1]), "+f"((c)[2]), "+f"((c)[3]) \
        : "r"((a)[0]), "r"((a)[1]), "r"((a)[2]), "r"((a)[3]), \
          "r"((b)[0]), "r"((b)[1]))
#define CPA16(dst, src) \
    asm volatile("cp.async.cg.shared.global [%0], [%1], 16;" :: "r"(dst), "l"(src))
#define CP_COMMIT() asm volatile("cp.async.commit_group;")
#define CP_WAIT1()  asm volatile("cp.async.wait_group 1;")
#define CP_WAIT0()  asm volatile("cp.async.wait_group 0;")

__device__ __forceinline__ uint32_t pack_bf16x2(float lo, float hi) {
    __nv_bfloat16 a = __float2bfloat16(lo);
    __nv_bfloat16 b = __float2bfloat16(hi);
    uint32_t r = ((uint32_t)*(uint16_t*)&b << 16) | (uint32_t)*(uint16_t*)&a;
    return r;
}

// ---------------- small kernels ----------------
__global__ void k_zero() {
    int i = blockIdx.x*blockDim.x + threadIdx.x;
    if (i < Gg) { g_nodecnt[i]=0; g_edgecnt[i]=0; }
    if (i < Nn) g_indeg[i]=0;
}

__global__ void k_encoder(const float* __restrict__ x, const float* __restrict__ W,
                          const float* __restrict__ b) {
    int idx = blockIdx.x*blockDim.x + threadIdx.x;
    if (idx >= NH) return;
    int i = idx >> 8, c = idx & 255;
    float acc = b[c];
#pragma unroll
    for (int k=0;k<Ff;k++) acc += x[i*Ff+k]*W[k*Hh+c];
    float v = fmaxf(acc, 0.f);
    g_h[idx] = v;
    __nv_bfloat16 hi = __float2bfloat16(v);
    g_A0h[idx] = hi;
    g_A0l[idx] = __float2bfloat16(v - __bfloat162float(hi));
}

// convert + transpose all weights to bf16 hi/lo, layout [mat][n][k]
__global__ void k_convW(const float* __restrict__ rW1, const float* __restrict__ hWr,
                        const float* __restrict__ hWn) {
    size_t idx = (size_t)blockIdx.x*blockDim.x + threadIdx.x;
    if (idx >= (size_t)NMATS*65536) return;
    int mat = (int)(idx >> 16);
    int r = (int)(idx & 65535);
    int n = r >> 8, k = r & 255;
    float w;
    if (mat == 0) {
        w = rW1[k*256 + n];
    } else {
        int hm = mat - 1;
        int l = hm >> 4, rr = hm & 15;
        int e = rr >> 1, m = rr & 1;
        const float* W = m ? hWn : hWr;
        w = W[((size_t)(l*NEx + e))*65536 + k*256 + n];
    }
    __nv_bfloat16 hi = __float2bfloat16(w);
    g_Wth[idx] = hi;
    g_Wtl[idx] = __float2bfloat16(w - __bfloat162float(hi));
}

__global__ void k_count_nodes(const int* __restrict__ batch) {
    __shared__ int hist[Gg];
    int t = threadIdx.x;
    if (t < Gg) hist[t]=0;
    __syncthreads();
    for (int i = blockIdx.x*blockDim.x + t; i < Nn; i += gridDim.x*blockDim.x)
        atomicAdd(&hist[batch[i]], 1);
    __syncthreads();
    if (t < Gg) atomicAdd(&g_nodecnt[t], hist[t]);
}

__global__ void k_count_edges(const int* __restrict__ ei, const int* __restrict__ batch) {
    __shared__ int hist[Gg];
    int t = threadIdx.x;
    if (t < Gg) hist[t]=0;
    __syncthreads();
    for (int e = blockIdx.x*blockDim.x + t; e < Ee; e += gridDim.x*blockDim.x)
        atomicAdd(&hist[batch[ei[e]]], 1);
    __syncthreads();
    if (t < Gg) atomicAdd(&g_edgecnt[t], hist[t]);
}

__global__ void k_indeg(const int* __restrict__ ei) {
    int e = blockIdx.x*blockDim.x + threadIdx.x;
    if (e < Ee) atomicAdd(&g_indeg[ei[Ee+e]], 1);
}

__global__ void k_sizefeat(const int* __restrict__ batch) {
    int i = blockIdx.x*blockDim.x + threadIdx.x;
    if (i >= Nn) return;
    int g = batch[i];
    g_sf[i*2+0] = logf((float)g_nodecnt[g] + 1.f);
    g_sf[i*2+1] = logf((float)g_edgecnt[g] + 1.f);
}

__global__ void k_scan1() {
    __shared__ int sh[1024];
    int t = threadIdx.x, gid = blockIdx.x*1024 + t;
    sh[t] = (gid < Nn) ? g_indeg[gid] : 0;
    __syncthreads();
    for (int off=1; off<1024; off<<=1) {
        int a = (t>=off) ? sh[t-off] : 0;
        __syncthreads();
        sh[t] += a;
        __syncthreads();
    }
    if (gid < Nn) g_scantmp[gid] = sh[t];
    if (t == 1023) g_bsum[blockIdx.x] = sh[1023];
}

__global__ void k_scan2() {
    __shared__ int sh[64];
    int t = threadIdx.x;
    const int NB1 = (Nn + 1023)/1024;
    sh[t] = (t < NB1) ? g_bsum[t] : 0;
    __syncthreads();
    for (int off=1; off<64; off<<=1) {
        int a = (t>=off) ? sh[t-off] : 0;
        __syncthreads();
        sh[t] += a;
        __syncthreads();
    }
    g_bsumscan[t] = sh[t];
}

__global__ void k_scan3() {
    int i = blockIdx.x*blockDim.x + threadIdx.x;
    if (i >= Nn) return;
    int blk = i >> 10;
    int incl = g_scantmp[i] + (blk ? g_bsumscan[blk-1] : 0);
    g_rowstart[i+1] = incl;
    if (i == 0) g_rowstart[0] = 0;
}

__global__ void k_cursor() {
    int i = blockIdx.x*blockDim.x + threadIdx.x;
    if (i < Nn) g_cursor[i] = g_rowstart[i];
}

__global__ void k_scatter(const int* __restrict__ ei) {
    int e = blockIdx.x*blockDim.x + threadIdx.x;
    if (e >= Ee) return;
    int d = ei[Ee+e];
    int p = atomicAdd(&g_cursor[d], 1);
    g_csr_src[p] = ei[e];
}

// ---------------- router SGEMM (exact fp32, tile 128x128) -> g_rt ----------------
__global__ void __launch_bounds__(256) k_sgemm_router(const float* __restrict__ B) {
    const float* A = g_h;
    float* Cb = g_rt;

    __shared__ float As[16][128];
    __shared__ float Bs[16][128];

    int tid = threadIdx.x;
    int bm = blockIdx.x*128, bn = blockIdx.y*128;
    int tx = tid & 15, ty = tid >> 4;
    int a_row = tid >> 2;
    int a_col = (tid & 3) * 4;
    int b_row = tid >> 5;
    int b_col = (tid & 31) * 4;

    float acc[8][8];
#pragma unroll
    for (int i=0;i<8;i++)
#pragma unroll
        for (int j=0;j<8;j++) acc[i][j]=0.f;

    for (int kt=0; kt<256; kt+=16) {
        __syncthreads();
#pragma unroll
        for (int i=0;i<2;i++) {
            int r = a_row + i*64;
            int gm = bm + r;
            float4 av = make_float4(0.f,0.f,0.f,0.f);
            if (gm < Nn) av = *(const float4*)(A + (size_t)gm*256 + kt + a_col);
            As[a_col+0][r]=av.x; As[a_col+1][r]=av.y;
            As[a_col+2][r]=av.z; As[a_col+3][r]=av.w;
        }
#pragma unroll
        for (int i=0;i<2;i++) {
            int r = b_row + i*8;
            *(float4*)&Bs[r][b_col] = *(const float4*)(B + (size_t)(kt+r)*256 + bn + b_col);
        }
        __syncthreads();
#pragma unroll
        for (int kk=0;kk<16;kk++) {
            float4 a0 = *(const float4*)&As[kk][ty*4];
            float4 a1 = *(const float4*)&As[kk][64+ty*4];
            float4 b0 = *(const float4*)&Bs[kk][tx*4];
            float4 b1 = *(const float4*)&Bs[kk][64+tx*4];
            float a[8] = {a0.x,a0.y,a0.z,a0.w,a1.x,a1.y,a1.z,a1.w};
            float b[8] = {b0.x,b0.y,b0.z,b0.w,b1.x,b1.y,b1.z,b1.w};
#pragma unroll
            for (int i=0;i<8;i++)
#pragma unroll
                for (int j=0;j<8;j++) acc[i][j] += a[i]*b[j];
        }
    }
#pragma unroll
    for (int ih=0; ih<2; ih++) {
#pragma unroll
        for (int i=0;i<4;i++) {
            int gm = bm + ih*64 + ty*4 + i;
            if (gm >= Nn) continue;
            float* crow = Cb + (size_t)gm*256 + bn;
            int r = ih*4 + i;
            *(float4*)(crow + tx*4)      = make_float4(acc[r][0],acc[r][1],acc[r][2],acc[r][3]);
            *(float4*)(crow + 64 + tx*4) = make_float4(acc[r][4],acc[r][5],acc[r][6],acc[r][7]);
        }
    }
}

// ============== HMMA bf16x3 GEMM, BK=32, 2-stage cp.async, B-frag pipelined =========
// asel: 0 -> A = g_A0, 1 -> A = g_A(e), 2 -> A = g_G0
// mSel: -1 -> z covers e*2+m ; 0/1 -> z covers e, m fixed
// epi:  0 -> plain fp32 store; 1 -> combine: relu(c + g_t[e] + bias) -> g_Ah/g_Al
// Stage (40960B): Ah@0, Al@10240, Bh@20480, Bl@30720 — rows pitch 80B. 2 stages dyn.
#define HG_STAGE 40960
#define HG_SMEM  (2*HG_STAGE)

__global__ void __launch_bounds__(256, 2) k_hgemm(int asel, int mSel, int matBase,
                                                  int epi, const float* __restrict__ bias)
{
    extern __shared__ __align__(16) char hg_smem[];
    uint32_t sbase = smem_to_u32(hg_smem);
    int tid = threadIdx.x, lane = tid & 31, wid = tid >> 5;
    int bm = blockIdx.x * 128, bn = blockIdx.y * 128;
    int z = blockIdx.z;
    int e, m;
    if (mSel < 0) { e = z >> 1; m = z & 1; } else { e = z; m = mSel; }
    int mat = matBase + e*2 + m;

    const __nv_bfloat16 *Abh, *Abl;
    if (asel == 0)      { Abh = g_A0h; Abl = g_A0l; }
    else if (asel == 1) { Abh = g_Ah + (size_t)e*NH; Abl = g_Al + (size_t)e*NH; }
    else                { Abh = g_G0h; Abl = g_G0l; }
    const __nv_bfloat16* Bh = g_Wth + (size_t)mat * 65536;
    const __nv_bfloat16* Bl = g_Wtl + (size_t)mat * 65536;

    int wm = (wid & 3) * 32;
    int wn = (wid >> 2) * 64;

    float c[2][8][4];
#pragma unroll
    for (int mi=0;mi<2;mi++)
#pragma unroll
        for (int nf=0;nf<8;nf++)
#pragma unroll
            for (int r=0;r<4;r++) c[mi][nf][r] = 0.f;

    int lrow = tid >> 1, lch = tid & 1;
    int agr = bm + lrow; if (agr >= Nn) agr = Nn - 1;
    const __nv_bfloat16* srcAh = Abh + (size_t)agr*256 + lch*8;
    const __nv_bfloat16* srcAl = Abl + (size_t)agr*256 + lch*8;
    const __nv_bfloat16* srcBh = Bh + (size_t)(bn + lrow)*256 + lch*8;
    const __nv_bfloat16* srcBl = Bl + (size_t)(bn + lrow)*256 + lch*8;
    uint32_t dstOff = (uint32_t)lrow*80 + (uint32_t)lch*16;

    {
        uint32_t d = sbase + dstOff;
        CPA16(d,            srcAh);
        CPA16(d + 32,       srcAh + 16);
        CPA16(d + 10240,    srcAl);
        CPA16(d + 10272,    srcAl + 16);
        CPA16(d + 20480,    srcBh);
        CPA16(d + 20512,    srcBh + 16);
        CPA16(d + 30720,    srcBl);
        CPA16(d + 30752,    srcBl + 16);
        CP_COMMIT();
    }

    int rsel = lane & 15;
    int cofs = (lane & 16) ? 16 : 0;

    for (int kt = 0; kt < 8; kt++) {
        if (kt < 7) {
            int k0 = (kt + 1) * 32;
            uint32_t d = sbase + ((kt + 1) & 1) * HG_STAGE + dstOff;
            CPA16(d,            srcAh + k0);
            CPA16(d + 32,       srcAh + k0 + 16);
            CPA16(d + 10240,    srcAl + k0);
            CPA16(d + 10272,    srcAl + k0 + 16);
            CPA16(d + 20480,    srcBh + k0);
            CPA16(d + 20512,    srcBh + k0 + 16);
            CPA16(d + 30720,    srcBl + k0);
            CPA16(d + 30752,    srcBl + k0 + 16);
            CP_COMMIT();
            CP_WAIT1();
        } else {
            CP_WAIT0();
        }
        __syncthreads();
        uint32_t buf = sbase + (kt & 1) * HG_STAGE;

#pragma unroll
        for (int half = 0; half < 2; half++) {
            uint32_t hcol = (uint32_t)(half*32 + cofs);
            uint32_t a_h[2][4], a_l[2][4];
#pragma unroll
            for (int mi = 0; mi < 2; mi++) {
                uint32_t ro = buf + (uint32_t)(wm + mi*16 + rsel) * 80 + hcol;
                LDSM4(a_h[mi][0], a_h[mi][1], a_h[mi][2], a_h[mi][3], ro);
                LDSM4(a_l[mi][0], a_l[mi][1], a_l[mi][2], a_l[mi][3], ro + 10240);
            }
            // B fragments double-buffered through the np loop: current np's MMAs
            // overlap np+1's LDSM (fine-grained tensor/smem overlap).
            uint32_t bh[2][2][2], bl[2][2][2];
            uint32_t bbase = buf + 20480 + (uint32_t)(wn + rsel) * 80 + hcol;
            {
                uint32_t r0,r1,r2,r3;
                LDSM4(r0,r1,r2,r3, bbase);
                bh[0][0][0]=r0; bh[0][1][0]=r1; bh[0][0][1]=r2; bh[0][1][1]=r3;
                LDSM4(r0,r1,r2,r3, bbase + 10240);
                bl[0][0][0]=r0; bl[0][1][0]=r1; bl[0][0][1]=r2; bl[0][1][1]=r3;
            }
#pragma unroll
            for (int np = 0; np < 4; np++) {
                int cb = np & 1, nb = 1 - cb;
                if (np < 3) {
                    uint32_t ro = bbase + (uint32_t)(np+1)*(16*80);
                    uint32_t r0,r1,r2,r3;
                    LDSM4(r0,r1,r2,r3, ro);
                    bh[nb][0][0]=r0; bh[nb][1][0]=r1; bh[nb][0][1]=r2; bh[nb][1][1]=r3;
                    LDSM4(r0,r1,r2,r3, ro + 10240);
                    bl[nb][0][0]=r0; bl[nb][1][0]=r1; bl[nb][0][1]=r2; bl[nb][1][1]=r3;
                }
#pragma unroll
                for (int j = 0; j < 2; j++)
#pragma unroll
                    for (int mi = 0; mi < 2; mi++)
                        MMA16816(c[mi][np*2+j], a_h[mi], bh[cb][j]);
#pragma unroll
                for (int j = 0; j < 2; j++)
#pragma unroll
                    for (int mi = 0; mi < 2; mi++)
                        MMA16816(c[mi][np*2+j], a_h[mi], bl[cb][j]);
#pragma unroll
                for (int j = 0; j < 2; j++)
#pragma unroll
                    for (int mi = 0; mi < 2; mi++)
                        MMA16816(c[mi][np*2+j], a_l[mi], bh[cb][j]);
            }
        }
        __syncthreads();
    }

    if (epi == 0) {
        float* C = (m ? g_v : g_t) + (size_t)e * NH;
#pragma unroll
        for (int mi = 0; mi < 2; mi++) {
            int row0 = bm + wm + mi*16 + (lane >> 2);
#pragma unroll
            for (int nf = 0; nf < 8; nf++) {
                int col = bn + wn + nf*8 + (lane & 3)*2;
                if (row0 < Nn)
                    *(float2*)(C + (size_t)row0*256 + col) = make_float2(c[mi][nf][0], c[mi][nf][1]);
                if (row0 + 8 < Nn)
                    *(float2*)(C + (size_t)(row0+8)*256 + col) = make_float2(c[mi][nf][2], c[mi][nf][3]);
            }
        }
    } else {
        // fused combine: he = relu(c + t + bias) -> bf16 hi/lo split
        const float* T = g_t + (size_t)e * NH;
        __nv_bfloat16* AH = g_Ah + (size_t)e * NH;
        __nv_bfloat16* AL = g_Al + (size_t)e * NH;
#pragma unroll
        for (int mi = 0; mi < 2; mi++) {
            int row0 = bm + wm + mi*16 + (lane >> 2);
#pragma unroll
            for (int nf = 0; nf < 8; nf++) {
                int col = bn + wn + nf*8 + (lane & 3)*2;
                float bc0 = bias[e*256 + col], bc1 = bias[e*256 + col + 1];
#pragma unroll
                for (int rr = 0; rr < 2; rr++) {
                    int row = row0 + rr*8;
                    if (row >= Nn) continue;
                    float2 t2 = *(const float2*)(T + (size_t)row*256 + col);
                    float v0 = fmaxf(c[mi][nf][rr*2+0] + t2.x + bc0, 0.f);
                    float v1 = fmaxf(c[mi][nf][rr*2+1] + t2.y + bc1, 0.f);
                    __nv_bfloat16 h0 = __float2bfloat16(v0);
                    __nv_bfloat16 h1 = __float2bfloat16(v1);
                    float l0 = v0 - __bfloat162float(h0);
                    float l1 = v1 - __bfloat162float(h1);
                    uint32_t hp = ((uint32_t)*(uint16_t*)&h1 << 16) | (uint32_t)*(uint16_t*)&h0;
                    *(uint32_t*)(AH + (size_t)row*256 + col) = hp;
                    *(uint32_t*)(AL + (size_t)row*256 + col) = pack_bf16x2(l0, l1);
                }
            }
        }
    }
}

// ---------------- router epilogue ----------------
__global__ void k_router_epi(const float* __restrict__ W1, const float* __restrict__ b1) {
    int idx = blockIdx.x*blockDim.x + threadIdx.x;
    if (idx >= NH) return;
    int i = idx >> 8, c = idx & 255;
    float v = g_rt[idx] + g_sf[i*2]*W1[256*256+c] + g_sf[i*2+1]*W1[257*256+c] + b1[c];
    g_r[idx] = fmaxf(v, 0.f);
}

// one thread per node; W2/b2 staged in smem (row read once)
__global__ void k_logits(const float* __restrict__ W2, const float* __restrict__ b2) {
    __shared__ float sW[2048];
    __shared__ float sb[8];
    int t = threadIdx.x;
    for (int j = t; j < 2048; j += 256) sW[j] = W2[j];
    if (t < 8) sb[t] = b2[t];
    __syncthreads();
    int i = blockIdx.x*256 + t;
    if (i >= Nn) return;
    const float4* r = (const float4*)(g_r + (size_t)i*256);
    float acc[8];
#pragma unroll
    for (int e=0;e<8;e++) acc[e] = sb[e];
    for (int k4 = 0; k4 < 64; k4++) {
        float4 v = r[k4];
        const float* w = &sW[k4*32];
#pragma unroll
        for (int e=0;e<8;e++)
            acc[e] += v.x*w[e] + v.y*w[8+e] + v.z*w[16+e] + v.w*w[24+e];
    }
#pragma unroll
    for (int e=0;e<8;e++) g_logits[i*8+e] = acc[e];
}

__global__ void k_topk() {
    int i = blockIdx.x*blockDim.x + threadIdx.x;
    if (i >= Nn) return;
    float l[8];
#pragma unroll
    for (int e=0;e<8;e++) l[e] = g_logits[i*8+e];
    int i1 = 0; float m1 = l[0];
#pragma unroll
    for (int e=1;e<8;e++) if (l[e] > m1) { m1 = l[e]; i1 = e; }
    int i2 = -1; float m2 = -1e30f;
#pragma unroll
    for (int e=0;e<8;e++) if (e != i1 && l[e] > m2) { m2 = l[e]; i2 = e; }
    float e2v = expf(m2 - m1);
    float inv = 1.f/(1.f + e2v);
    float s[8];
#pragma unroll
    for (int e=0;e<8;e++) s[e]=0.f;
    s[i1] = inv; s[i2] = e2v*inv;
#pragma unroll
    for (int e=0;e<8;e++) g_sparse[i*8+e] = s[e];
}

// ---------------- layer-0 SpMM: agg(h) once, shared across experts ----------------
__global__ void k_spmm0() {
    int dst = blockIdx.x*8 + (threadIdx.x >> 5);
    int lane = threadIdx.x & 31;
    if (dst >= Nn) return;
    const float* vb = g_h + lane*8;
    int s0 = g_rowstart[dst], s1 = g_rowstart[dst+1];
    float a0=0.f,a1=0.f,a2=0.f,a3=0.f,a4=0.f,a5=0.f,a6=0.f,a7=0.f;
    for (int p = s0; p < s1; p++) {
        int src = g_csr_src[p];
        const float4* row = (const float4*)(vb + (size_t)src*256);
        float4 x0 = row[0], x1 = row[1];
        a0 += x0.x; a1 += x0.y; a2 += x0.z; a3 += x0.w;
        a4 += x1.x; a5 += x1.y; a6 += x1.z; a7 += x1.w;
    }
    float vals[8] = {a0,a1,a2,a3,a4,a5,a6,a7};
    union { __nv_bfloat16 h[8]; uint4 u; } H, L;
#pragma unroll
    for (int j = 0; j < 8; j++) {
        __nv_bfloat16 hi = __float2bfloat16(vals[j]);
        H.h[j] = hi;
        L.h[j] = __float2bfloat16(vals[j] - __bfloat162float(hi));
    }
    size_t base = (size_t)dst*256 + lane*8;
    *(uint4*)(g_G0h + base) = H.u;
    *(uint4*)(g_G0l + base) = L.u;
}

// ------- SpMM + combine, expert-major (grid: x = dst/8, y = expert) -------
// fuseOut=0: store bf16 hi/lo activations (layer 1).
// fuseOut=1: last hidden layer — fused output projection; writes g_mz only.
__global__ void k_spmm_combine(const float* __restrict__ bias,
                               const float* __restrict__ Wr,
                               const float* __restrict__ Wn,
                               int fuseOut) {
    int dst = blockIdx.x*8 + (threadIdx.x >> 5);
    int e = blockIdx.y;
    int lane = threadIdx.x & 31;
    if (dst >= Nn) return;
    const float* vb = g_v + (size_t)e*NH + lane*8;
    int s0 = g_rowstart[dst], s1 = g_rowstart[dst+1];
    float a0=0.f,a1=0.f,a2=0.f,a3=0.f,a4=0.f,a5=0.f,a6=0.f,a7=0.f;
    for (int p = s0; p < s1; p++) {
        int src = g_csr_src[p];
        const float4* row = (const float4*)(vb + (size_t)src*256);
        float4 x0 = row[0], x1 = row[1];
        a0 += x0.x; a1 += x0.y; a2 += x0.z; a3 += x0.w;
        a4 += x1.x; a5 += x1.y; a6 += x1.z; a7 += x1.w;
    }
    size_t base = (size_t)e*NH + (size_t)dst*256 + lane*8;
    const float4* tb = (const float4*)(g_t + base);
    float4 t0 = tb[0], t1 = tb[1];
    const float4* bb = (const float4*)(bias + e*256 + lane*8);
    float4 b0 = bb[0], b1 = bb[1];
    float vals[8];
    vals[0]=t0.x+a0+b0.x; vals[1]=t0.y+a1+b0.y; vals[2]=t0.z+a2+b0.z; vals[3]=t0.w+a3+b0.w;
    vals[4]=t1.x+a4+b1.x; vals[5]=t1.y+a5+b1.y; vals[6]=t1.z+a6+b1.z; vals[7]=t1.w+a7+b1.w;
    if (!fuseOut) {
        union { __nv_bfloat16 h[8]; uint4 u; } H, L;
#pragma unroll
        for (int j = 0; j < 8; j++) {
            float v = fmaxf(vals[j], 0.f);
            __nv_bfloat16 hi = __float2bfloat16(v);
            H.h[j] = hi;
            L.h[j] = __float2bfloat16(v - __bfloat162float(hi));
        }
        *(uint4*)(g_Ah + base) = H.u;
        *(uint4*)(g_Al + base) = L.u;
    } else {
        const float* WRe = Wr + e*512;
        const float* WNe = Wn + e*512;
        float m0=0.f, m1=0.f, z0=0.f, z1=0.f;
#pragma unroll
        for (int j = 0; j < 8; j++) {
            float v = fmaxf(vals[j], 0.f);
            int k = lane*8 + j;
            m0 += v*WRe[k*2];   m1 += v*WRe[k*2+1];
            z0 += v*WNe[k*2];   z1 += v*WNe[k*2+1];
        }
#pragma unroll
        for (int off = 16; off > 0; off >>= 1) {
            m0 += __shfl_xor_sync(0xFFFFFFFFu, m0, off);
            m1 += __shfl_xor_sync(0xFFFFFFFFu, m1, off);
            z0 += __shfl_xor_sync(0xFFFFFFFFu, z0, off);
            z1 += __shfl_xor_sync(0xFFFFFFFFu, z1, off);
        }
        if (lane == 0) {
            float* o = g_mz + ((size_t)e*Nn + dst)*4;
            o[0]=m0; o[1]=m1; o[2]=z0; o[3]=z1;
        }
    }
}

__global__ void k_aggz() {
    int idx = blockIdx.x*blockDim.x + threadIdx.x;
    if (idx >= NEx*Nn) return;
    int dst = idx % Nn;
    int e = idx / Nn;
    int s0 = g_rowstart[dst], s1 = g_rowstart[dst+1];
    float a0=0.f, a1=0.f;
    for (int p=s0; p<s1; p++) {
        int src = g_csr_src[p];
        const float* z = g_mz + ((size_t)e*Nn + src)*4 + 2;
        a0 += z[0]; a1 += z[1];
    }
    g_aggz[((size_t)e*Nn+dst)*2+0] = a0;
    g_aggz[((size_t)e*Nn+dst)*2+1] = a1;
}

__global__ void k_final(const float* __restrict__ outb, float* __restrict__ out) {
    int i = blockIdx.x*blockDim.x + threadIdx.x;
    if (i >= Nn) return;
    float o0=0.f, o1=0.f;
#pragma unroll
    for (int e=0;e<8;e++) {
        float s = g_sparse[i*8+e];
        const float* mz = g_mz + ((size_t)e*Nn+i)*4;
        const float* az = g_aggz + ((size_t)e*Nn+i)*2;
        o0 += s*(mz[0] + az[0] + outb[e*2+0]);
        o1 += s*(mz[1] + az[1] + outb[e*2+1]);
    }
    out[i*2+0] = o0;
    out[i*2+1] = o1;
}

// ---------------- launch ----------------
extern "C" void kernel_launch(void* const* d_in, const int* in_sizes, int n_in,
                              void* d_out, int out_size) {
    const float* x    = (const float*)d_in[0];
    const int*   ei   = (const int*)  d_in[1];
    const int*   batch= (const int*)  d_in[2];
    const float* encW = (const float*)d_in[3];
    const float* encb = (const float*)d_in[4];
    const float* rW1  = (const float*)d_in[5];
    const float* rb1  = (const float*)d_in[6];
    const float* rW2  = (const float*)d_in[7];
    const float* rb2  = (const float*)d_in[8];
    const float* hWr  = (const float*)d_in[9];
    const float* hWn  = (const float*)d_in[10];
    const float* hb   = (const float*)d_in[11];
    const float* oWr  = (const float*)d_in[12];
    const float* oWn  = (const float*)d_in[13];
    const float* ob   = (const float*)d_in[14];
    float* out = (float*)d_out;

    cudaFuncSetAttribute(k_hgemm, cudaFuncAttributeMaxDynamicSharedMemorySize, HG_SMEM);

    const int NTILES = (Nn + 127) / 128;   // 391
    dim3 gHalf(NTILES, 2, NEx);            // one m per launch
    dim3 gFull(NTILES, 2, NEx*2);          // both m
    dim3 gS2((Nn + 7)/8, NEx);             // expert-major SpMM

    k_zero<<<(Nn+255)/256,256>>>();
    k_encoder<<<(NH+255)/256,256>>>(x, encW, encb);
    k_convW<<<(NMATS*65536+255)/256,256>>>(rW1, hWr, hWn);
    k_hgemm<<<gHalf,256,HG_SMEM>>>(0, 0, 1, 0, nullptr);   // L0 t (profiled slot)
    k_count_nodes<<<256,256>>>(batch);
    k_count_edges<<<512,256>>>(ei, batch);
    k_indeg<<<(Ee+255)/256,256>>>(ei);
    k_sizefeat<<<(Nn+255)/256,256>>>(batch);
    k_scan1<<<(Nn+1023)/1024,1024>>>();
    k_scan2<<<1,64>>>();
    k_scan3<<<(Nn+255)/256,256>>>();
    k_cursor<<<(Nn+255)/256,256>>>();
    k_scatter<<<(Ee+255)/256,256>>>(ei);

    // router (exact fp32 in its own buffer g_rt)
    {
        dim3 gR((Nn+127)/128, 2, 1);
        k_sgemm_router<<<gR,256>>>(rW1);
        k_router_epi<<<(NH+255)/256,256>>>(rW1, rb1);
        k_logits<<<(Nn+255)/256,256>>>(rW2, rb2);
        k_topk<<<(Nn+255)/256,256>>>();
    }

    // layer 0: shared aggregate of h, then he = relu(t + agg@Wn + b) fused in epilogue
    k_spmm0<<<(Nn+7)/8,256>>>();
    k_hgemm<<<gHalf,256,HG_SMEM>>>(2, 1, 1, 1, hb);   // L0 v + fused combine

    // layer 1: GEMMs + SpMM/combine (store activations)
    k_hgemm<<<gFull,256,HG_SMEM>>>(1, -1, 1 + 1*(NEx*2), 0, nullptr);
    k_spmm_combine<<<gS2,256>>>(hb + (size_t)1*NEx*Hh, oWr, oWn, 0);

    // layer 2: GEMMs + SpMM/combine with fused output projection
    k_hgemm<<<gFull,256,HG_SMEM>>>(1, -1, 1 + 2*(NEx*2), 0, nullptr);
    k_spmm_combine<<<gS2,256>>>(hb + (size_t)2*NEx*Hh, oWr, oWn, 1);

    // output layer
    k_aggz<<<(NEx*Nn+255)/256,256>>>();
    k_final<<<(Nn+255)/256,256>>>(ob, out);
}

// round 13
// speedup vs baseline: 1.5885x; 1.2417x over previous
#include <cuda_runtime.h>
#include <cuda_fp16.h>
#include <cstdint>
#include <math.h>

#define Nn 50000
#define Ee 800000
#define Gg 64
#define Ff 6
#define Hh 256
#define Oo 2
#define NEx 8
#define NH (Nn*Hh)
#define NMATS 49   // 1 router + 3 layers * 8 experts * 2

// ---------------- scratch (static __device__ arrays; no allocation) ----------------
__device__ __align__(128) float g_h[NH];                  // encoder output (fp32)
__device__ __align__(128) __half g_A0f[NH];               // encoder fp16
__device__ __align__(128) __half g_G0f[NH];               // agg(h) fp16 (layer-0, shared)
__device__ __align__(128) float g_r[NH];                  // router hidden
__device__ __align__(128) float g_rt[NH];                 // router GEMM scratch
__device__ __align__(128) float g_t[NEx*NH];              // he @ Wr
__device__ __align__(128) float g_v[NEx*NH];              // he @ Wn
__device__ __align__(128) __half g_Af[NEx*NH];            // per-expert activation fp16
__device__ __align__(128) __half g_Wfh[NMATS*65536];      // weights fp16 hi [mat][n][k]
__device__ __align__(128) __half g_Wfl[NMATS*65536];      // weights fp16 lo
__device__ __align__(128) float g_sf[Nn*2];
__device__ __align__(128) float g_logits[Nn*NEx];
__device__ __align__(128) float g_sparse[Nn*NEx];
__device__ __align__(128) float g_mz[NEx*Nn*4];           // [m0,m1,z0,z1] per (e,node)
__device__ __align__(128) float g_aggz[NEx*Nn*2];
__device__ int g_nodecnt[Gg];
__device__ int g_edgecnt[Gg];
__device__ int g_indeg[Nn];
__device__ int g_scantmp[Nn];
__device__ int g_bsum[64];
__device__ int g_bsumscan[64];
__device__ int g_rowstart[Nn+1];
__device__ int g_cursor[Nn];
__device__ int g_csr_src[Ee];

// ======================= warp MMA helpers (plain-target: sm_80+) =======================
__device__ __forceinline__ uint32_t smem_to_u32(const void* smem_ptr) {
    uint32_t addr;
    asm("{ .reg .u64 tmp; cvta.to.shared.u64 tmp, %1; cvt.u32.u64 %0, tmp; }"
        : "=r"(addr) : "l"(smem_ptr));
    return addr;
}
#define LDSM4(r0,r1,r2,r3,addr) \
    asm volatile("ldmatrix.sync.aligned.m8n8.x4.shared.b16 {%0,%1,%2,%3}, [%4];" \
        : "=r"(r0), "=r"(r1), "=r"(r2), "=r"(r3) : "r"(addr))
#define MMA16816F16(c, a, b) \
    asm volatile("mma.sync.aligned.m16n8k16.row.col.f32.f16.f16.f32 " \
        "{%0,%1,%2,%3}, {%4,%5,%6,%7}, {%8,%9}, {%0,%1,%2,%3};" \
        : "+f"((c)[0]), "+f"((c)[1]), "+f"((c)[2]), "+f"((c)[3]) \
        : "r"((a)[0]), "r"((a)[1]), "r"((a)[2]), "r"((a)[3]), \
          "r"((b)[0]), "r"((b)[1]))
#define CPA16(dst, src) \
    asm volatile("cp.async.cg.shared.global [%0], [%1], 16;" :: "r"(dst), "l"(src))
#define CP_COMMIT() asm volatile("cp.async.commit_group;")
#define CP_WAIT1()  asm volatile("cp.async.wait_group 1;")
#define CP_WAIT0()  asm volatile("cp.async.wait_group 0;")

// ---------------- small kernels ----------------
__global__ void k_zero() {
    int i = blockIdx.x*blockDim.x + threadIdx.x;
    if (i < Gg) { g_nodecnt[i]=0; g_edgecnt[i]=0; }
    if (i < Nn) g_indeg[i]=0;
}

__global__ void k_encoder(const float* __restrict__ x, const float* __restrict__ W,
                          const float* __restrict__ b) {
    int idx = blockIdx.x*blockDim.x + threadIdx.x;
    if (idx >= NH) return;
    int i = idx >> 8, c = idx & 255;
    float acc = b[c];
#pragma unroll
    for (int k=0;k<Ff;k++) acc += x[i*Ff+k]*W[k*Hh+c];
    float v = fmaxf(acc, 0.f);
    g_h[idx] = v;
    g_A0f[idx] = __float2half_rn(v);
}

// convert + transpose all weights to fp16 hi/lo, layout [mat][n][k]
__global__ void k_convW(const float* __restrict__ rW1, const float* __restrict__ hWr,
                        const float* __restrict__ hWn) {
    size_t idx = (size_t)blockIdx.x*blockDim.x + threadIdx.x;
    if (idx >= (size_t)NMATS*65536) return;
    int mat = (int)(idx >> 16);
    int r = (int)(idx & 65535);
    int n = r >> 8, k = r & 255;
    float w;
    if (mat == 0) {
        w = rW1[k*256 + n];
    } else {
        int hm = mat - 1;
        int l = hm >> 4, rr = hm & 15;
        int e = rr >> 1, m = rr & 1;
        const float* W = m ? hWn : hWr;
        w = W[((size_t)(l*NEx + e))*65536 + k*256 + n];
    }
    __half hi = __float2half_rn(w);
    g_Wfh[idx] = hi;
    g_Wfl[idx] = __float2half_rn(w - __half2float(hi));
}

__global__ void k_count_nodes(const int* __restrict__ batch) {
    __shared__ int hist[Gg];
    int t = threadIdx.x;
    if (t < Gg) hist[t]=0;
    __syncthreads();
    for (int i = blockIdx.x*blockDim.x + t; i < Nn; i += gridDim.x*blockDim.x)
        atomicAdd(&hist[batch[i]], 1);
    __syncthreads();
    if (t < Gg) atomicAdd(&g_nodecnt[t], hist[t]);
}

__global__ void k_count_edges(const int* __restrict__ ei, const int* __restrict__ batch) {
    __shared__ int hist[Gg];
    int t = threadIdx.x;
    if (t < Gg) hist[t]=0;
    __syncthreads();
    for (int e = blockIdx.x*blockDim.x + t; e < Ee; e += gridDim.x*blockDim.x)
        atomicAdd(&hist[batch[ei[e]]], 1);
    __syncthreads();
    if (t < Gg) atomicAdd(&g_edgecnt[t], hist[t]);
}

__global__ void k_indeg(const int* __restrict__ ei) {
    int e = blockIdx.x*blockDim.x + threadIdx.x;
    if (e < Ee) atomicAdd(&g_indeg[ei[Ee+e]], 1);
}

__global__ void k_sizefeat(const int* __restrict__ batch) {
    int i = blockIdx.x*blockDim.x + threadIdx.x;
    if (i >= Nn) return;
    int g = batch[i];
    g_sf[i*2+0] = logf((float)g_nodecnt[g] + 1.f);
    g_sf[i*2+1] = logf((float)g_edgecnt[g] + 1.f);
}

__global__ void k_scan1() {
    __shared__ int sh[1024];
    int t = threadIdx.x, gid = blockIdx.x*1024 + t;
    sh[t] = (gid < Nn) ? g_indeg[gid] : 0;
    __syncthreads();
    for (int off=1; off<1024; off<<=1) {
        int a = (t>=off) ? sh[t-off] : 0;
        __syncthreads();
        sh[t] += a;
        __syncthreads();
    }
    if (gid < Nn) g_scantmp[gid] = sh[t];
    if (t == 1023) g_bsum[blockIdx.x] = sh[1023];
}

__global__ void k_scan2() {
    __shared__ int sh[64];
    int t = threadIdx.x;
    const int NB1 = (Nn + 1023)/1024;
    sh[t] = (t < NB1) ? g_bsum[t] : 0;
    __syncthreads();
    for (int off=1; off<64; off<<=1) {
        int a = (t>=off) ? sh[t-off] : 0;
        __syncthreads();
        sh[t] += a;
        __syncthreads();
    }
    g_bsumscan[t] = sh[t];
}

__global__ void k_scan3() {
    int i = blockIdx.x*blockDim.x + threadIdx.x;
    if (i >= Nn) return;
    int blk = i >> 10;
    int incl = g_scantmp[i] + (blk ? g_bsumscan[blk-1] : 0);
    g_rowstart[i+1] = incl;
    if (i == 0) g_rowstart[0] = 0;
}

__global__ void k_cursor() {
    int i = blockIdx.x*blockDim.x + threadIdx.x;
    if (i < Nn) g_cursor[i] = g_rowstart[i];
}

__global__ void k_scatter(const int* __restrict__ ei) {
    int e = blockIdx.x*blockDim.x + threadIdx.x;
    if (e >= Ee) return;
    int d = ei[Ee+e];
    int p = atomicAdd(&g_cursor[d], 1);
    g_csr_src[p] = ei[e];
}

// ---------------- router SGEMM (exact fp32, tile 128x128) -> g_rt ----------------
__global__ void __launch_bounds__(256) k_sgemm_router(const float* __restrict__ B) {
    const float* A = g_h;
    float* Cb = g_rt;

    __shared__ float As[16][128];
    __shared__ float Bs[16][128];

    int tid = threadIdx.x;
    int bm = blockIdx.x*128, bn = blockIdx.y*128;
    int tx = tid & 15, ty = tid >> 4;
    int a_row = tid >> 2;
    int a_col = (tid & 3) * 4;
    int b_row = tid >> 5;
    int b_col = (tid & 31) * 4;

    float acc[8][8];
#pragma unroll
    for (int i=0;i<8;i++)
#pragma unroll
        for (int j=0;j<8;j++) acc[i][j]=0.f;

    for (int kt=0; kt<256; kt+=16) {
        __syncthreads();
#pragma unroll
        for (int i=0;i<2;i++) {
            int r = a_row + i*64;
            int gm = bm + r;
            float4 av = make_float4(0.f,0.f,0.f,0.f);
            if (gm < Nn) av = *(const float4*)(A + (size_t)gm*256 + kt + a_col);
            As[a_col+0][r]=av.x; As[a_col+1][r]=av.y;
            As[a_col+2][r]=av.z; As[a_col+3][r]=av.w;
        }
#pragma unroll
        for (int i=0;i<2;i++) {
            int r = b_row + i*8;
            *(float4*)&Bs[r][b_col] = *(const float4*)(B + (size_t)(kt+r)*256 + bn + b_col);
        }
        __syncthreads();
#pragma unroll
        for (int kk=0;kk<16;kk++) {
            float4 a0 = *(const float4*)&As[kk][ty*4];
            float4 a1 = *(const float4*)&As[kk][64+ty*4];
            float4 b0 = *(const float4*)&Bs[kk][tx*4];
            float4 b1 = *(const float4*)&Bs[kk][64+tx*4];
            float a[8] = {a0.x,a0.y,a0.z,a0.w,a1.x,a1.y,a1.z,a1.w};
            float b[8] = {b0.x,b0.y,b0.z,b0.w,b1.x,b1.y,b1.z,b1.w};
#pragma unroll
            for (int i=0;i<8;i++)
#pragma unroll
                for (int j=0;j<8;j++) acc[i][j] += a[i]*b[j];
        }
    }
#pragma unroll
    for (int ih=0; ih<2; ih++) {
#pragma unroll
        for (int i=0;i<4;i++) {
            int gm = bm + ih*64 + ty*4 + i;
            if (gm >= Nn) continue;
            float* crow = Cb + (size_t)gm*256 + bn;
            int r = ih*4 + i;
            *(float4*)(crow + tx*4)      = make_float4(acc[r][0],acc[r][1],acc[r][2],acc[r][3]);
            *(float4*)(crow + 64 + tx*4) = make_float4(acc[r][4],acc[r][5],acc[r][6],acc[r][7]);
        }
    }
}

// ============== HMMA fp16 2-term GEMM, BK=32, 2-stage cp.async ====================
// C = A_f16 @ (Wh + Wl): A single fp16 (activations), weights split exactly.
// asel: 0 -> A = g_A0f, 1 -> A = g_Af(e), 2 -> A = g_G0f
// mSel: -1 -> z covers e*2+m ; 0/1 -> z covers e, m fixed
// epi:  0 -> fp32 store to g_t/g_v; 1 -> fused combine: relu(c+t+bias) -> g_Af (fp16)
// Stage (30720B): A@0, Bh@10240, Bl@20480 — rows pitch 80B. 2 stages = 61440B dyn.
#define HG_STAGE 30720
#define HG_SMEM  (2*HG_STAGE)

__global__ void __launch_bounds__(256, 2) k_hgemm(int asel, int mSel, int matBase,
                                                  int epi, const float* __restrict__ bias)
{
    extern __shared__ __align__(16) char hg_smem[];
    uint32_t sbase = smem_to_u32(hg_smem);
    int tid = threadIdx.x, lane = tid & 31, wid = tid >> 5;
    int bm = blockIdx.x * 128, bn = blockIdx.y * 128;
    int z = blockIdx.z;
    int e, m;
    if (mSel < 0) { e = z >> 1; m = z & 1; } else { e = z; m = mSel; }
    int mat = matBase + e*2 + m;

    const __half* Af;
    if (asel == 0)      Af = g_A0f;
    else if (asel == 1) Af = g_Af + (size_t)e*NH;
    else                Af = g_G0f;
    const __half* Bh = g_Wfh + (size_t)mat * 65536;
    const __half* Bl = g_Wfl + (size_t)mat * 65536;

    int wm = (wid & 3) * 32;
    int wn = (wid >> 2) * 64;

    float c[2][8][4];
#pragma unroll
    for (int mi=0;mi<2;mi++)
#pragma unroll
        for (int nf=0;nf<8;nf++)
#pragma unroll
            for (int r=0;r<4;r++) c[mi][nf][r] = 0.f;

    int lrow = tid >> 1, lch = tid & 1;
    int agr = bm + lrow; if (agr >= Nn) agr = Nn - 1;   // clamp: junk rows masked on store
    const __half* srcA  = Af + (size_t)agr*256 + lch*8;
    const __half* srcBh = Bh + (size_t)(bn + lrow)*256 + lch*8;
    const __half* srcBl = Bl + (size_t)(bn + lrow)*256 + lch*8;
    uint32_t dstOff = (uint32_t)lrow*80 + (uint32_t)lch*16;

    // prologue: stage 0 (k [0,32))
    {
        uint32_t d = sbase + dstOff;
        CPA16(d,            srcA);
        CPA16(d + 32,       srcA + 16);
        CPA16(d + 10240,    srcBh);
        CPA16(d + 10272,    srcBh + 16);
        CPA16(d + 20480,    srcBl);
        CPA16(d + 20512,    srcBl + 16);
        CP_COMMIT();
    }

    int rsel = lane & 15;
    int cofs = (lane & 16) ? 16 : 0;

    for (int kt = 0; kt < 8; kt++) {
        if (kt < 7) {
            int k0 = (kt + 1) * 32;
            uint32_t d = sbase + ((kt + 1) & 1) * HG_STAGE + dstOff;
            CPA16(d,            srcA + k0);
            CPA16(d + 32,       srcA + k0 + 16);
            CPA16(d + 10240,    srcBh + k0);
            CPA16(d + 10272,    srcBh + k0 + 16);
            CPA16(d + 20480,    srcBl + k0);
            CPA16(d + 20512,    srcBl + k0 + 16);
            CP_COMMIT();
            CP_WAIT1();
        } else {
            CP_WAIT0();
        }
        __syncthreads();
        uint32_t buf = sbase + (kt & 1) * HG_STAGE;

#pragma unroll
        for (int half_ = 0; half_ < 2; half_++) {
            uint32_t hcol = (uint32_t)(half_*32 + cofs);
            uint32_t a_f[2][4];
#pragma unroll
            for (int mi = 0; mi < 2; mi++) {
                uint32_t ro = buf + (uint32_t)(wm + mi*16 + rsel) * 80 + hcol;
                LDSM4(a_f[mi][0], a_f[mi][1], a_f[mi][2], a_f[mi][3], ro);
            }
            uint32_t b_h[8][2], b_l[8][2];
#pragma unroll
            for (int np = 0; np < 4; np++) {
                uint32_t ro = buf + 10240 + (uint32_t)(wn + np*16 + rsel) * 80 + hcol;
                uint32_t r0, r1, r2, r3;
                LDSM4(r0, r1, r2, r3, ro);
                b_h[np*2][0]=r0; b_h[np*2+1][0]=r1; b_h[np*2][1]=r2; b_h[np*2+1][1]=r3;
                LDSM4(r0, r1, r2, r3, ro + 10240);
                b_l[np*2][0]=r0; b_l[np*2+1][0]=r1; b_l[np*2][1]=r2; b_l[np*2+1][1]=r3;
            }
            // term-major: reuse distance 16 — latency hidden
#pragma unroll
            for (int mi = 0; mi < 2; mi++)
#pragma unroll
                for (int nf = 0; nf < 8; nf++)
                    MMA16816F16(c[mi][nf], a_f[mi], b_h[nf]);
#pragma unroll
            for (int mi = 0; mi < 2; mi++)
#pragma unroll
                for (int nf = 0; nf < 8; nf++)
                    MMA16816F16(c[mi][nf], a_f[mi], b_l[nf]);
        }
        __syncthreads();
    }

    if (epi == 0) {
        float* C = (m ? g_v : g_t) + (size_t)e * NH;
#pragma unroll
        for (int mi = 0; mi < 2; mi++) {
            int row0 = bm + wm + mi*16 + (lane >> 2);
#pragma unroll
            for (int nf = 0; nf < 8; nf++) {
                int col = bn + wn + nf*8 + (lane & 3)*2;
                if (row0 < Nn)
                    *(float2*)(C + (size_t)row0*256 + col) = make_float2(c[mi][nf][0], c[mi][nf][1]);
                if (row0 + 8 < Nn)
                    *(float2*)(C + (size_t)(row0+8)*256 + col) = make_float2(c[mi][nf][2], c[mi][nf][3]);
            }
        }
    } else {
        // fused combine: he = relu(c + t + bias) -> fp16
        const float* T = g_t + (size_t)e * NH;
        __half* AF = g_Af + (size_t)e * NH;
#pragma unroll
        for (int mi = 0; mi < 2; mi++) {
            int row0 = bm + wm + mi*16 + (lane >> 2);
#pragma unroll
            for (int nf = 0; nf < 8; nf++) {
                int col = bn + wn + nf*8 + (lane & 3)*2;
                float bc0 = bias[e*256 + col], bc1 = bias[e*256 + col + 1];
#pragma unroll
                for (int rr = 0; rr < 2; rr++) {
                    int row = row0 + rr*8;
                    if (row >= Nn) continue;
                    float2 t2 = *(const float2*)(T + (size_t)row*256 + col);
                    float v0 = fmaxf(c[mi][nf][rr*2+0] + t2.x + bc0, 0.f);
                    float v1 = fmaxf(c[mi][nf][rr*2+1] + t2.y + bc1, 0.f);
                    *(__half2*)(AF + (size_t)row*256 + col) = __floats2half2_rn(v0, v1);
                }
            }
        }
    }
}

// ---------------- router epilogue ----------------
__global__ void k_router_epi(const float* __restrict__ W1, const float* __restrict__ b1) {
    int idx = blockIdx.x*blockDim.x + threadIdx.x;
    if (idx >= NH) return;
    int i = idx >> 8, c = idx & 255;
    float v = g_rt[idx] + g_sf[i*2]*W1[256*256+c] + g_sf[i*2+1]*W1[257*256+c] + b1[c];
    g_r[idx] = fmaxf(v, 0.f);
}

// one thread per node; W2/b2 staged in smem (row read once)
__global__ void k_logits(const float* __restrict__ W2, const float* __restrict__ b2) {
    __shared__ float sW[2048];
    __shared__ float sb[8];
    int t = threadIdx.x;
    for (int j = t; j < 2048; j += 256) sW[j] = W2[j];
    if (t < 8) sb[t] = b2[t];
    __syncthreads();
    int i = blockIdx.x*256 + t;
    if (i >= Nn) return;
    const float4* r = (const float4*)(g_r + (size_t)i*256);
    float acc[8];
#pragma unroll
    for (int e=0;e<8;e++) acc[e] = sb[e];
    for (int k4 = 0; k4 < 64; k4++) {
        float4 v = r[k4];
        const float* w = &sW[k4*32];
#pragma unroll
        for (int e=0;e<8;e++)
            acc[e] += v.x*w[e] + v.y*w[8+e] + v.z*w[16+e] + v.w*w[24+e];
    }
#pragma unroll
    for (int e=0;e<8;e++) g_logits[i*8+e] = acc[e];
}

__global__ void k_topk() {
    int i = blockIdx.x*blockDim.x + threadIdx.x;
    if (i >= Nn) return;
    float l[8];
#pragma unroll
    for (int e=0;e<8;e++) l[e] = g_logits[i*8+e];
    int i1 = 0; float m1 = l[0];
#pragma unroll
    for (int e=1;e<8;e++) if (l[e] > m1) { m1 = l[e]; i1 = e; }
    int i2 = -1; float m2 = -1e30f;
#pragma unroll
    for (int e=0;e<8;e++) if (e != i1 && l[e] > m2) { m2 = l[e]; i2 = e; }
    float e2v = expf(m2 - m1);
    float inv = 1.f/(1.f + e2v);
    float s[8];
#pragma unroll
    for (int e=0;e<8;e++) s[e]=0.f;
    s[i1] = inv; s[i2] = e2v*inv;
#pragma unroll
    for (int e=0;e<8;e++) g_sparse[i*8+e] = s[e];
}

// ---------------- layer-0 SpMM: agg(h) once, shared across experts ----------------
__global__ void k_spmm0() {
    int dst = blockIdx.x*8 + (threadIdx.x >> 5);
    int lane = threadIdx.x & 31;
    if (dst >= Nn) return;
    const float* vb = g_h + lane*8;
    int s0 = g_rowstart[dst], s1 = g_rowstart[dst+1];
    float a0=0.f,a1=0.f,a2=0.f,a3=0.f,a4=0.f,a5=0.f,a6=0.f,a7=0.f;
    for (int p = s0; p < s1; p++) {
        int src = g_csr_src[p];
        const float4* row = (const float4*)(vb + (size_t)src*256);
        float4 x0 = row[0], x1 = row[1];
        a0 += x0.x; a1 += x0.y; a2 += x0.z; a3 += x0.w;
        a4 += x1.x; a5 += x1.y; a6 += x1.z; a7 += x1.w;
    }
    float vals[8] = {a0,a1,a2,a3,a4,a5,a6,a7};
    union { __half h[8]; uint4 u; } H;
#pragma unroll
    for (int j = 0; j < 8; j++) H.h[j] = __float2half_rn(vals[j]);
    *(uint4*)(g_G0f + (size_t)dst*256 + lane*8) = H.u;
}

// ------- SpMM + combine, expert-major (grid: x = dst/8, y = expert) -------
// fuseOut=0: store fp16 activations (layer 1).
// fuseOut=1: last hidden layer — fused output projection; writes g_mz only.
__global__ void k_spmm_combine(const float* __restrict__ bias,
                               const float* __restrict__ Wr,
                               const float* __restrict__ Wn,
                               int fuseOut) {
    int dst = blockIdx.x*8 + (threadIdx.x >> 5);
    int e = blockIdx.y;
    int lane = threadIdx.x & 31;
    if (dst >= Nn) return;
    const float* vb = g_v + (size_t)e*NH + lane*8;
    int s0 = g_rowstart[dst], s1 = g_rowstart[dst+1];
    float a0=0.f,a1=0.f,a2=0.f,a3=0.f,a4=0.f,a5=0.f,a6=0.f,a7=0.f;
    for (int p = s0; p < s1; p++) {
        int src = g_csr_src[p];
        const float4* row = (const float4*)(vb + (size_t)src*256);
        float4 x0 = row[0], x1 = row[1];
        a0 += x0.x; a1 += x0.y; a2 += x0.z; a3 += x0.w;
        a4 += x1.x; a5 += x1.y; a6 += x1.z; a7 += x1.w;
    }
    size_t base = (size_t)e*NH + (size_t)dst*256 + lane*8;
    const float4* tb = (const float4*)(g_t + base);
    float4 t0 = tb[0], t1 = tb[1];
    const float4* bb = (const float4*)(bias + e*256 + lane*8);
    float4 b0 = bb[0], b1 = bb[1];
    float vals[8];
    vals[0]=t0.x+a0+b0.x; vals[1]=t0.y+a1+b0.y; vals[2]=t0.z+a2+b0.z; vals[3]=t0.w+a3+b0.w;
    vals[4]=t1.x+a4+b1.x; vals[5]=t1.y+a5+b1.y; vals[6]=t1.z+a6+b1.z; vals[7]=t1.w+a7+b1.w;
    if (!fuseOut) {
        union { __half h[8]; uint4 u; } H;
#pragma unroll
        for (int j = 0; j < 8; j++)
            H.h[j] = __float2half_rn(fmaxf(vals[j], 0.f));
        *(uint4*)(g_Af + base) = H.u;
    } else {
        const float* WRe = Wr + e*512;
        const float* WNe = Wn + e*512;
        float m0=0.f, m1=0.f, z0=0.f, z1=0.f;
#pragma unroll
        for (int j = 0; j < 8; j++) {
            float v = fmaxf(vals[j], 0.f);
            int k = lane*8 + j;
            m0 += v*WRe[k*2];   m1 += v*WRe[k*2+1];
            z0 += v*WNe[k*2];   z1 += v*WNe[k*2+1];
        }
#pragma unroll
        for (int off = 16; off > 0; off >>= 1) {
            m0 += __shfl_xor_sync(0xFFFFFFFFu, m0, off);
            m1 += __shfl_xor_sync(0xFFFFFFFFu, m1, off);
            z0 += __shfl_xor_sync(0xFFFFFFFFu, z0, off);
            z1 += __shfl_xor_sync(0xFFFFFFFFu, z1, off);
        }
        if (lane == 0) {
            float* o = g_mz + ((size_t)e*Nn + dst)*4;
            o[0]=m0; o[1]=m1; o[2]=z0; o[3]=z1;
        }
    }
}

__global__ void k_aggz() {
    int idx = blockIdx.x*blockDim.x + threadIdx.x;
    if (idx >= NEx*Nn) return;
    int dst = idx % Nn;
    int e = idx / Nn;
    int s0 = g_rowstart[dst], s1 = g_rowstart[dst+1];
    float a0=0.f, a1=0.f;
    for (int p=s0; p<s1; p++) {
        int src = g_csr_src[p];
        const float* z = g_mz + ((size_t)e*Nn + src)*4 + 2;
        a0 += z[0]; a1 += z[1];
    }
    g_aggz[((size_t)e*Nn+dst)*2+0] = a0;
    g_aggz[((size_t)e*Nn+dst)*2+1] = a1;
}

__global__ void k_final(const float* __restrict__ outb, float* __restrict__ out) {
    int i = blockIdx.x*blockDim.x + threadIdx.x;
    if (i >= Nn) return;
    float o0=0.f, o1=0.f;
#pragma unroll
    for (int e=0;e<8;e++) {
        float s = g_sparse[i*8+e];
        const float* mz = g_mz + ((size_t)e*Nn+i)*4;
        const float* az = g_aggz + ((size_t)e*Nn+i)*2;
        o0 += s*(mz[0] + az[0] + outb[e*2+0]);
        o1 += s*(mz[1] + az[1] + outb[e*2+1]);
    }
    out[i*2+0] = o0;
    out[i*2+1] = o1;
}

// ---------------- launch ----------------
extern "C" void kernel_launch(void* const* d_in, const int* in_sizes, int n_in,
                              void* d_out, int out_size) {
    const float* x    = (const float*)d_in[0];
    const int*   ei   = (const int*)  d_in[1];
    const int*   batch= (const int*)  d_in[2];
    const float* encW = (const float*)d_in[3];
    const float* encb = (const float*)d_in[4];
    const float* rW1  = (const float*)d_in[5];
    const float* rb1  = (const float*)d_in[6];
    const float* rW2  = (const float*)d_in[7];
    const float* rb2  = (const float*)d_in[8];
    const float* hWr  = (const float*)d_in[9];
    const float* hWn  = (const float*)d_in[10];
    const float* hb   = (const float*)d_in[11];
    const float* oWr  = (const float*)d_in[12];
    const float* oWn  = (const float*)d_in[13];
    const float* ob   = (const float*)d_in[14];
    float* out = (float*)d_out;

    cudaFuncSetAttribute(k_hgemm, cudaFuncAttributeMaxDynamicSharedMemorySize, HG_SMEM);

    const int NTILES = (Nn + 127) / 128;   // 391
    dim3 gHalf(NTILES, 2, NEx);            // one m per launch
    dim3 gFull(NTILES, 2, NEx*2);          // both m
    dim3 gS2((Nn + 7)/8, NEx);             // expert-major SpMM

    k_zero<<<(Nn+255)/256,256>>>();
    k_encoder<<<(NH+255)/256,256>>>(x, encW, encb);
    k_convW<<<(NMATS*65536+255)/256,256>>>(rW1, hWr, hWn);
    k_hgemm<<<gHalf,256,HG_SMEM>>>(0, 0, 1, 0, nullptr);   // L0 t (profiled slot)
    k_count_nodes<<<256,256>>>(batch);
    k_count_edges<<<512,256>>>(ei, batch);
    k_indeg<<<(Ee+255)/256,256>>>(ei);
    k_sizefeat<<<(Nn+255)/256,256>>>(batch);
    k_scan1<<<(Nn+1023)/1024,1024>>>();
    k_scan2<<<1,64>>>();
    k_scan3<<<(Nn+255)/256,256>>>();
    k_cursor<<<(Nn+255)/256,256>>>();
    k_scatter<<<(Ee+255)/256,256>>>(ei);

    // router (exact fp32 in its own buffer g_rt)
    {
        dim3 gR((Nn+127)/128, 2, 1);
        k_sgemm_router<<<gR,256>>>(rW1);
        k_router_epi<<<(NH+255)/256,256>>>(rW1, rb1);
        k_logits<<<(Nn+255)/256,256>>>(rW2, rb2);
        k_topk<<<(Nn+255)/256,256>>>();
    }

    // layer 0: shared aggregate of h, then he = relu(t + agg@Wn + b) fused in epilogue
    k_spmm0<<<(Nn+7)/8,256>>>();
    k_hgemm<<<gHalf,256,HG_SMEM>>>(2, 1, 1, 1, hb);   // L0 v + fused combine

    // layer 1: GEMMs + SpMM/combine (store activations)
    k_hgemm<<<gFull,256,HG_SMEM>>>(1, -1, 1 + 1*(NEx*2), 0, nullptr);
    k_spmm_combine<<<gS2,256>>>(hb + (size_t)1*NEx*Hh, oWr, oWn, 0);

    // layer 2: GEMMs + SpMM/combine with fused output projection
    k_hgemm<<<gFull,256,HG_SMEM>>>(1, -1, 1 + 2*(NEx*2), 0, nullptr);
    k_spmm_combine<<<gS2,256>>>(hb + (size_t)2*NEx*Hh, oWr, oWn, 1);

    // output layer
    k_aggz<<<(NEx*Nn+255)/256,256>>>();
    k_final<<<(Nn+255)/256,256>>>(ob, out);
}

// round 14
// speedup vs baseline: 2.0240x; 1.2742x over previous
#include <cuda_runtime.h>
#include <cuda_fp16.h>
#include <cstdint>
#include <math.h>

#define Nn 50000
#define Ee 800000
#define Gg 64
#define Ff 6
#define Hh 256
#define Oo 2
#define NEx 8
#define NH (Nn*Hh)
#define NMATS 49   // 1 router + 3 layers * 8 experts * 2

// ---------------- scratch (static __device__ arrays; no allocation) ----------------
__device__ __align__(128) float g_h[NH];                  // encoder output (fp32)
__device__ __align__(128) __half g_A0f[NH];               // encoder fp16
__device__ __align__(128) __half g_G0f[NH];               // agg(h) fp16 (layer-0, shared)
__device__ __align__(128) float g_r[NH];                  // router hidden
__device__ __align__(128) float g_rt[NH];                 // router GEMM scratch
__device__ __align__(128) float g_t[NEx*NH];              // he @ Wr
__device__ __align__(128) float g_v[NEx*NH];              // he @ Wn
__device__ __align__(128) __half g_Af[NEx*NH];            // per-expert activation fp16
__device__ __align__(128) __half g_Wf[NMATS*65536];       // weights fp16 [mat][n][k]
__device__ __align__(128) float g_sf[Nn*2];
__device__ __align__(128) float g_logits[Nn*NEx];
__device__ __align__(128) float g_sparse[Nn*NEx];
__device__ __align__(128) float g_mz[NEx*Nn*4];           // [m0,m1,z0,z1] per (e,node)
__device__ __align__(128) float g_aggz[NEx*Nn*2];
__device__ int g_nodecnt[Gg];
__device__ int g_edgecnt[Gg];
__device__ int g_indeg[Nn];
__device__ int g_scantmp[Nn];
__device__ int g_bsum[64];
__device__ int g_bsumscan[64];
__device__ int g_rowstart[Nn+1];
__device__ int g_cursor[Nn];
__device__ int g_csr_src[Ee];

// ======================= warp MMA helpers (plain-target: sm_80+) =======================
__device__ __forceinline__ uint32_t smem_to_u32(const void* smem_ptr) {
    uint32_t addr;
    asm("{ .reg .u64 tmp; cvta.to.shared.u64 tmp, %1; cvt.u32.u64 %0, tmp; }"
        : "=r"(addr) : "l"(smem_ptr));
    return addr;
}
#define LDSM4(r0,r1,r2,r3,addr) \
    asm volatile("ldmatrix.sync.aligned.m8n8.x4.shared.b16 {%0,%1,%2,%3}, [%4];" \
        : "=r"(r0), "=r"(r1), "=r"(r2), "=r"(r3) : "r"(addr))
#define MMA16816F16(c, a, b) \
    asm volatile("mma.sync.aligned.m16n8k16.row.col.f32.f16.f16.f32 " \
        "{%0,%1,%2,%3}, {%4,%5,%6,%7}, {%8,%9}, {%0,%1,%2,%3};" \
        : "+f"((c)[0]), "+f"((c)[1]), "+f"((c)[2]), "+f"((c)[3]) \
        : "r"((a)[0]), "r"((a)[1]), "r"((a)[2]), "r"((a)[3]), \
          "r"((b)[0]), "r"((b)[1]))
#define CPA16(dst, src) \
    asm volatile("cp.async.cg.shared.global [%0], [%1], 16;" :: "r"(dst), "l"(src))
#define CP_COMMIT() asm volatile("cp.async.commit_group;")
#define CP_WAIT1()  asm volatile("cp.async.wait_group 1;")
#define CP_WAIT0()  asm volatile("cp.async.wait_group 0;")

// ---------------- small kernels ----------------
__global__ void k_zero() {
    int i = blockIdx.x*blockDim.x + threadIdx.x;
    if (i < Gg) { g_nodecnt[i]=0; g_edgecnt[i]=0; }
    if (i < Nn) g_indeg[i]=0;
}

__global__ void k_encoder(const float* __restrict__ x, const float* __restrict__ W,
                          const float* __restrict__ b) {
    int idx = blockIdx.x*blockDim.x + threadIdx.x;
    if (idx >= NH) return;
    int i = idx >> 8, c = idx & 255;
    float acc = b[c];
#pragma unroll
    for (int k=0;k<Ff;k++) acc += x[i*Ff+k]*W[k*Hh+c];
    float v = fmaxf(acc, 0.f);
    g_h[idx] = v;
    g_A0f[idx] = __float2half_rn(v);
}

// convert + transpose all weights to fp16, layout [mat][n][k]
__global__ void k_convW(const float* __restrict__ rW1, const float* __restrict__ hWr,
                        const float* __restrict__ hWn) {
    size_t idx = (size_t)blockIdx.x*blockDim.x + threadIdx.x;
    if (idx >= (size_t)NMATS*65536) return;
    int mat = (int)(idx >> 16);
    int r = (int)(idx & 65535);
    int n = r >> 8, k = r & 255;
    float w;
    if (mat == 0) {
        w = rW1[k*256 + n];
    } else {
        int hm = mat - 1;
        int l = hm >> 4, rr = hm & 15;
        int e = rr >> 1, m = rr & 1;
        const float* W = m ? hWn : hWr;
        w = W[((size_t)(l*NEx + e))*65536 + k*256 + n];
    }
    g_Wf[idx] = __float2half_rn(w);
}

__global__ void k_count_nodes(const int* __restrict__ batch) {
    __shared__ int hist[Gg];
    int t = threadIdx.x;
    if (t < Gg) hist[t]=0;
    __syncthreads();
    for (int i = blockIdx.x*blockDim.x + t; i < Nn; i += gridDim.x*blockDim.x)
        atomicAdd(&hist[batch[i]], 1);
    __syncthreads();
    if (t < Gg) atomicAdd(&g_nodecnt[t], hist[t]);
}

__global__ void k_count_edges(const int* __restrict__ ei, const int* __restrict__ batch) {
    __shared__ int hist[Gg];
    int t = threadIdx.x;
    if (t < Gg) hist[t]=0;
    __syncthreads();
    for (int e = blockIdx.x*blockDim.x + t; e < Ee; e += gridDim.x*blockDim.x)
        atomicAdd(&hist[batch[ei[e]]], 1);
    __syncthreads();
    if (t < Gg) atomicAdd(&g_edgecnt[t], hist[t]);
}

__global__ void k_indeg(const int* __restrict__ ei) {
    int e = blockIdx.x*blockDim.x + threadIdx.x;
    if (e < Ee) atomicAdd(&g_indeg[ei[Ee+e]], 1);
}

__global__ void k_sizefeat(const int* __restrict__ batch) {
    int i = blockIdx.x*blockDim.x + threadIdx.x;
    if (i >= Nn) return;
    int g = batch[i];
    g_sf[i*2+0] = logf((float)g_nodecnt[g] + 1.f);
    g_sf[i*2+1] = logf((float)g_edgecnt[g] + 1.f);
}

__global__ void k_scan1() {
    __shared__ int sh[1024];
    int t = threadIdx.x, gid = blockIdx.x*1024 + t;
    sh[t] = (gid < Nn) ? g_indeg[gid] : 0;
    __syncthreads();
    for (int off=1; off<1024; off<<=1) {
        int a = (t>=off) ? sh[t-off] : 0;
        __syncthreads();
        sh[t] += a;
        __syncthreads();
    }
    if (gid < Nn) g_scantmp[gid] = sh[t];
    if (t == 1023) g_bsum[blockIdx.x] = sh[1023];
}

__global__ void k_scan2() {
    __shared__ int sh[64];
    int t = threadIdx.x;
    const int NB1 = (Nn + 1023)/1024;
    sh[t] = (t < NB1) ? g_bsum[t] : 0;
    __syncthreads();
    for (int off=1; off<64; off<<=1) {
        int a = (t>=off) ? sh[t-off] : 0;
        __syncthreads();
        sh[t] += a;
        __syncthreads();
    }
    g_bsumscan[t] = sh[t];
}

__global__ void k_scan3() {
    int i = blockIdx.x*blockDim.x + threadIdx.x;
    if (i >= Nn) return;
    int blk = i >> 10;
    int incl = g_scantmp[i] + (blk ? g_bsumscan[blk-1] : 0);
    g_rowstart[i+1] = incl;
    if (i == 0) g_rowstart[0] = 0;
}

__global__ void k_cursor() {
    int i = blockIdx.x*blockDim.x + threadIdx.x;
    if (i < Nn) g_cursor[i] = g_rowstart[i];
}

__global__ void k_scatter(const int* __restrict__ ei) {
    int e = blockIdx.x*blockDim.x + threadIdx.x;
    if (e >= Ee) return;
    int d = ei[Ee+e];
    int p = atomicAdd(&g_cursor[d], 1);
    g_csr_src[p] = ei[e];
}

// ---------------- router SGEMM (exact fp32, tile 128x128) -> g_rt ----------------
__global__ void __launch_bounds__(256) k_sgemm_router(const float* __restrict__ B) {
    const float* A = g_h;
    float* Cb = g_rt;

    __shared__ float As[16][128];
    __shared__ float Bs[16][128];

    int tid = threadIdx.x;
    int bm = blockIdx.x*128, bn = blockIdx.y*128;
    int tx = tid & 15, ty = tid >> 4;
    int a_row = tid >> 2;
    int a_col = (tid & 3) * 4;
    int b_row = tid >> 5;
    int b_col = (tid & 31) * 4;

    float acc[8][8];
#pragma unroll
    for (int i=0;i<8;i++)
#pragma unroll
        for (int j=0;j<8;j++) acc[i][j]=0.f;

    for (int kt=0; kt<256; kt+=16) {
        __syncthreads();
#pragma unroll
        for (int i=0;i<2;i++) {
            int r = a_row + i*64;
            int gm = bm + r;
            float4 av = make_float4(0.f,0.f,0.f,0.f);
            if (gm < Nn) av = *(const float4*)(A + (size_t)gm*256 + kt + a_col);
            As[a_col+0][r]=av.x; As[a_col+1][r]=av.y;
            As[a_col+2][r]=av.z; As[a_col+3][r]=av.w;
        }
#pragma unroll
        for (int i=0;i<2;i++) {
            int r = b_row + i*8;
            *(float4*)&Bs[r][b_col] = *(const float4*)(B + (size_t)(kt+r)*256 + bn + b_col);
        }
        __syncthreads();
#pragma unroll
        for (int kk=0;kk<16;kk++) {
            float4 a0 = *(const float4*)&As[kk][ty*4];
            float4 a1 = *(const float4*)&As[kk][64+ty*4];
            float4 b0 = *(const float4*)&Bs[kk][tx*4];
            float4 b1 = *(const float4*)&Bs[kk][64+tx*4];
            float a[8] = {a0.x,a0.y,a0.z,a0.w,a1.x,a1.y,a1.z,a1.w};
            float b[8] = {b0.x,b0.y,b0.z,b0.w,b1.x,b1.y,b1.z,b1.w};
#pragma unroll
            for (int i=0;i<8;i++)
#pragma unroll
                for (int j=0;j<8;j++) acc[i][j] += a[i]*b[j];
        }
    }
#pragma unroll
    for (int ih=0; ih<2; ih++) {
#pragma unroll
        for (int i=0;i<4;i++) {
            int gm = bm + ih*64 + ty*4 + i;
            if (gm >= Nn) continue;
            float* crow = Cb + (size_t)gm*256 + bn;
            int r = ih*4 + i;
            *(float4*)(crow + tx*4)      = make_float4(acc[r][0],acc[r][1],acc[r][2],acc[r][3]);
            *(float4*)(crow + 64 + tx*4) = make_float4(acc[r][4],acc[r][5],acc[r][6],acc[r][7]);
        }
    }
}

// ============== HMMA fp16 1-term GEMM, BK=32, 2-stage cp.async, static smem =========
// C = A_f16 @ W_f16 (fp32 accumulate).
// asel: 0 -> A = g_A0f, 1 -> A = g_Af(e), 2 -> A = g_G0f
// mSel: -1 -> z covers e*2+m ; 0/1 -> z covers e, m fixed
// epi:  0 -> fp32 store to g_t/g_v; 1 -> fused combine: relu(c+t+bias) -> g_Af (fp16)
// Stage (20480B): A@0, B@10240 — rows pitch 80B (conflict-free ldmatrix). 2 stages static.
#define HG_STAGE 20480

__global__ void __launch_bounds__(256, 2) k_hgemm(int asel, int mSel, int matBase,
                                                  int epi, const float* __restrict__ bias)
{
    __shared__ __align__(16) char smarr[2*HG_STAGE];   // 40 KB static
    uint32_t sbase = smem_to_u32(smarr);
    int tid = threadIdx.x, lane = tid & 31, wid = tid >> 5;
    int bm = blockIdx.x * 128, bn = blockIdx.y * 128;
    int z = blockIdx.z;
    int e, m;
    if (mSel < 0) { e = z >> 1; m = z & 1; } else { e = z; m = mSel; }
    int mat = matBase + e*2 + m;

    const __half* Af;
    if (asel == 0)      Af = g_A0f;
    else if (asel == 1) Af = g_Af + (size_t)e*NH;
    else                Af = g_G0f;
    const __half* Bf = g_Wf + (size_t)mat * 65536;

    int wm = (wid & 3) * 32;
    int wn = (wid >> 2) * 64;

    float c[2][8][4];
#pragma unroll
    for (int mi=0;mi<2;mi++)
#pragma unroll
        for (int nf=0;nf<8;nf++)
#pragma unroll
            for (int r=0;r<4;r++) c[mi][nf][r] = 0.f;

    int lrow = tid >> 1, lch = tid & 1;
    int agr = bm + lrow; if (agr >= Nn) agr = Nn - 1;   // clamp: junk rows masked on store
    const __half* srcA = Af + (size_t)agr*256 + lch*8;
    const __half* srcB = Bf + (size_t)(bn + lrow)*256 + lch*8;
    uint32_t dstOff = (uint32_t)lrow*80 + (uint32_t)lch*16;

    // prologue: stage 0 (k [0,32))
    {
        uint32_t d = sbase + dstOff;
        CPA16(d,         srcA);
        CPA16(d + 32,    srcA + 16);
        CPA16(d + 10240, srcB);
        CPA16(d + 10272, srcB + 16);
        CP_COMMIT();
    }

    int rsel = lane & 15;
    int cofs = (lane & 16) ? 16 : 0;

    for (int kt = 0; kt < 8; kt++) {
        if (kt < 7) {
            int k0 = (kt + 1) * 32;
            uint32_t d = sbase + ((kt + 1) & 1) * HG_STAGE + dstOff;
            CPA16(d,         srcA + k0);
            CPA16(d + 32,    srcA + k0 + 16);
            CPA16(d + 10240, srcB + k0);
            CPA16(d + 10272, srcB + k0 + 16);
            CP_COMMIT();
            CP_WAIT1();
        } else {
            CP_WAIT0();
        }
        __syncthreads();
        uint32_t buf = sbase + (kt & 1) * HG_STAGE;

#pragma unroll
        for (int half_ = 0; half_ < 2; half_++) {
            uint32_t hcol = (uint32_t)(half_*32 + cofs);
            uint32_t a_f[2][4];
#pragma unroll
            for (int mi = 0; mi < 2; mi++) {
                uint32_t ro = buf + (uint32_t)(wm + mi*16 + rsel) * 80 + hcol;
                LDSM4(a_f[mi][0], a_f[mi][1], a_f[mi][2], a_f[mi][3], ro);
            }
            uint32_t b_f[8][2];
#pragma unroll
            for (int np = 0; np < 4; np++) {
                uint32_t ro = buf + 10240 + (uint32_t)(wn + np*16 + rsel) * 80 + hcol;
                uint32_t r0, r1, r2, r3;
                LDSM4(r0, r1, r2, r3, ro);
                b_f[np*2][0]=r0; b_f[np*2+1][0]=r1; b_f[np*2][1]=r2; b_f[np*2+1][1]=r3;
            }
#pragma unroll
            for (int mi = 0; mi < 2; mi++)
#pragma unroll
                for (int nf = 0; nf < 8; nf++)
                    MMA16816F16(c[mi][nf], a_f[mi], b_f[nf]);
        }
        __syncthreads();
    }

    if (epi == 0) {
        float* C = (m ? g_v : g_t) + (size_t)e * NH;
#pragma unroll
        for (int mi = 0; mi < 2; mi++) {
            int row0 = bm + wm + mi*16 + (lane >> 2);
#pragma unroll
            for (int nf = 0; nf < 8; nf++) {
                int col = bn + wn + nf*8 + (lane & 3)*2;
                if (row0 < Nn)
                    *(float2*)(C + (size_t)row0*256 + col) = make_float2(c[mi][nf][0], c[mi][nf][1]);
                if (row0 + 8 < Nn)
                    *(float2*)(C + (size_t)(row0+8)*256 + col) = make_float2(c[mi][nf][2], c[mi][nf][3]);
            }
        }
    } else {
        // fused combine: he = relu(c + t + bias) -> fp16
        const float* T = g_t + (size_t)e * NH;
        __half* AF = g_Af + (size_t)e * NH;
#pragma unroll
        for (int mi = 0; mi < 2; mi++) {
            int row0 = bm + wm + mi*16 + (lane >> 2);
#pragma unroll
            for (int nf = 0; nf < 8; nf++) {
                int col = bn + wn + nf*8 + (lane & 3)*2;
                float bc0 = bias[e*256 + col], bc1 = bias[e*256 + col + 1];
#pragma unroll
                for (int rr = 0; rr < 2; rr++) {
                    int row = row0 + rr*8;
                    if (row >= Nn) continue;
                    float2 t2 = *(const float2*)(T + (size_t)row*256 + col);
                    float v0 = fmaxf(c[mi][nf][rr*2+0] + t2.x + bc0, 0.f);
                    float v1 = fmaxf(c[mi][nf][rr*2+1] + t2.y + bc1, 0.f);
                    *(__half2*)(AF + (size_t)row*256 + col) = __floats2half2_rn(v0, v1);
                }
            }
        }
    }
}

// ---------------- router epilogue ----------------
__global__ void k_router_epi(const float* __restrict__ W1, const float* __restrict__ b1) {
    int idx = blockIdx.x*blockDim.x + threadIdx.x;
    if (idx >= NH) return;
    int i = idx >> 8, c = idx & 255;
    float v = g_rt[idx] + g_sf[i*2]*W1[256*256+c] + g_sf[i*2+1]*W1[257*256+c] + b1[c];
    g_r[idx] = fmaxf(v, 0.f);
}

// one thread per node; W2/b2 staged in smem (row read once)
__global__ void k_logits(const float* __restrict__ W2, const float* __restrict__ b2) {
    __shared__ float sW[2048];
    __shared__ float sb[8];
    int t = threadIdx.x;
    for (int j = t; j < 2048; j += 256) sW[j] = W2[j];
    if (t < 8) sb[t] = b2[t];
    __syncthreads();
    int i = blockIdx.x*256 + t;
    if (i >= Nn) return;
    const float4* r = (const float4*)(g_r + (size_t)i*256);
    float acc[8];
#pragma unroll
    for (int e=0;e<8;e++) acc[e] = sb[e];
    for (int k4 = 0; k4 < 64; k4++) {
        float4 v = r[k4];
        const float* w = &sW[k4*32];
#pragma unroll
        for (int e=0;e<8;e++)
            acc[e] += v.x*w[e] + v.y*w[8+e] + v.z*w[16+e] + v.w*w[24+e];
    }
#pragma unroll
    for (int e=0;e<8;e++) g_logits[i*8+e] = acc[e];
}

__global__ void k_topk() {
    int i = blockIdx.x*blockDim.x + threadIdx.x;
    if (i >= Nn) return;
    float l[8];
#pragma unroll
    for (int e=0;e<8;e++) l[e] = g_logits[i*8+e];
    int i1 = 0; float m1 = l[0];
#pragma unroll
    for (int e=1;e<8;e++) if (l[e] > m1) { m1 = l[e]; i1 = e; }
    int i2 = -1; float m2 = -1e30f;
#pragma unroll
    for (int e=0;e<8;e++) if (e != i1 && l[e] > m2) { m2 = l[e]; i2 = e; }
    float e2v = expf(m2 - m1);
    float inv = 1.f/(1.f + e2v);
    float s[8];
#pragma unroll
    for (int e=0;e<8;e++) s[e]=0.f;
    s[i1] = inv; s[i2] = e2v*inv;
#pragma unroll
    for (int e=0;e<8;e++) g_sparse[i*8+e] = s[e];
}

// ---------------- layer-0 SpMM: agg(h) once, shared across experts ----------------
__global__ void k_spmm0() {
    int dst = blockIdx.x*8 + (threadIdx.x >> 5);
    int lane = threadIdx.x & 31;
    if (dst >= Nn) return;
    const float* vb = g_h + lane*8;
    int s0 = g_rowstart[dst], s1 = g_rowstart[dst+1];
    float a0=0.f,a1=0.f,a2=0.f,a3=0.f,a4=0.f,a5=0.f,a6=0.f,a7=0.f;
    for (int p = s0; p < s1; p++) {
        int src = g_csr_src[p];
        const float4* row = (const float4*)(vb + (size_t)src*256);
        float4 x0 = row[0], x1 = row[1];
        a0 += x0.x; a1 += x0.y; a2 += x0.z; a3 += x0.w;
        a4 += x1.x; a5 += x1.y; a6 += x1.z; a7 += x1.w;
    }
    float vals[8] = {a0,a1,a2,a3,a4,a5,a6,a7};
    union { __half h[8]; uint4 u; } H;
#pragma unroll
    for (int j = 0; j < 8; j++) H.h[j] = __float2half_rn(vals[j]);
    *(uint4*)(g_G0f + (size_t)dst*256 + lane*8) = H.u;
}

// ------- SpMM + combine, expert-major (grid: x = dst/8, y = expert) -------
// fuseOut=0: store fp16 activations (layer 1).
// fuseOut=1: last hidden layer — fused output projection; writes g_mz only.
__global__ void k_spmm_combine(const float* __restrict__ bias,
                               const float* __restrict__ Wr,
                               const float* __restrict__ Wn,
                               int fuseOut) {
    int dst = blockIdx.x*8 + (threadIdx.x >> 5);
    int e = blockIdx.y;
    int lane = threadIdx.x & 31;
    if (dst >= Nn) return;
    const float* vb = g_v + (size_t)e*NH + lane*8;
    int s0 = g_rowstart[dst], s1 = g_rowstart[dst+1];
    float a0=0.f,a1=0.f,a2=0.f,a3=0.f,a4=0.f,a5=0.f,a6=0.f,a7=0.f;
    for (int p = s0; p < s1; p++) {
        int src = g_csr_src[p];
        const float4* row = (const float4*)(vb + (size_t)src*256);
        float4 x0 = row[0], x1 = row[1];
        a0 += x0.x; a1 += x0.y; a2 += x0.z; a3 += x0.w;
        a4 += x1.x; a5 += x1.y; a6 += x1.z; a7 += x1.w;
    }
    size_t base = (size_t)e*NH + (size_t)dst*256 + lane*8;
    const float4* tb = (const float4*)(g_t + base);
    float4 t0 = tb[0], t1 = tb[1];
    const float4* bb = (const float4*)(bias + e*256 + lane*8);
    float4 b0 = bb[0], b1 = bb[1];
    float vals[8];
    vals[0]=t0.x+a0+b0.x; vals[1]=t0.y+a1+b0.y; vals[2]=t0.z+a2+b0.z; vals[3]=t0.w+a3+b0.w;
    vals[4]=t1.x+a4+b1.x; vals[5]=t1.y+a5+b1.y; vals[6]=t1.z+a6+b1.z; vals[7]=t1.w+a7+b1.w;
    if (!fuseOut) {
        union { __half h[8]; uint4 u; } H;
#pragma unroll
        for (int j = 0; j < 8; j++)
            H.h[j] = __float2half_rn(fmaxf(vals[j], 0.f));
        *(uint4*)(g_Af + base) = H.u;
    } else {
        const float* WRe = Wr + e*512;
        const float* WNe = Wn + e*512;
        float m0=0.f, m1=0.f, z0=0.f, z1=0.f;
#pragma unroll
        for (int j = 0; j < 8; j++) {
            float v = fmaxf(vals[j], 0.f);
            int k = lane*8 + j;
            m0 += v*WRe[k*2];   m1 += v*WRe[k*2+1];
            z0 += v*WNe[k*2];   z1 += v*WNe[k*2+1];
        }
#pragma unroll
        for (int off = 16; off > 0; off >>= 1) {
            m0 += __shfl_xor_sync(0xFFFFFFFFu, m0, off);
            m1 += __shfl_xor_sync(0xFFFFFFFFu, m1, off);
            z0 += __shfl_xor_sync(0xFFFFFFFFu, z0, off);
            z1 += __shfl_xor_sync(0xFFFFFFFFu, z1, off);
        }
        if (lane == 0) {
            float* o = g_mz + ((size_t)e*Nn + dst)*4;
            o[0]=m0; o[1]=m1; o[2]=z0; o[3]=z1;
        }
    }
}

__global__ void k_aggz() {
    int idx = blockIdx.x*blockDim.x + threadIdx.x;
    if (idx >= NEx*Nn) return;
    int dst = idx % Nn;
    int e = idx / Nn;
    int s0 = g_rowstart[dst], s1 = g_rowstart[dst+1];
    float a0=0.f, a1=0.f;
    for (int p=s0; p<s1; p++) {
        int src = g_csr_src[p];
        const float* z = g_mz + ((size_t)e*Nn + src)*4 + 2;
        a0 += z[0]; a1 += z[1];
    }
    g_aggz[((size_t)e*Nn+dst)*2+0] = a0;
    g_aggz[((size_t)e*Nn+dst)*2+1] = a1;
}

__global__ void k_final(const float* __restrict__ outb, float* __restrict__ out) {
    int i = blockIdx.x*blockDim.x + threadIdx.x;
    if (i >= Nn) return;
    float o0=0.f, o1=0.f;
#pragma unroll
    for (int e=0;e<8;e++) {
        float s = g_sparse[i*8+e];
        const float* mz = g_mz + ((size_t)e*Nn+i)*4;
        const float* az = g_aggz + ((size_t)e*Nn+i)*2;
        o0 += s*(mz[0] + az[0] + outb[e*2+0]);
        o1 += s*(mz[1] + az[1] + outb[e*2+1]);
    }
    out[i*2+0] = o0;
    out[i*2+1] = o1;
}

// ---------------- launch ----------------
extern "C" void kernel_launch(void* const* d_in, const int* in_sizes, int n_in,
                              void* d_out, int out_size) {
    const float* x    = (const float*)d_in[0];
    const int*   ei   = (const int*)  d_in[1];
    const int*   batch= (const int*)  d_in[2];
    const float* encW = (const float*)d_in[3];
    const float* encb = (const float*)d_in[4];
    const float* rW1  = (const float*)d_in[5];
    const float* rb1  = (const float*)d_in[6];
    const float* rW2  = (const float*)d_in[7];
    const float* rb2  = (const float*)d_in[8];
    const float* hWr  = (const float*)d_in[9];
    const float* hWn  = (const float*)d_in[10];
    const float* hb   = (const float*)d_in[11];
    const float* oWr  = (const float*)d_in[12];
    const float* oWn  = (const float*)d_in[13];
    const float* ob   = (const float*)d_in[14];
    float* out = (float*)d_out;

    const int NTILES = (Nn + 127) / 128;   // 391
    dim3 gHalf(NTILES, 2, NEx);            // one m per launch
    dim3 gFull(NTILES, 2, NEx*2);          // both m
    dim3 gS2((Nn + 7)/8, NEx);             // expert-major SpMM

    k_zero<<<(Nn+255)/256,256>>>();
    k_encoder<<<(NH+255)/256,256>>>(x, encW, encb);
    k_convW<<<(NMATS*65536+255)/256,256>>>(rW1, hWr, hWn);
    k_hgemm<<<gHalf,256>>>(0, 0, 1, 0, nullptr);   // L0 t (profiled slot)
    k_count_nodes<<<256,256>>>(batch);
    k_count_edges<<<512,256>>>(ei, batch);
    k_indeg<<<(Ee+255)/256,256>>>(ei);
    k_sizefeat<<<(Nn+255)/256,256>>>(batch);
    k_scan1<<<(Nn+1023)/1024,1024>>>();
    k_scan2<<<1,64>>>();
    k_scan3<<<(Nn+255)/256,256>>>();
    k_cursor<<<(Nn+255)/256,256>>>();
    k_scatter<<<(Ee+255)/256,256>>>(ei);

    // router (exact fp32 in its own buffer g_rt)
    {
        dim3 gR((Nn+127)/128, 2, 1);
        k_sgemm_router<<<gR,256>>>(rW1);
        k_router_epi<<<(NH+255)/256,256>>>(rW1, rb1);
        k_logits<<<(Nn+255)/256,256>>>(rW2, rb2);
        k_topk<<<(Nn+255)/256,256>>>();
    }

    // layer 0: shared aggregate of h, then he = relu(t + agg@Wn + b) fused in epilogue
    k_spmm0<<<(Nn+7)/8,256>>>();
    k_hgemm<<<gHalf,256>>>(2, 1, 1, 1, hb);   // L0 v + fused combine

    // layer 1: GEMMs + SpMM/combine (store activations)
    k_hgemm<<<gFull,256>>>(1, -1, 1 + 1*(NEx*2), 0, nullptr);
    k_spmm_combine<<<gS2,256>>>(hb + (size_t)1*NEx*Hh, oWr, oWn, 0);

    // layer 2: GEMMs + SpMM/combine with fused output projection
    k_hgemm<<<gFull,256>>>(1, -1, 1 + 2*(NEx*2), 0, nullptr);
    k_spmm_combine<<<gS2,256>>>(hb + (size_t)2*NEx*Hh, oWr, oWn, 1);

    // output layer
    k_aggz<<<(NEx*Nn+255)/256,256>>>();
    k_final<<<(Nn+255)/256,256>>>(ob, out);
}

// round 17
// speedup vs baseline: 2.2217x; 1.0977x over previous
#include <cuda_runtime.h>
#include <cuda_fp16.h>
#include <cstdint>
#include <math.h>

#define Nn 50000
#define Ee 800000
#define Gg 64
#define Ff 6
#define Hh 256
#define Oo 2
#define NEx 8
#define NH (Nn*Hh)
#define NMATS 49   // 1 router + 3 layers * 8 experts * 2

// ---------------- scratch (static __device__ arrays; no allocation) ----------------
__device__ __align__(128) float g_h[NH];                  // encoder output (fp32)
__device__ __align__(128) __half g_A0f[NH];               // encoder fp16
__device__ __align__(128) __half g_G0f[NH];               // agg(h) fp16 (layer-0, shared)
__device__ __align__(128) float g_r[NH];                  // router hidden
__device__ __align__(128) float g_rt[NH];                 // router GEMM scratch
__device__ __align__(128) float g_t[NEx*NH];              // he @ Wr (fp32)
__device__ __align__(128) __half g_vf[NEx*NH];            // he @ Wn (fp16, gathered by SpMM)
__device__ __align__(128) __half g_Af[NEx*NH];            // per-expert activation fp16
__device__ __align__(128) __half g_Wf[NMATS*65536];       // weights fp16 [mat][n][k]
__device__ __align__(128) float g_sf[Nn*2];
__device__ __align__(128) float g_logits[Nn*NEx];
__device__ __align__(128) float g_sparse[Nn*NEx];
__device__ __align__(128) float g_m[NEx*Nn*2];            // output proj m (float2 per e,node)
__device__ __align__(128) float g_z[NEx*Nn*2];            // output proj z (float2 per e,node)
__device__ __align__(128) float g_aggz[NEx*Nn*2];
__device__ int g_nodecnt[Gg];
__device__ int g_edgecnt[Gg];
__device__ int g_indeg[Nn];
__device__ int g_scantmp[Nn];
__device__ int g_bsum[64];
__device__ int g_bsumscan[64];
__device__ int g_rowstart[Nn+1];
__device__ int g_cursor[Nn];
__device__ int g_csr_src[Ee];

// ======================= warp MMA helpers (plain-target: sm_80+) =======================
__device__ __forceinline__ uint32_t smem_to_u32(const void* smem_ptr) {
    uint32_t addr;
    asm("{ .reg .u64 tmp; cvta.to.shared.u64 tmp, %1; cvt.u32.u64 %0, tmp; }"
        : "=r"(addr) : "l"(smem_ptr));
    return addr;
}
#define LDSM4(r0,r1,r2,r3,addr) \
    asm volatile("ldmatrix.sync.aligned.m8n8.x4.shared.b16 {%0,%1,%2,%3}, [%4];" \
        : "=r"(r0), "=r"(r1), "=r"(r2), "=r"(r3) : "r"(addr))
#define MMA16816F16(c, a, b) \
    asm volatile("mma.sync.aligned.m16n8k16.row.col.f32.f16.f16.f32 " \
        "{%0,%1,%2,%3}, {%4,%5,%6,%7}, {%8,%9}, {%0,%1,%2,%3};" \
        : "+f"((c)[0]), "+f"((c)[1]), "+f"((c)[2]), "+f"((c)[3]) \
        : "r"((a)[0]), "r"((a)[1]), "r"((a)[2]), "r"((a)[3]), \
          "r"((b)[0]), "r"((b)[1]))
#define CPA16(dst, src) \
    asm volatile("cp.async.cg.shared.global [%0], [%1], 16;" :: "r"(dst), "l"(src))
#define CP_COMMIT() asm volatile("cp.async.commit_group;")
#define CP_WAIT0()  asm volatile("cp.async.wait_group 0;")

// ---------------- small kernels ----------------
__global__ void k_zero() {
    int i = blockIdx.x*blockDim.x + threadIdx.x;
    if (i < Gg) { g_nodecnt[i]=0; g_edgecnt[i]=0; }
    if (i < Nn) g_indeg[i]=0;
}

__global__ void k_encoder(const float* __restrict__ x, const float* __restrict__ W,
                          const float* __restrict__ b) {
    int idx = blockIdx.x*blockDim.x + threadIdx.x;
    if (idx >= NH) return;
    int i = idx >> 8, c = idx & 255;
    float acc = b[c];
#pragma unroll
    for (int k=0;k<Ff;k++) acc += x[i*Ff+k]*W[k*Hh+c];
    float v = fmaxf(acc, 0.f);
    g_h[idx] = v;
    g_A0f[idx] = __float2half_rn(v);
}

// convert + transpose all weights to fp16, layout [mat][n][k]
__global__ void k_convW(const float* __restrict__ rW1, const float* __restrict__ hWr,
                        const float* __restrict__ hWn) {
    size_t idx = (size_t)blockIdx.x*blockDim.x + threadIdx.x;
    if (idx >= (size_t)NMATS*65536) return;
    int mat = (int)(idx >> 16);
    int r = (int)(idx & 65535);
    int n = r >> 8, k = r & 255;
    float w;
    if (mat == 0) {
        w = rW1[k*256 + n];
    } else {
        int hm = mat - 1;
        int l = hm >> 4, rr = hm & 15;
        int e = rr >> 1, m = rr & 1;
        const float* W = m ? hWn : hWr;
        w = W[((size_t)(l*NEx + e))*65536 + k*256 + n];
    }
    g_Wf[idx] = __float2half_rn(w);
}

__global__ void k_count_nodes(const int* __restrict__ batch) {
    __shared__ int hist[Gg];
    int t = threadIdx.x;
    if (t < Gg) hist[t]=0;
    __syncthreads();
    for (int i = blockIdx.x*blockDim.x + t; i < Nn; i += gridDim.x*blockDim.x)
        atomicAdd(&hist[batch[i]], 1);
    __syncthreads();
    if (t < Gg) atomicAdd(&g_nodecnt[t], hist[t]);
}

__global__ void k_count_edges(const int* __restrict__ ei, const int* __restrict__ batch) {
    __shared__ int hist[Gg];
    int t = threadIdx.x;
    if (t < Gg) hist[t]=0;
    __syncthreads();
    for (int e = blockIdx.x*blockDim.x + t; e < Ee; e += gridDim.x*blockDim.x)
        atomicAdd(&hist[batch[ei[e]]], 1);
    __syncthreads();
    if (t < Gg) atomicAdd(&g_edgecnt[t], hist[t]);
}

__global__ void k_indeg(const int* __restrict__ ei) {
    int e = blockIdx.x*blockDim.x + threadIdx.x;
    if (e < Ee) atomicAdd(&g_indeg[ei[Ee+e]], 1);
}

__global__ void k_sizefeat(const int* __restrict__ batch) {
    int i = blockIdx.x*blockDim.x + threadIdx.x;
    if (i >= Nn) return;
    int g = batch[i];
    g_sf[i*2+0] = logf((float)g_nodecnt[g] + 1.f);
    g_sf[i*2+1] = logf((float)g_edgecnt[g] + 1.f);
}

__global__ void k_scan1() {
    __shared__ int sh[1024];
    int t = threadIdx.x, gid = blockIdx.x*1024 + t;
    sh[t] = (gid < Nn) ? g_indeg[gid] : 0;
    __syncthreads();
    for (int off=1; off<1024; off<<=1) {
        int a = (t>=off) ? sh[t-off] : 0;
        __syncthreads();
        sh[t] += a;
        __syncthreads();
    }
    if (gid < Nn) g_scantmp[gid] = sh[t];
    if (t == 1023) g_bsum[blockIdx.x] = sh[1023];
}

__global__ void k_scan2() {
    __shared__ int sh[64];
    int t = threadIdx.x;
    const int NB1 = (Nn + 1023)/1024;
    sh[t] = (t < NB1) ? g_bsum[t] : 0;
    __syncthreads();
    for (int off=1; off<64; off<<=1) {
        int a = (t>=off) ? sh[t-off] : 0;
        __syncthreads();
        sh[t] += a;
        __syncthreads();
    }
    g_bsumscan[t] = sh[t];
}

__global__ void k_scan3() {
    int i = blockIdx.x*blockDim.x + threadIdx.x;
    if (i >= Nn) return;
    int blk = i >> 10;
    int incl = g_scantmp[i] + (blk ? g_bsumscan[blk-1] : 0);
    g_rowstart[i+1] = incl;
    if (i == 0) g_rowstart[0] = 0;
}

__global__ void k_cursor() {
    int i = blockIdx.x*blockDim.x + threadIdx.x;
    if (i < Nn) g_cursor[i] = g_rowstart[i];
}

__global__ void k_scatter(const int* __restrict__ ei) {
    int e = blockIdx.x*blockDim.x + threadIdx.x;
    if (e >= Ee) return;
    int d = ei[Ee+e];
    int p = atomicAdd(&g_cursor[d], 1);
    g_csr_src[p] = ei[e];
}

// ---------------- router SGEMM (exact fp32, tile 128x128) -> g_rt ----------------
__global__ void __launch_bounds__(256) k_sgemm_router(const float* __restrict__ B) {
    const float* A = g_h;
    float* Cb = g_rt;

    __shared__ float As[16][128];
    __shared__ float Bs[16][128];

    int tid = threadIdx.x;
    int bm = blockIdx.x*128, bn = blockIdx.y*128;
    int tx = tid & 15, ty = tid >> 4;
    int a_row = tid >> 2;
    int a_col = (tid & 3) * 4;
    int b_row = tid >> 5;
    int b_col = (tid & 31) * 4;

    float acc[8][8];
#pragma unroll
    for (int i=0;i<8;i++)
#pragma unroll
        for (int j=0;j<8;j++) acc[i][j]=0.f;

    for (int kt=0; kt<256; kt+=16) {
        __syncthreads();
#pragma unroll
        for (int i=0;i<2;i++) {
            int r = a_row + i*64;
            int gm = bm + r;
            float4 av = make_float4(0.f,0.f,0.f,0.f);
            if (gm < Nn) av = *(const float4*)(A + (size_t)gm*256 + kt + a_col);
            As[a_col+0][r]=av.x; As[a_col+1][r]=av.y;
            As[a_col+2][r]=av.z; As[a_col+3][r]=av.w;
        }
#pragma unroll
        for (int i=0;i<2;i++) {
            int r = b_row + i*8;
            *(float4*)&Bs[r][b_col] = *(const float4*)(B + (size_t)(kt+r)*256 + bn + b_col);
        }
        __syncthreads();
#pragma unroll
        for (int kk=0;kk<16;kk++) {
            float4 a0 = *(const float4*)&As[kk][ty*4];
            float4 a1 = *(const float4*)&As[kk][64+ty*4];
            float4 b0 = *(const float4*)&Bs[kk][tx*4];
            float4 b1 = *(const float4*)&Bs[kk][64+tx*4];
            float a[8] = {a0.x,a0.y,a0.z,a0.w,a1.x,a1.y,a1.z,a1.w};
            float b[8] = {b0.x,b0.y,b0.z,b0.w,b1.x,b1.y,b1.z,b1.w};
#pragma unroll
            for (int i=0;i<8;i++)
#pragma unroll
                for (int j=0;j<8;j++) acc[i][j] += a[i]*b[j];
        }
    }
#pragma unroll
    for (int ih=0; ih<2; ih++) {
#pragma unroll
        for (int i=0;i<4;i++) {
            int gm = bm + ih*64 + ty*4 + i;
            if (gm >= Nn) continue;
            float* crow = Cb + (size_t)gm*256 + bn;
            int r = ih*4 + i;
            *(float4*)(crow + tx*4)      = make_float4(acc[r][0],acc[r][1],acc[r][2],acc[r][3]);
            *(float4*)(crow + 64 + tx*4) = make_float4(acc[r][4],acc[r][5],acc[r][6],acc[r][7]);
        }
    }
}

// ============== HMMA fp16 1-term GEMM, BK=32, 2-stage cp.async, static smem =========
// C = A_f16 @ W_f16 (fp32 accumulate). ONE barrier per K-step, race-free ordering:
//   wait(stage kt) -> syncthreads -> issue cp.async(stage kt+1) -> compute(stage kt)
// The barrier both publishes stage kt's data and proves all warps finished reading
// buffer (kt+1)&1 in iteration kt-1 before it is overwritten.
// asel: 0 -> A = g_A0f, 1 -> A = g_Af(e), 2 -> A = g_G0f
// mSel: -1 -> z covers e*2+m ; 0/1 -> z covers e, m fixed
// epi:  0 -> store (m=0: fp32 g_t, m=1: fp16 g_vf); 1 -> fused combine -> g_Af
#define HG_STAGE 20480

__global__ void __launch_bounds__(256, 2) k_hgemm(int asel, int mSel, int matBase,
                                                  int epi, const float* __restrict__ bias)
{
    __shared__ __align__(16) char smarr[2*HG_STAGE];   // 40 KB static
    uint32_t sbase = smem_to_u32(smarr);
    int tid = threadIdx.x, lane = tid & 31, wid = tid >> 5;
    int bm = blockIdx.x * 128, bn = blockIdx.y * 128;
    int z = blockIdx.z;
    int e, m;
    if (mSel < 0) { e = z >> 1; m = z & 1; } else { e = z; m = mSel; }
    int mat = matBase + e*2 + m;

    const __half* Af;
    if (asel == 0)      Af = g_A0f;
    else if (asel == 1) Af = g_Af + (size_t)e*NH;
    else                Af = g_G0f;
    const __half* Bf = g_Wf + (size_t)mat * 65536;

    int wm = (wid & 3) * 32;
    int wn = (wid >> 2) * 64;

    float c[2][8][4];
#pragma unroll
    for (int mi=0;mi<2;mi++)
#pragma unroll
        for (int nf=0;nf<8;nf++)
#pragma unroll
            for (int r=0;r<4;r++) c[mi][nf][r] = 0.f;

    int lrow = tid >> 1, lch = tid & 1;
    int agr = bm + lrow; if (agr >= Nn) agr = Nn - 1;   // clamp: junk rows masked on store
    const __half* srcA = Af + (size_t)agr*256 + lch*8;
    const __half* srcB = Bf + (size_t)(bn + lrow)*256 + lch*8;
    uint32_t dstOff = (uint32_t)lrow*80 + (uint32_t)lch*16;

    // prologue: stage 0 (k [0,32))
    {
        uint32_t d = sbase + dstOff;
        CPA16(d,         srcA);
        CPA16(d + 32,    srcA + 16);
        CPA16(d + 10240, srcB);
        CPA16(d + 10272, srcB + 16);
        CP_COMMIT();
    }

    int rsel = lane & 15;
    int cofs = (lane & 16) ? 16 : 0;

    for (int kt = 0; kt < 8; kt++) {
        CP_WAIT0();        // stage kt copy complete (only pending group)
        __syncthreads();   // publish stage kt; all warps done reading buf (kt+1)&1
        if (kt < 7) {
            int k0 = (kt + 1) * 32;
            uint32_t d = sbase + ((kt + 1) & 1) * HG_STAGE + dstOff;
            CPA16(d,         srcA + k0);
            CPA16(d + 32,    srcA + k0 + 16);
            CPA16(d + 10240, srcB + k0);
            CPA16(d + 10272, srcB + k0 + 16);
            CP_COMMIT();
        }
        uint32_t buf = sbase + (kt & 1) * HG_STAGE;

#pragma unroll
        for (int half_ = 0; half_ < 2; half_++) {
            uint32_t hcol = (uint32_t)(half_*32 + cofs);
            uint32_t a_f[2][4];
#pragma unroll
            for (int mi = 0; mi < 2; mi++) {
                uint32_t ro = buf + (uint32_t)(wm + mi*16 + rsel) * 80 + hcol;
                LDSM4(a_f[mi][0], a_f[mi][1], a_f[mi][2], a_f[mi][3], ro);
            }
            uint32_t b_f[8][2];
#pragma unroll
            for (int np = 0; np < 4; np++) {
                uint32_t ro = buf + 10240 + (uint32_t)(wn + np*16 + rsel) * 80 + hcol;
                uint32_t r0, r1, r2, r3;
                LDSM4(r0, r1, r2, r3, ro);
                b_f[np*2][0]=r0; b_f[np*2+1][0]=r1; b_f[np*2][1]=r2; b_f[np*2+1][1]=r3;
            }
#pragma unroll
            for (int mi = 0; mi < 2; mi++)
#pragma unroll
                for (int nf = 0; nf < 8; nf++)
                    MMA16816F16(c[mi][nf], a_f[mi], b_f[nf]);
        }
    }

    if (epi == 0) {
        if (m == 0) {
            float* C = g_t + (size_t)e * NH;
#pragma unroll
            for (int mi = 0; mi < 2; mi++) {
                int row0 = bm + wm + mi*16 + (lane >> 2);
#pragma unroll
                for (int nf = 0; nf < 8; nf++) {
                    int col = bn + wn + nf*8 + (lane & 3)*2;
                    if (row0 < Nn)
                        *(float2*)(C + (size_t)row0*256 + col) = make_float2(c[mi][nf][0], c[mi][nf][1]);
                    if (row0 + 8 < Nn)
                        *(float2*)(C + (size_t)(row0+8)*256 + col) = make_float2(c[mi][nf][2], c[mi][nf][3]);
                }
            }
        } else {
            __half* V = g_vf + (size_t)e * NH;
#pragma unroll
            for (int mi = 0; mi < 2; mi++) {
                int row0 = bm + wm + mi*16 + (lane >> 2);
#pragma unroll
                for (int nf = 0; nf < 8; nf++) {
                    int col = bn + wn + nf*8 + (lane & 3)*2;
                    if (row0 < Nn)
                        *(__half2*)(V + (size_t)row0*256 + col) = __floats2half2_rn(c[mi][nf][0], c[mi][nf][1]);
                    if (row0 + 8 < Nn)
                        *(__half2*)(V + (size_t)(row0+8)*256 + col) = __floats2half2_rn(c[mi][nf][2], c[mi][nf][3]);
                }
            }
        }
    } else {
        // fused combine: he = relu(c + t + bias) -> fp16
        const float* T = g_t + (size_t)e * NH;
        __half* AF = g_Af + (size_t)e * NH;
#pragma unroll
        for (int mi = 0; mi < 2; mi++) {
            int row0 = bm + wm + mi*16 + (lane >> 2);
#pragma unroll
            for (int nf = 0; nf < 8; nf++) {
                int col = bn + wn + nf*8 + (lane & 3)*2;
                float bc0 = bias[e*256 + col], bc1 = bias[e*256 + col + 1];
#pragma unroll
                for (int rr = 0; rr < 2; rr++) {
                    int row = row0 + rr*8;
                    if (row >= Nn) continue;
                    float2 t2 = *(const float2*)(T + (size_t)row*256 + col);
                    float v0 = fmaxf(c[mi][nf][rr*2+0] + t2.x + bc0, 0.f);
                    float v1 = fmaxf(c[mi][nf][rr*2+1] + t2.y + bc1, 0.f);
                    *(__half2*)(AF + (size_t)row*256 + col) = __floats2half2_rn(v0, v1);
                }
            }
        }
    }
}

// ---------------- router epilogue ----------------
__global__ void k_router_epi(const float* __restrict__ W1, const float* __restrict__ b1) {
    int idx = blockIdx.x*blockDim.x + threadIdx.x;
    if (idx >= NH) return;
    int i = idx >> 8, c = idx & 255;
    float v = g_rt[idx] + g_sf[i*2]*W1[256*256+c] + g_sf[i*2+1]*W1[257*256+c] + b1[c];
    g_r[idx] = fmaxf(v, 0.f);
}

// one thread per node; W2/b2 staged in smem (row read once)
__global__ void k_logits(const float* __restrict__ W2, const float* __restrict__ b2) {
    __shared__ float sW[2048];
    __shared__ float sb[8];
    int t = threadIdx.x;
    for (int j = t; j < 2048; j += 256) sW[j] = W2[j];
    if (t < 8) sb[t] = b2[t];
    __syncthreads();
    int i = blockIdx.x*256 + t;
    if (i >= Nn) return;
    const float4* r = (const float4*)(g_r + (size_t)i*256);
    float acc[8];
#pragma unroll
    for (int e=0;e<8;e++) acc[e] = sb[e];
    for (int k4 = 0; k4 < 64; k4++) {
        float4 v = r[k4];
        const float* w = &sW[k4*32];
#pragma unroll
        for (int e=0;e<8;e++)
            acc[e] += v.x*w[e] + v.y*w[8+e] + v.z*w[16+e] + v.w*w[24+e];
    }
#pragma unroll
    for (int e=0;e<8;e++) g_logits[i*8+e] = acc[e];
}

__global__ void k_topk() {
    int i = blockIdx.x*blockDim.x + threadIdx.x;
    if (i >= Nn) return;
    float l[8];
#pragma unroll
    for (int e=0;e<8;e++) l[e] = g_logits[i*8+e];
    int i1 = 0; float m1 = l[0];
#pragma unroll
    for (int e=1;e<8;e++) if (l[e] > m1) { m1 = l[e]; i1 = e; }
    int i2 = -1; float m2 = -1e30f;
#pragma unroll
    for (int e=0;e<8;e++) if (e != i1 && l[e] > m2) { m2 = l[e]; i2 = e; }
    float e2v = expf(m2 - m1);
    float inv = 1.f/(1.f + e2v);
    float s[8];
#pragma unroll
    for (int e=0;e<8;e++) s[e]=0.f;
    s[i1] = inv; s[i2] = e2v*inv;
#pragma unroll
    for (int e=0;e<8;e++) g_sparse[i*8+e] = s[e];
}

// ---------------- layer-0 SpMM: agg(h) once (fp16 source), shared across experts ----------------
__global__ void k_spmm0() {
    int dst = blockIdx.x*8 + (threadIdx.x >> 5);
    int lane = threadIdx.x & 31;
    if (dst >= Nn) return;
    const __half* vb = g_A0f + lane*8;
    int s0 = g_rowstart[dst], s1 = g_rowstart[dst+1];
    float a0=0.f,a1=0.f,a2=0.f,a3=0.f,a4=0.f,a5=0.f,a6=0.f,a7=0.f;
    for (int p = s0; p < s1; p++) {
        int src = g_csr_src[p];
        uint4 raw = *(const uint4*)(vb + (size_t)src*256);
        const __half2* h2 = (const __half2*)&raw;
        float2 f0 = __half22float2(h2[0]), f1 = __half22float2(h2[1]);
        float2 f2 = __half22float2(h2[2]), f3 = __half22float2(h2[3]);
        a0 += f0.x; a1 += f0.y; a2 += f1.x; a3 += f1.y;
        a4 += f2.x; a5 += f2.y; a6 += f3.x; a7 += f3.y;
    }
    float vals[8] = {a0,a1,a2,a3,a4,a5,a6,a7};
    union { __half h[8]; uint4 u; } H;
#pragma unroll
    for (int j = 0; j < 8; j++) H.h[j] = __float2half_rn(vals[j]);
    *(uint4*)(g_G0f + (size_t)dst*256 + lane*8) = H.u;
}

// ------- SpMM + combine, expert-major (grid: x = dst/8, y = expert), fp16 gather -------
// fuseOut=0: store fp16 activations (layer 1).
// fuseOut=1: last hidden layer — fused output projection; writes g_m/g_z only.
__global__ void k_spmm_combine(const float* __restrict__ bias,
                               const float* __restrict__ Wr,
                               const float* __restrict__ Wn,
                               int fuseOut) {
    int dst = blockIdx.x*8 + (threadIdx.x >> 5);
    int e = blockIdx.y;
    int lane = threadIdx.x & 31;
    if (dst >= Nn) return;
    const __half* vb = g_vf + (size_t)e*NH + lane*8;
    int s0 = g_rowstart[dst], s1 = g_rowstart[dst+1];
    float a0=0.f,a1=0.f,a2=0.f,a3=0.f,a4=0.f,a5=0.f,a6=0.f,a7=0.f;
    for (int p = s0; p < s1; p++) {
        int src = g_csr_src[p];
        uint4 raw = *(const uint4*)(vb + (size_t)src*256);
        const __half2* h2 = (const __half2*)&raw;
        float2 f0 = __half22float2(h2[0]), f1 = __half22float2(h2[1]);
        float2 f2 = __half22float2(h2[2]), f3 = __half22float2(h2[3]);
        a0 += f0.x; a1 += f0.y; a2 += f1.x; a3 += f1.y;
        a4 += f2.x; a5 += f2.y; a6 += f3.x; a7 += f3.y;
    }
    size_t base = (size_t)e*NH + (size_t)dst*256 + lane*8;
    const float4* tb = (const float4*)(g_t + base);
    float4 t0 = tb[0], t1 = tb[1];
    const float4* bb = (const float4*)(bias + e*256 + lane*8);
    float4 b0 = bb[0], b1 = bb[1];
    float vals[8];
    vals[0]=t0.x+a0+b0.x; vals[1]=t0.y+a1+b0.y; vals[2]=t0.z+a2+b0.z; vals[3]=t0.w+a3+b0.w;
    vals[4]=t1.x+a4+b1.x; vals[5]=t1.y+a5+b1.y; vals[6]=t1.z+a6+b1.z; vals[7]=t1.w+a7+b1.w;
    if (!fuseOut) {
        union { __half h[8]; uint4 u; } H;
#pragma unroll
        for (int j = 0; j < 8; j++)
            H.h[j] = __float2half_rn(fmaxf(vals[j], 0.f));
        *(uint4*)(g_Af + base) = H.u;
    } else {
        const float* WRe = Wr + e*512;
        const float* WNe = Wn + e*512;
        float m0=0.f, m1=0.f, z0=0.f, z1=0.f;
#pragma unroll
        for (int j = 0; j < 8; j++) {
            float v = fmaxf(vals[j], 0.f);
            int k = lane*8 + j;
            m0 += v*WRe[k*2];   m1 += v*WRe[k*2+1];
            z0 += v*WNe[k*2];   z1 += v*WNe[k*2+1];
        }
#pragma unroll
        for (int off = 16; off > 0; off >>= 1) {
            m0 += __shfl_xor_sync(0xFFFFFFFFu, m0, off);
            m1 += __shfl_xor_sync(0xFFFFFFFFu, m1, off);
            z0 += __shfl_xor_sync(0xFFFFFFFFu, z0, off);
            z1 += __shfl_xor_sync(0xFFFFFFFFu, z1, off);
        }
        if (lane == 0) {
            size_t o = ((size_t)e*Nn + dst)*2;
            *(float2*)(g_m + o) = make_float2(m0, m1);
            *(float2*)(g_z + o) = make_float2(z0, z1);
        }
    }
}

__global__ void k_aggz() {
    int idx = blockIdx.x*blockDim.x + threadIdx.x;
    if (idx >= NEx*Nn) return;
    int dst = idx % Nn;
    int e = idx / Nn;
    int s0 = g_rowstart[dst], s1 = g_rowstart[dst+1];
    float a0=0.f, a1=0.f;
    const float* zb = g_z + (size_t)e*Nn*2;
    for (int p=s0; p<s1; p++) {
        int src = g_csr_src[p];
        float2 zz = *(const float2*)(zb + (size_t)src*2);
        a0 += zz.x; a1 += zz.y;
    }
    *(float2*)(g_aggz + ((size_t)e*Nn+dst)*2) = make_float2(a0, a1);
}

__global__ void k_final(const float* __restrict__ outb, float* __restrict__ out) {
    int i = blockIdx.x*blockDim.x + threadIdx.x;
    if (i >= Nn) return;
    float o0=0.f, o1=0.f;
#pragma unroll
    for (int e=0;e<8;e++) {
        float s = g_sparse[i*8+e];
        float2 mm = *(const float2*)(g_m + ((size_t)e*Nn+i)*2);
        float2 az = *(const float2*)(g_aggz + ((size_t)e*Nn+i)*2);
        o0 += s*(mm.x + az.x + outb[e*2+0]);
        o1 += s*(mm.y + az.y + outb[e*2+1]);
    }
    out[i*2+0] = o0;
    out[i*2+1] = o1;
}

// ---------------- launch ----------------
extern "C" void kernel_launch(void* const* d_in, const int* in_sizes, int n_in,
                              void* d_out, int out_size) {
    const float* x    = (const float*)d_in[0];
    const int*   ei   = (const int*)  d_in[1];
    const int*   batch= (const int*)  d_in[2];
    const float* encW = (const float*)d_in[3];
    const float* encb = (const float*)d_in[4];
    const float* rW1  = (const float*)d_in[5];
    const float* rb1  = (const float*)d_in[6];
    const float* rW2  = (const float*)d_in[7];
    const float* rb2  = (const float*)d_in[8];
    const float* hWr  = (const float*)d_in[9];
    const float* hWn  = (const float*)d_in[10];
    const float* hb   = (const float*)d_in[11];
    const float* oWr  = (const float*)d_in[12];
    const float* oWn  = (const float*)d_in[13];
    const float* ob   = (const float*)d_in[14];
    float* out = (float*)d_out;

    const int NTILES = (Nn + 127) / 128;   // 391
    dim3 gHalf(NTILES, 2, NEx);            // one m per launch
    dim3 gFull(NTILES, 2, NEx*2);          // both m
    dim3 gS2((Nn + 7)/8, NEx);             // expert-major SpMM

    k_zero<<<(Nn+255)/256,256>>>();
    k_encoder<<<(NH+255)/256,256>>>(x, encW, encb);
    k_convW<<<(NMATS*65536+255)/256,256>>>(rW1, hWr, hWn);
    k_hgemm<<<gHalf,256>>>(0, 0, 1, 0, nullptr);   // L0 t (profiled slot)
    k_count_nodes<<<256,256>>>(batch);
    k_count_edges<<<512,256>>>(ei, batch);
    k_indeg<<<(Ee+255)/256,256>>>(ei);
    k_sizefeat<<<(Nn+255)/256,256>>>(batch);
    k_scan1<<<(Nn+1023)/1024,1024>>>();
    k_scan2<<<1,64>>>();
    k_scan3<<<(Nn+255)/256,256>>>();
    k_cursor<<<(Nn+255)/256,256>>>();
    k_scatter<<<(Ee+255)/256,256>>>(ei);

    // router (exact fp32 in its own buffer g_rt)
    {
        dim3 gR((Nn+127)/128, 2, 1);
        k_sgemm_router<<<gR,256>>>(rW1);
        k_router_epi<<<(NH+255)/256,256>>>(rW1, rb1);
        k_logits<<<(Nn+255)/256,256>>>(rW2, rb2);
        k_topk<<<(Nn+255)/256,256>>>();
    }

    // layer 0: shared aggregate of h (fp16), then he = relu(t + agg@Wn + b) fused
    k_spmm0<<<(Nn+7)/8,256>>>();
    k_hgemm<<<gHalf,256>>>(2, 1, 1, 1, hb);   // L0 v + fused combine

    // layer 1: GEMMs + SpMM/combine (store activations)
    k_hgemm<<<gFull,256>>>(1, -1, 1 + 1*(NEx*2), 0, nullptr);
    k_spmm_combine<<<gS2,256>>>(hb + (size_t)1*NEx*Hh, oWr, oWn, 0);

    // layer 2: GEMMs + SpMM/combine with fused output projection
    k_hgemm<<<gFull,256>>>(1, -1, 1 + 2*(NEx*2), 0, nullptr);
    k_spmm_combine<<<gS2,256>>>(hb + (size_t)2*NEx*Hh, oWr, oWn, 1);

    // output layer
    k_aggz<<<(NEx*Nn+255)/256,256>>>();
    k_final<<<(Nn+255)/256,256>>>(ob, out);
}